// round 7
// baseline (speedup 1.0000x reference)
#include <cuda_runtime.h>
#include <cuda_bf16.h>
#include <cstdint>
#include <cstddef>
#include <math.h>

// ---------------------------------------------------------------------------
// Problem constants
// ---------------------------------------------------------------------------
#define BB     4
#define LL     2048
#define PP     1024
#define NFEAT  100
#define DD     1024
#define HH     8
#define HDIM   128
#define NHID   4096
#define NLAYERS 3
#define NOUTD  10
#define LB     (LL*BB)
#define KPAD   112

typedef __nv_bfloat16 bf16;
typedef long long ll;

// ---------------------------------------------------------------------------
// Scratch (device globals)
// ---------------------------------------------------------------------------
__device__ float g_m1[BB*NFEAT], g_s1[BB*NFEAT];
__device__ float g_m2[BB*NFEAT], g_s2[BB*NFEAT];
__device__ float g_m3[BB*NFEAT], g_s3[BB*NFEAT];
__device__ __align__(256) float g_xn[(size_t)LB*KPAD];
__device__ __align__(256) float g_src[(size_t)LB*DD];
__device__ __align__(256) float g_tmp[(size_t)LB*DD];
__device__ __align__(256) float g_vh [(size_t)BB*HH*PP*HDIM];
__device__ __align__(256) float g_logits[(size_t)BB*HH*LL*PP];

__device__ __align__(256) bf16 g_ah[(size_t)LB*DD];
__device__ __align__(256) bf16 g_al[(size_t)LB*DD];
__device__ __align__(256) bf16 g_qhh[(size_t)BB*HH*LL*HDIM];
__device__ __align__(256) bf16 g_qhl[(size_t)BB*HH*LL*HDIM];
__device__ __align__(256) bf16 g_khh[(size_t)BB*HH*PP*HDIM];
__device__ __align__(256) bf16 g_khl[(size_t)BB*HH*PP*HDIM];
__device__ __align__(256) bf16 g_vth[(size_t)BB*HH*HDIM*PP];
__device__ __align__(256) bf16 g_vtl[(size_t)BB*HH*HDIM*PP];
__device__ __align__(256) bf16 g_ph [(size_t)BB*HH*LL*PP];
__device__ __align__(256) bf16 g_pl [(size_t)BB*HH*LL*PP];
__device__ __align__(256) bf16 g_ffh[(size_t)LB*NHID];
__device__ __align__(256) bf16 g_ffl[(size_t)LB*NHID];

__device__ __align__(256) bf16 g_WqTh [(size_t)NLAYERS*DD*DD];
__device__ __align__(256) bf16 g_WqTl [(size_t)NLAYERS*DD*DD];
__device__ __align__(256) bf16 g_WkvTh[(size_t)NLAYERS*2*DD*DD];
__device__ __align__(256) bf16 g_WkvTl[(size_t)NLAYERS*2*DD*DD];
__device__ __align__(256) bf16 g_WoTh [(size_t)NLAYERS*DD*DD];
__device__ __align__(256) bf16 g_WoTl [(size_t)NLAYERS*DD*DD];
__device__ __align__(256) bf16 g_W1Th [(size_t)NLAYERS*NHID*DD];
__device__ __align__(256) bf16 g_W1Tl [(size_t)NLAYERS*NHID*DD];
__device__ __align__(256) bf16 g_W2Th [(size_t)NLAYERS*DD*NHID];
__device__ __align__(256) bf16 g_W2Tl [(size_t)NLAYERS*DD*NHID];
__device__ __align__(256) bf16 g_hW1Th[(size_t)NHID*DD];
__device__ __align__(256) bf16 g_hW1Tl[(size_t)NHID*DD];

// ---------------------------------------------------------------------------
// Helpers
// ---------------------------------------------------------------------------
__device__ __forceinline__ float warpSum(float v) {
#pragma unroll
  for (int o = 16; o > 0; o >>= 1) v += __shfl_xor_sync(0xffffffffu, v, o);
  return v;
}

__device__ __forceinline__ float blockReduceSum(float v) {
  __shared__ float sh[32];
  int lane = threadIdx.x & 31, wid = threadIdx.x >> 5;
  v = warpSum(v);
  if (lane == 0) sh[wid] = v;
  __syncthreads();
  int nw = (blockDim.x + 31) >> 5;
  v = (threadIdx.x < nw) ? sh[threadIdx.x] : 0.f;
  if (wid == 0) { v = warpSum(v); if (lane == 0) sh[0] = v; }
  __syncthreads();
  float r = sh[0];
  __syncthreads();
  return r;
}

__device__ __forceinline__ float blockReduceMax(float v) {
  __shared__ float sh[32];
  int lane = threadIdx.x & 31, wid = threadIdx.x >> 5;
#pragma unroll
  for (int o = 16; o > 0; o >>= 1) v = fmaxf(v, __shfl_xor_sync(0xffffffffu, v, o));
  if (lane == 0) sh[wid] = v;
  __syncthreads();
  int nw = (blockDim.x + 31) >> 5;
  v = (threadIdx.x < nw) ? sh[threadIdx.x] : -3.4e38f;
  if (wid == 0) {
#pragma unroll
    for (int o = 16; o > 0; o >>= 1) v = fmaxf(v, __shfl_xor_sync(0xffffffffu, v, o));
    if (lane == 0) sh[0] = v;
  }
  __syncthreads();
  float r = sh[0];
  __syncthreads();
  return r;
}

__device__ __forceinline__ float gelu_f(float x) {
  return 0.5f * x * (1.0f + erff(x * 0.7071067811865475f));
}

__device__ __forceinline__ void split2(float v, bf16& h, bf16& l) {
  h = __float2bfloat16_rn(v);
  l = __float2bfloat16_rn(v - __bfloat162float(h));
}

__device__ __forceinline__ unsigned s2u(const void* p) {
  return (unsigned)__cvta_generic_to_shared(p);
}

__device__ __forceinline__ void cpa16(unsigned s, const void* g) {
  asm volatile("cp.async.cg.shared.global [%0], [%1], 16;\n" :: "r"(s), "l"(g));
}

__device__ __forceinline__ void ldsm4(unsigned* r, unsigned addr) {
  asm volatile("ldmatrix.sync.aligned.m8n8.x4.shared.b16 {%0,%1,%2,%3}, [%4];\n"
    : "=r"(r[0]), "=r"(r[1]), "=r"(r[2]), "=r"(r[3]) : "r"(addr));
}

__device__ __forceinline__ void mma16816(float* c, const unsigned* a, const unsigned* b) {
  asm volatile("mma.sync.aligned.m16n8k16.row.col.f32.bf16.bf16.f32 "
    "{%0,%1,%2,%3}, {%4,%5,%6,%7}, {%8,%9}, {%0,%1,%2,%3};\n"
    : "+f"(c[0]), "+f"(c[1]), "+f"(c[2]), "+f"(c[3])
    : "r"(a[0]), "r"(a[1]), "r"(a[2]), "r"(a[3]), "r"(b[0]), "r"(b[1]));
}

// ---------------------------------------------------------------------------
// Preprocessing / LN / softmax / transpose kernels
// ---------------------------------------------------------------------------
__global__ void __launch_bounds__(256) colstats_kernel(const float* __restrict__ xsrc, int mode) {
  int bf = blockIdx.x;
  int b = bf / NFEAT, f = bf - b*NFEAT;
  const float* base = xsrc + (size_t)b*LL*NFEAT + f;
  float m1 = g_m1[bf], s1 = g_s1[bf];
  float m2 = g_m2[bf], s2 = g_s2[bf];
  float lo1 = m1 - 4.f*s1, hi1 = m1 + 4.f*s1;
  float inv2 = 1.f / (s2 + 1e-6f);
  float sum = 0.f, sq = 0.f;
  for (int t = threadIdx.x; t < PP; t += blockDim.x) {
    float v = base[(size_t)t*NFEAT];
    if (mode >= 1) v = fminf(fmaxf(v, lo1), hi1);
    if (mode >= 2) v = (v - m2) * inv2;
    sum += v; sq += v*v;
  }
  sum = blockReduceSum(sum);
  sq  = blockReduceSum(sq);
  if (threadIdx.x == 0) {
    float m = sum * (1.f/PP);
    float var = sq * (1.f/PP) - m*m;
    float s = sqrtf(fmaxf(var, 0.f));
    if (mode == 0)      { g_m1[bf] = m; g_s1[bf] = s; }
    else if (mode == 1) { g_m2[bf] = m; g_s2[bf] = s; }
    else                { g_m3[bf] = m; g_s3[bf] = s; }
  }
}

__global__ void __launch_bounds__(256) norm_write_kernel(const float* __restrict__ xsrc) {
  int idx = blockIdx.x * blockDim.x + threadIdx.x;
  if (idx >= LB*KPAD) return;
  int row = idx / KPAD, f = idx - row*KPAD;
  int l = row / BB, b = row - l*BB;
  float out = 0.f;
  if (f < NFEAT) {
    int bf = b*NFEAT + f;
    float v = xsrc[(size_t)b*LL*NFEAT + (size_t)l*NFEAT + f];
    float m1 = g_m1[bf], s1 = g_s1[bf];
    v = fminf(fmaxf(v, m1 - 4.f*s1), m1 + 4.f*s1);
    v = (v - g_m2[bf]) / (g_s2[bf] + 1e-6f);
    float m3 = g_m3[bf], s3 = g_s3[bf];
    v = fminf(fmaxf(v, m3 - 4.f*s3), m3 + 4.f*s3);
    if (!isfinite(v)) v = 0.f;
    out = v;
  }
  g_xn[idx] = out;
}

__global__ void __launch_bounds__(256) encode_finish_kernel(const float* __restrict__ xeD,
    const float* __restrict__ ysrc, const float* __restrict__ yencW, const float* __restrict__ yencb) {
  int row = blockIdx.x;
  int l = row / BB, b = row - l*BB;
  const float* xr = xeD + (size_t)row * DD;
  float v[4]; float sq = 0.f;
#pragma unroll
  for (int i = 0; i < 4; i++) { v[i] = xr[threadIdx.x + i*256]; sq += v[i]*v[i]; }
  float ms = blockReduceSum(sq) * (1.f/DD);
  float inv = 1.f / sqrtf(ms);
  bool addy = (l < PP);
  float yv = addy ? ysrc[(size_t)b*PP + l] : 0.f;
  float* dst = g_src + ((size_t)b*LL + l) * DD;
#pragma unroll
  for (int i = 0; i < 4; i++) {
    int c = threadIdx.x + i*256;
    float o = v[i] * inv;
    if (addy) o += yv * yencW[c] + yencb[c];
    dst[c] = o;
  }
}

__global__ void __launch_bounds__(256) ln_split_kernel(const float* __restrict__ x,
    const float* __restrict__ gg, const float* __restrict__ bbp,
    bf16* __restrict__ oh, bf16* __restrict__ ol) {
  int row = blockIdx.x;
  const float* xr = x + (size_t)row * DD;
  float v[4]; float s = 0.f;
#pragma unroll
  for (int i = 0; i < 4; i++) { v[i] = xr[threadIdx.x + i*256]; s += v[i]; }
  float m = blockReduceSum(s) * (1.f/DD);
  float d = 0.f;
#pragma unroll
  for (int i = 0; i < 4; i++) { float t = v[i]-m; d += t*t; }
  float var = blockReduceSum(d) * (1.f/DD);
  float r = rsqrtf(var + 1e-5f);
#pragma unroll
  for (int i = 0; i < 4; i++) {
    int c = threadIdx.x + i*256;
    float o = (v[i]-m)*r*gg[c] + bbp[c];
    bf16 h, l; split2(o, h, l);
    oh[(size_t)row*DD + c] = h;
    ol[(size_t)row*DD + c] = l;
  }
}

__global__ void __launch_bounds__(256) qln_split_kernel(const float* __restrict__ qraw,
    const float* __restrict__ gg, const float* __restrict__ bbp,
    bf16* __restrict__ qh, bf16* __restrict__ ql) {
  int row = blockIdx.x;
  int h = threadIdx.x >> 5, lane = threadIdx.x & 31;
  int b = row / LL, l = row - b*LL;
  const float* src = qraw + (size_t)row*DD + h*HDIM;
  float v[4]; float s = 0.f;
#pragma unroll
  for (int i = 0; i < 4; i++) { v[i] = src[lane + i*32]; s += v[i]; }
  float m = warpSum(s) * (1.f/HDIM);
  float d = 0.f;
#pragma unroll
  for (int i = 0; i < 4; i++) { float t = v[i]-m; d += t*t; }
  float var = warpSum(d) * (1.f/HDIM);
  float r = rsqrtf(var + 1e-5f);
  size_t base = ((size_t)(b*HH + h)*LL + l) * HDIM;
#pragma unroll
  for (int i = 0; i < 4; i++) {
    int c = lane + i*32;
    float o = (v[i]-m)*r*gg[c] + bbp[c];
    bf16 hh, llv; split2(o, hh, llv);
    qh[base + c] = hh; ql[base + c] = llv;
  }
}

__global__ void __launch_bounds__(256) klnv_split_kernel(const float* __restrict__ kv,
    const float* __restrict__ gg, const float* __restrict__ bbp,
    bf16* __restrict__ kh, bf16* __restrict__ kl, float* __restrict__ vh) {
  int row = blockIdx.x;
  int h = threadIdx.x >> 5, lane = threadIdx.x & 31;
  int b = row / PP, t = row - b*PP;
  const float* kp = kv + (size_t)row*2*DD + h*HDIM;
  const float* vp = kp + DD;
  float v[4]; float s = 0.f;
#pragma unroll
  for (int i = 0; i < 4; i++) { v[i] = kp[lane + i*32]; s += v[i]; }
  float m = warpSum(s) * (1.f/HDIM);
  float d = 0.f;
#pragma unroll
  for (int i = 0; i < 4; i++) { float t2 = v[i]-m; d += t2*t2; }
  float var = warpSum(d) * (1.f/HDIM);
  float r = rsqrtf(var + 1e-5f);
  size_t base = ((size_t)(b*HH + h)*PP + t) * HDIM;
#pragma unroll
  for (int i = 0; i < 4; i++) {
    int c = lane + i*32;
    float o = (v[i]-m)*r*gg[c] + bbp[c];
    bf16 hh, llv; split2(o, hh, llv);
    kh[base + c] = hh; kl[base + c] = llv;
    vh[base + c] = vp[c];
  }
}

__global__ void __launch_bounds__(256) softmax_split_kernel(const float* __restrict__ x,
    bf16* __restrict__ ph, bf16* __restrict__ pl) {
  const float* xr = x + (size_t)blockIdx.x * PP;
  float v[4];
  float mx = -3.4e38f;
#pragma unroll
  for (int i = 0; i < 4; i++) { v[i] = xr[threadIdx.x + i*256]; mx = fmaxf(mx, v[i]); }
  mx = blockReduceMax(mx);
  float s = 0.f;
#pragma unroll
  for (int i = 0; i < 4; i++) { v[i] = expf(v[i] - mx); s += v[i]; }
  float tot = blockReduceSum(s);
  float inv = 1.f / tot;
  size_t base = (size_t)blockIdx.x * PP;
#pragma unroll
  for (int i = 0; i < 4; i++) {
    float p = v[i] * inv;
    bf16 h, l; split2(p, h, l);
    int c = threadIdx.x + i*256;
    ph[base + c] = h; pl[base + c] = l;
  }
}

__global__ void __launch_bounds__(256) split_rows_kernel(const float* __restrict__ x,
    bf16* __restrict__ h, bf16* __restrict__ l, int n) {
  int idx = blockIdx.x * blockDim.x + threadIdx.x;
  if (idx >= n) return;
  bf16 hh, llv; split2(x[idx], hh, llv);
  h[idx] = hh; l[idx] = llv;
}

__global__ void __launch_bounds__(256) transpose_split_kernel(const float* __restrict__ src,
    bf16* __restrict__ dh, bf16* __restrict__ dl, int R, int C,
    ll sStride, ll dStride) {
  __shared__ float t[32][33];
  int z = blockIdx.z;
  src += (ll)z * sStride;
  dh  += (ll)z * dStride;
  dl  += (ll)z * dStride;
  int c0 = blockIdx.x * 32, r0 = blockIdx.y * 32;
  int tx = threadIdx.x & 31, ty = threadIdx.x >> 5;
#pragma unroll
  for (int j = ty; j < 32; j += 8)
    t[j][tx] = src[(size_t)(r0+j)*C + c0 + tx];
  __syncthreads();
#pragma unroll
  for (int j = ty; j < 32; j += 8) {
    float v = t[tx][j];
    bf16 hh, llv; split2(v, hh, llv);
    size_t off = (size_t)(c0+j)*R + r0 + tx;
    dh[off] = hh; dl[off] = llv;
  }
}

// ---------------------------------------------------------------------------
// fp32 SGEMM (encoder only)
// ---------------------------------------------------------------------------
template<bool HASBIAS>
__global__ void __launch_bounds__(256, 2) sgemm_kernel(
    const float* __restrict__ A, const float* __restrict__ B, float* __restrict__ C,
    const float* __restrict__ bias, int K, int kGuard, int lda, int ldb, int ldc)
{
  __shared__ float As[16][128];
  __shared__ float Bs[16][128];
  const int tid = threadIdx.x;
  const int row0 = blockIdx.y * 128;
  const int col0 = blockIdx.x * 128;
  const int tx = tid & 15, ty = tid >> 4;
  const int tm0 = ty*8, tn0 = tx*8;
  float acc[8][8];
#pragma unroll
  for (int i = 0; i < 8; i++)
#pragma unroll
    for (int j = 0; j < 8; j++) acc[i][j] = 0.f;
  for (int k0 = 0; k0 < K; k0 += 16) {
#pragma unroll
    for (int u = 0; u < 2; u++) {
      int f = tid + u*256;
      int r = f >> 2, c4 = (f & 3) << 2;
      float4 va = *reinterpret_cast<const float4*>(A + (size_t)(row0 + r)*lda + (k0 + c4));
      As[c4+0][r] = va.x; As[c4+1][r] = va.y; As[c4+2][r] = va.z; As[c4+3][r] = va.w;
    }
#pragma unroll
    for (int u = 0; u < 2; u++) {
      int f = tid + u*256;
      int kk = f >> 5, n4 = (f & 31) << 2;
      float4 vb = make_float4(0.f, 0.f, 0.f, 0.f);
      if (k0 + kk < kGuard)
        vb = *reinterpret_cast<const float4*>(B + (size_t)(k0 + kk)*ldb + (col0 + n4));
      *reinterpret_cast<float4*>(&Bs[kk][n4]) = vb;
    }
    __syncthreads();
#pragma unroll
    for (int kk = 0; kk < 16; kk++) {
      float4 a0 = *reinterpret_cast<const float4*>(&As[kk][tm0]);
      float4 a1 = *reinterpret_cast<const float4*>(&As[kk][tm0+4]);
      float4 b0 = *reinterpret_cast<const float4*>(&Bs[kk][tn0]);
      float4 b1 = *reinterpret_cast<const float4*>(&Bs[kk][tn0+4]);
      float ra[8] = {a0.x,a0.y,a0.z,a0.w,a1.x,a1.y,a1.z,a1.w};
      float rb[8] = {b0.x,b0.y,b0.z,b0.w,b1.x,b1.y,b1.z,b1.w};
#pragma unroll
      for (int i = 0; i < 8; i++)
#pragma unroll
        for (int j = 0; j < 8; j++)
          acc[i][j] = fmaf(ra[i], rb[j], acc[i][j]);
    }
    __syncthreads();
  }
#pragma unroll
  for (int i = 0; i < 8; i++) {
    float* crow = C + (size_t)(row0 + tm0 + i)*ldc + (col0 + tn0);
#pragma unroll
    for (int j = 0; j < 8; j += 4) {
      float4 v;
      v.x = acc[i][j+0]; v.y = acc[i][j+1]; v.z = acc[i][j+2]; v.w = acc[i][j+3];
      if (HASBIAS) {
        float4 bbv = *reinterpret_cast<const float4*>(bias + col0 + tn0 + j);
        v.x += bbv.x; v.y += bbv.y; v.z += bbv.z; v.w += bbv.w;
      }
      *reinterpret_cast<float4*>(crow + j) = v;
    }
  }
}

// ---------------------------------------------------------------------------
// mma.sync GEMM v2 (bf16x3 split): C = act(alpha*(Ah+Al)@(Bh+Bl)^T + bias)
// Block 128 x BN (BN=256 or 128), 256 threads = 8 warps in 2(M)x4(N) layout,
// warp tile 64 x BN/4. K-chunk 32, 3-stage cp.async pipeline.
// ---------------------------------------------------------------------------
template<int BN>
__device__ __forceinline__ void load_chunk2(bf16* stage,
    const bf16* __restrict__ Ah, const bf16* __restrict__ Al,
    const bf16* __restrict__ Bh, const bf16* __restrict__ Bl,
    int row0, int col0, int k0, int lda, int ldb, int tid) {
  const int SA = 128*40;
  const int SB = BN*40;
  bf16* sAh = stage;
  bf16* sAl = stage + SA;
  bf16* sBh = stage + 2*SA;
  bf16* sBl = stage + 2*SA + SB;
#pragma unroll
  for (int i = 0; i < 2; i++) {
    int idx = tid + (i << 8);
    int r = idx >> 2, c4 = idx & 3;
    int so = r*40 + c4*8;
    const bf16* ga = Ah + (size_t)(row0 + r)*lda + k0 + c4*8;
    const bf16* gl = Al + (size_t)(row0 + r)*lda + k0 + c4*8;
    cpa16(s2u(sAh + so), ga);
    cpa16(s2u(sAl + so), gl);
  }
#pragma unroll
  for (int i = 0; i < BN/64; i++) {
    int idx = tid + (i << 8);
    int r = idx >> 2, c4 = idx & 3;
    int so = r*40 + c4*8;
    const bf16* gb = Bh + (size_t)(col0 + r)*ldb + k0 + c4*8;
    const bf16* gl = Bl + (size_t)(col0 + r)*ldb + k0 + c4*8;
    cpa16(s2u(sBh + so), gb);
    cpa16(s2u(sBl + so), gl);
  }
}

template<int BN, bool ACT, bool HASBIAS, int OUTMODE>
__global__ void __launch_bounds__(256) mma2_kernel(
    const bf16* __restrict__ Ah, const bf16* __restrict__ Al,
    const bf16* __restrict__ Bh, const bf16* __restrict__ Bl,
    float* __restrict__ C, bf16* __restrict__ Ch, bf16* __restrict__ Cl,
    const float* __restrict__ bias,
    int K, int lda, int ldb, int ldc, int inner,
    ll aSO, ll aSI, ll bSO, ll bSI, ll cSO, ll cSI, float alpha)
{
  extern __shared__ __align__(128) bf16 smb[];
  const int SA = 128*40;
  const int SB = BN*40;
  const int STAGE = 2*SA + 2*SB;
  const int WN = BN/4;
  const int NTn = WN/8;

  int bz = blockIdx.z;
  int bo = bz / inner, bi = bz - bo*inner;
  ll aoff = (ll)bo*aSO + (ll)bi*aSI;
  ll boff = (ll)bo*bSO + (ll)bi*bSI;
  ll coff = (ll)bo*cSO + (ll)bi*cSI;
  Ah += aoff; Al += aoff; Bh += boff; Bl += boff;

  const int tid = threadIdx.x, wid = tid >> 5, lane = tid & 31;
  const int row0 = blockIdx.y * 128;
  const int col0 = blockIdx.x * BN;
  const int wm = (wid & 1) * 64;
  const int wn = (wid >> 1) * WN;

  float acc[4][8][4];
#pragma unroll
  for (int mt = 0; mt < 4; mt++)
#pragma unroll
    for (int nt = 0; nt < NTn; nt++)
#pragma unroll
      for (int q = 0; q < 4; q++) acc[mt][nt][q] = 0.f;

  const int NC = K >> 5;

  load_chunk2<BN>(smb,         Ah, Al, Bh, Bl, row0, col0, 0,  lda, ldb, tid);
  asm volatile("cp.async.commit_group;\n");
  load_chunk2<BN>(smb + STAGE, Ah, Al, Bh, Bl, row0, col0, 32, lda, ldb, tid);
  asm volatile("cp.async.commit_group;\n");

  const int arow = lane & 15;
  const int khalf = (lane >> 4) << 3;

  for (int c = 0; c < NC; c++) {
    asm volatile("cp.async.wait_group 1;\n" ::: "memory");
    __syncthreads();
    if (c + 2 < NC) {
      load_chunk2<BN>(smb + ((c+2)%3)*STAGE, Ah, Al, Bh, Bl,
                      row0, col0, (c+2) << 5, lda, ldb, tid);
    }
    asm volatile("cp.async.commit_group;\n");

    bf16* st  = smb + (c%3)*STAGE;
    bf16* sAh = st;
    bf16* sAl = st + SA;
    bf16* sBh = st + 2*SA;
    bf16* sBl = st + 2*SA + SB;

#pragma unroll
    for (int kk = 0; kk < 2; kk++) {
      int kof = kk*16 + khalf;
      unsigned ahf[4][4], alf[4][4], bfr[8][2];
#pragma unroll
      for (int mt = 0; mt < 4; mt++) {
        ldsm4(ahf[mt], s2u(sAh + (wm + mt*16 + arow)*40 + kof));
        ldsm4(alf[mt], s2u(sAl + (wm + mt*16 + arow)*40 + kof));
      }
#pragma unroll
      for (int np = 0; np < NTn/2; np++) {
        unsigned t[4];
        ldsm4(t, s2u(sBh + (wn + np*16 + arow)*40 + kof));
        bfr[2*np][0] = t[0]; bfr[2*np][1] = t[2];
        bfr[2*np+1][0] = t[1]; bfr[2*np+1][1] = t[3];
      }
#pragma unroll
      for (int mt = 0; mt < 4; mt++)
#pragma unroll
        for (int nt = 0; nt < NTn; nt++)
          mma16816(acc[mt][nt], ahf[mt], bfr[nt]);
#pragma unroll
      for (int mt = 0; mt < 4; mt++)
#pragma unroll
        for (int nt = 0; nt < NTn; nt++)
          mma16816(acc[mt][nt], alf[mt], bfr[nt]);
#pragma unroll
      for (int np = 0; np < NTn/2; np++) {
        unsigned t[4];
        ldsm4(t, s2u(sBl + (wn + np*16 + arow)*40 + kof));
        bfr[2*np][0] = t[0]; bfr[2*np][1] = t[2];
        bfr[2*np+1][0] = t[1]; bfr[2*np+1][1] = t[3];
      }
#pragma unroll
      for (int mt = 0; mt < 4; mt++)
#pragma unroll
        for (int nt = 0; nt < NTn; nt++)
          mma16816(acc[mt][nt], ahf[mt], bfr[nt]);
    }
  }

  int rb = row0 + wm + (lane >> 2);
  int cb = col0 + wn + (lane & 3)*2;
#pragma unroll
  for (int mt = 0; mt < 4; mt++) {
#pragma unroll
    for (int nt = 0; nt < NTn; nt++) {
#pragma unroll
      for (int h2 = 0; h2 < 2; h2++) {
        int r = rb + mt*16 + h2*8;
        int cc = cb + nt*8;
        float v0 = alpha * acc[mt][nt][h2*2+0];
        float v1 = alpha * acc[mt][nt][h2*2+1];
        if (HASBIAS) { v0 += bias[cc]; v1 += bias[cc+1]; }
        if (ACT) { v0 = gelu_f(v0); v1 = gelu_f(v1); }
        ll off = coff + (ll)r*ldc + cc;
        if (OUTMODE == 0) {
          float2 o; o.x = v0; o.y = v1;
          *reinterpret_cast<float2*>(C + off) = o;
        } else if (OUTMODE == 1) {
          float2 o = *reinterpret_cast<const float2*>(C + off);
          o.x += v0; o.y += v1;
          *reinterpret_cast<float2*>(C + off) = o;
        } else {
          bf16 h0, l0, h1, l1;
          split2(v0, h0, l0); split2(v1, h1, l1);
          __nv_bfloat162 phv; phv.x = h0; phv.y = h1;
          __nv_bfloat162 plv; plv.x = l0; plv.y = l1;
          *reinterpret_cast<__nv_bfloat162*>(Ch + off) = phv;
          *reinterpret_cast<__nv_bfloat162*>(Cl + off) = plv;
        }
      }
    }
  }
}

// ---------------------------------------------------------------------------
// Head second GEMM
// ---------------------------------------------------------------------------
__global__ void __launch_bounds__(256) head2_kernel(const bf16* __restrict__ hbh,
    const bf16* __restrict__ hbl, const float* __restrict__ W2,
    const float* __restrict__ b2, float* __restrict__ out) {
  int idx = blockIdx.x;
  int b = idx / PP, t = idx - b*PP;
  const bf16* hh = hbh + (size_t)idx * NHID;
  const bf16* hl = hbl + (size_t)idx * NHID;
  float acc[NOUTD];
#pragma unroll
  for (int o = 0; o < NOUTD; o++) acc[o] = 0.f;
  for (int k = threadIdx.x; k < NHID; k += 256) {
    float v = __bfloat162float(hh[k]) + __bfloat162float(hl[k]);
    const float* w = W2 + (size_t)k * (NOUTD + 1);
#pragma unroll
    for (int o = 0; o < NOUTD; o++) acc[o] += v * w[o];
  }
  __shared__ float smr[8][NOUTD];
  int lane = threadIdx.x & 31, wid = threadIdx.x >> 5;
#pragma unroll
  for (int o = 0; o < NOUTD; o++) acc[o] = warpSum(acc[o]);
  if (lane == 0) {
#pragma unroll
    for (int o = 0; o < NOUTD; o++) smr[wid][o] = acc[o];
  }
  __syncthreads();
  if (threadIdx.x < NOUTD) {
    float sv = 0.f;
#pragma unroll
    for (int w = 0; w < 8; w++) sv += smr[w][threadIdx.x];
    out[((size_t)t*BB + b)*NOUTD + threadIdx.x] = sv + b2[threadIdx.x];
  }
}

// ---------------------------------------------------------------------------
// Orchestration
// ---------------------------------------------------------------------------
typedef void (*mm_fn)(const bf16*, const bf16*, const bf16*, const bf16*,
                      float*, bf16*, bf16*, const float*,
                      int, int, int, int, int, ll, ll, ll, ll, ll, ll, float);

extern "C" void kernel_launch(void* const* d_in, const int* in_sizes, int n_in,
                              void* d_out, int out_size) {
  (void)in_sizes; (void)n_in; (void)out_size;
  const float* x_src = (const float*)d_in[0];
  const float* y_src = (const float*)d_in[1];
  const float* enc_W = (const float*)d_in[2];
  const float* enc_b = (const float*)d_in[3];
  const float* yenc_W = (const float*)d_in[4];
  const float* yenc_b = (const float*)d_in[5];
  const float* Wq    = (const float*)d_in[6];
  const float* Wkv   = (const float*)d_in[7];
  const float* Wout  = (const float*)d_in[8];
  const float* an_g  = (const float*)d_in[9];
  const float* an_b  = (const float*)d_in[10];
  const float* qn_g  = (const float*)d_in[11];
  const float* qn_b  = (const float*)d_in[12];
  const float* kn_g  = (const float*)d_in[13];
  const float* kn_b  = (const float*)d_in[14];
  const float* fn_g  = (const float*)d_in[15];
  const float* fn_b  = (const float*)d_in[16];
  const float* ffW1  = (const float*)d_in[17];
  const float* ffb1  = (const float*)d_in[18];
  const float* ffW2  = (const float*)d_in[19];
  const float* ffb2  = (const float*)d_in[20];
  const float* hW1   = (const float*)d_in[21];
  const float* hb1   = (const float*)d_in[22];
  const float* hW2   = (const float*)d_in[23];
  const float* hb2   = (const float*)d_in[24];
  float* out = (float*)d_out;

  const int SM256 = 3 * 2 * 2 * 40 * (128 + 256);   // 184320
  const int SM128 = 3 * 2 * 2 * 40 * (128 + 128);   // 122880
  {
    mm_fn f;
    f = mma2_kernel<256,false,false,0>;
    cudaFuncSetAttribute(f, cudaFuncAttributeMaxDynamicSharedMemorySize, SM256);
    f = mma2_kernel<256,false,false,1>;
    cudaFuncSetAttribute(f, cudaFuncAttributeMaxDynamicSharedMemorySize, SM256);
    f = mma2_kernel<256,true,true,2>;
    cudaFuncSetAttribute(f, cudaFuncAttributeMaxDynamicSharedMemorySize, SM256);
    f = mma2_kernel<256,false,true,1>;
    cudaFuncSetAttribute(f, cudaFuncAttributeMaxDynamicSharedMemorySize, SM256);
    f = mma2_kernel<128,false,false,2>;
    cudaFuncSetAttribute(f, cudaFuncAttributeMaxDynamicSharedMemorySize, SM128);
  }

  float *p_xn, *p_src, *p_tmp, *p_vh, *p_logits;
  cudaGetSymbolAddress((void**)&p_xn, g_xn);
  cudaGetSymbolAddress((void**)&p_src, g_src);
  cudaGetSymbolAddress((void**)&p_tmp, g_tmp);
  cudaGetSymbolAddress((void**)&p_vh, g_vh);
  cudaGetSymbolAddress((void**)&p_logits, g_logits);
  bf16 *p_ah, *p_al, *p_qhh, *p_qhl, *p_khh, *p_khl;
  bf16 *p_vth, *p_vtl, *p_ph, *p_pl, *p_ffh, *p_ffl;
  cudaGetSymbolAddress((void**)&p_ah, g_ah);
  cudaGetSymbolAddress((void**)&p_al, g_al);
  cudaGetSymbolAddress((void**)&p_qhh, g_qhh);
  cudaGetSymbolAddress((void**)&p_qhl, g_qhl);
  cudaGetSymbolAddress((void**)&p_khh, g_khh);
  cudaGetSymbolAddress((void**)&p_khl, g_khl);
  cudaGetSymbolAddress((void**)&p_vth, g_vth);
  cudaGetSymbolAddress((void**)&p_vtl, g_vtl);
  cudaGetSymbolAddress((void**)&p_ph, g_ph);
  cudaGetSymbolAddress((void**)&p_pl, g_pl);
  cudaGetSymbolAddress((void**)&p_ffh, g_ffh);
  cudaGetSymbolAddress((void**)&p_ffl, g_ffl);
  bf16 *pWqh, *pWql, *pWkvh, *pWkvl, *pWoh, *pWol;
  bf16 *pW1h, *pW1l, *pW2h, *pW2l, *pHW1h, *pHW1l;
  cudaGetSymbolAddress((void**)&pWqh, g_WqTh);
  cudaGetSymbolAddress((void**)&pWql, g_WqTl);
  cudaGetSymbolAddress((void**)&pWkvh, g_WkvTh);
  cudaGetSymbolAddress((void**)&pWkvl, g_WkvTl);
  cudaGetSymbolAddress((void**)&pWoh, g_WoTh);
  cudaGetSymbolAddress((void**)&pWol, g_WoTl);
  cudaGetSymbolAddress((void**)&pW1h, g_W1Th);
  cudaGetSymbolAddress((void**)&pW1l, g_W1Tl);
  cudaGetSymbolAddress((void**)&pW2h, g_W2Th);
  cudaGetSymbolAddress((void**)&pW2l, g_W2Tl);
  cudaGetSymbolAddress((void**)&pHW1h, g_hW1Th);
  cudaGetSymbolAddress((void**)&pHW1l, g_hW1Tl);

  const float qk_scale = 0.08838834764831845f;

  transpose_split_kernel<<<dim3(DD/32, DD/32, NLAYERS), 256>>>(Wq, pWqh, pWql, DD, DD, (ll)DD*DD, (ll)DD*DD);
  transpose_split_kernel<<<dim3(2*DD/32, DD/32, NLAYERS), 256>>>(Wkv, pWkvh, pWkvl, DD, 2*DD, (ll)DD*2*DD, (ll)DD*2*DD);
  transpose_split_kernel<<<dim3(DD/32, DD/32, NLAYERS), 256>>>(Wout, pWoh, pWol, DD, DD, (ll)DD*DD, (ll)DD*DD);
  transpose_split_kernel<<<dim3(NHID/32, DD/32, NLAYERS), 256>>>(ffW1, pW1h, pW1l, DD, NHID, (ll)DD*NHID, (ll)DD*NHID);
  transpose_split_kernel<<<dim3(DD/32, NHID/32, NLAYERS), 256>>>(ffW2, pW2h, pW2l, NHID, DD, (ll)NHID*DD, (ll)NHID*DD);
  transpose_split_kernel<<<dim3(NHID/32, DD/32, 1), 256>>>(hW1, pHW1h, pHW1l, DD, NHID, 0, 0);

  colstats_kernel<<<BB*NFEAT, 256>>>(x_src, 0);
  colstats_kernel<<<BB*NFEAT, 256>>>(x_src, 1);
  colstats_kernel<<<BB*NFEAT, 256>>>(x_src, 2);
  norm_write_kernel<<<(LB*KPAD + 255)/256, 256>>>(x_src);
  sgemm_kernel<true><<<dim3(DD/128, LB/128, 1), 256>>>(
      p_xn, enc_W, p_tmp, enc_b, KPAD, NFEAT, KPAD, DD, DD);
  encode_finish_kernel<<<LB, 256>>>(p_tmp, y_src, yenc_W, yenc_b);

  for (int i = 0; i < NLAYERS; i++) {
    ln_split_kernel<<<LB, 256>>>(p_src, an_g + i*DD, an_b + i*DD, p_ah, p_al);
    mma2_kernel<256,false,false,0><<<dim3(4, 64, 1), 256, SM256>>>(
        p_ah, p_al, pWqh + (size_t)i*DD*DD, pWql + (size_t)i*DD*DD,
        p_tmp, nullptr, nullptr, nullptr,
        DD, DD, DD, DD, 1, 0,0,0,0,0,0, 1.f);
    qln_split_kernel<<<LB, 256>>>(p_tmp, qn_g + i*HDIM, qn_b + i*HDIM, p_qhh, p_qhl);
    mma2_kernel<256,false,false,0><<<dim3(8, 8, BB), 256, SM256>>>(
        p_ah, p_al, pWkvh + (size_t)i*DD*2*DD, pWkvl + (size_t)i*DD*2*DD,
        p_tmp, nullptr, nullptr, nullptr,
        DD, DD, DD, 2*DD, 1,
        (ll)LL*DD, 0, 0, 0, (ll)PP*2*DD, 0, 1.f);
    klnv_split_kernel<<<BB*PP, 256>>>(p_tmp, kn_g + i*HDIM, kn_b + i*HDIM, p_khh, p_khl, p_vh);
    transpose_split_kernel<<<dim3(HDIM/32, PP/32, BB*HH), 256>>>(
        p_vh, p_vth, p_vtl, PP, HDIM, (ll)PP*HDIM, (ll)PP*HDIM);
    mma2_kernel<256,false,false,0><<<dim3(4, 16, BB*HH), 256, SM256>>>(
        p_qhh, p_qhl, p_khh, p_khl, p_logits, nullptr, nullptr, nullptr,
        HDIM, HDIM, HDIM, PP, 1,
        (ll)LL*HDIM, 0, (ll)PP*HDIM, 0, (ll)LL*PP, 0, qk_scale);
    softmax_split_kernel<<<BB*HH*LL, 256>>>(p_logits, p_ph, p_pl);
    mma2_kernel<128,false,false,2><<<dim3(1, 16, BB*HH), 256, SM128>>>(
        p_ph, p_pl, p_vth, p_vtl, nullptr, p_ah, p_al, nullptr,
        PP, PP, PP, DD, HH,
        (ll)HH*LL*PP, (ll)LL*PP,
        (ll)HH*HDIM*PP, (ll)HDIM*PP,
        (ll)LL*DD, (ll)HDIM, 1.f);
    mma2_kernel<256,false,false,1><<<dim3(4, 64, 1), 256, SM256>>>(
        p_ah, p_al, pWoh + (size_t)i*DD*DD, pWol + (size_t)i*DD*DD,
        p_src, nullptr, nullptr, nullptr,
        DD, DD, DD, DD, 1, 0,0,0,0,0,0, 1.f);
    ln_split_kernel<<<LB, 256>>>(p_src, fn_g + i*DD, fn_b + i*DD, p_ah, p_al);
    mma2_kernel<256,true,true,2><<<dim3(NHID/256, 64, 1), 256, SM256>>>(
        p_ah, p_al, pW1h + (size_t)i*NHID*DD, pW1l + (size_t)i*NHID*DD,
        nullptr, p_ffh, p_ffl, ffb1 + (size_t)i*NHID,
        DD, DD, DD, NHID, 1, 0,0,0,0,0,0, 1.f);
    mma2_kernel<256,false,true,1><<<dim3(4, 64, 1), 256, SM256>>>(
        p_ffh, p_ffl, pW2h + (size_t)i*DD*NHID, pW2l + (size_t)i*DD*NHID,
        p_src, nullptr, nullptr, ffb2 + (size_t)i*DD,
        NHID, NHID, NHID, DD, 1, 0,0,0,0,0,0, 1.f);
  }

  split_rows_kernel<<<(LB*DD + 255)/256, 256>>>(p_src, p_ah, p_al, LB*DD);
  mma2_kernel<256,true,true,2><<<dim3(NHID/256, PP/128, BB), 256, SM256>>>(
      p_ah + (size_t)PP*DD, p_al + (size_t)PP*DD, pHW1h, pHW1l,
      nullptr, p_ffh, p_ffl, hb1,
      DD, DD, DD, NHID, 1,
      (ll)LL*DD, 0, 0, 0, (ll)PP*NHID, 0, 1.f);
  head2_kernel<<<BB*PP, 256>>>(p_ffh, p_ffl, hW2, hb2, out);
}

// round 8
// speedup vs baseline: 1.1026x; 1.1026x over previous
#include <cuda_runtime.h>
#include <cuda_bf16.h>
#include <cstdint>
#include <cstddef>
#include <math.h>

// ---------------------------------------------------------------------------
// Problem constants
// ---------------------------------------------------------------------------
#define BB     4
#define LL     2048
#define PP     1024
#define NFEAT  100
#define DD     1024
#define HH     8
#define HDIM   128
#define NHID   4096
#define NLAYERS 3
#define NOUTD  10
#define LB     (LL*BB)
#define KPAD   112

typedef __nv_bfloat16 bf16;
typedef long long ll;

// ---------------------------------------------------------------------------
// Scratch (device globals)
// ---------------------------------------------------------------------------
__device__ float g_m1[BB*NFEAT], g_s1[BB*NFEAT];
__device__ float g_m2[BB*NFEAT], g_s2[BB*NFEAT];
__device__ float g_m3[BB*NFEAT], g_s3[BB*NFEAT];
__device__ __align__(256) float g_xn[(size_t)LB*KPAD];
__device__ __align__(256) float g_src[(size_t)LB*DD];
__device__ __align__(256) float g_tmp[(size_t)LB*DD];
__device__ __align__(256) float g_vh [(size_t)BB*HH*PP*HDIM];
__device__ __align__(256) float g_logits[(size_t)BB*HH*LL*PP];

__device__ __align__(256) bf16 g_ah[(size_t)LB*DD];
__device__ __align__(256) bf16 g_al[(size_t)LB*DD];
__device__ __align__(256) bf16 g_qhh[(size_t)BB*HH*LL*HDIM];
__device__ __align__(256) bf16 g_qhl[(size_t)BB*HH*LL*HDIM];
__device__ __align__(256) bf16 g_khh[(size_t)BB*HH*PP*HDIM];
__device__ __align__(256) bf16 g_khl[(size_t)BB*HH*PP*HDIM];
__device__ __align__(256) bf16 g_vth[(size_t)BB*HH*HDIM*PP];
__device__ __align__(256) bf16 g_vtl[(size_t)BB*HH*HDIM*PP];
__device__ __align__(256) bf16 g_ph [(size_t)BB*HH*LL*PP];
__device__ __align__(256) bf16 g_pl [(size_t)BB*HH*LL*PP];
__device__ __align__(256) bf16 g_ffh[(size_t)LB*NHID];
__device__ __align__(256) bf16 g_ffl[(size_t)LB*NHID];

__device__ __align__(256) bf16 g_WqTh [(size_t)NLAYERS*DD*DD];
__device__ __align__(256) bf16 g_WqTl [(size_t)NLAYERS*DD*DD];
__device__ __align__(256) bf16 g_WkvTh[(size_t)NLAYERS*2*DD*DD];
__device__ __align__(256) bf16 g_WkvTl[(size_t)NLAYERS*2*DD*DD];
__device__ __align__(256) bf16 g_WoTh [(size_t)NLAYERS*DD*DD];
__device__ __align__(256) bf16 g_WoTl [(size_t)NLAYERS*DD*DD];
__device__ __align__(256) bf16 g_W1Th [(size_t)NLAYERS*NHID*DD];
__device__ __align__(256) bf16 g_W1Tl [(size_t)NLAYERS*NHID*DD];
__device__ __align__(256) bf16 g_W2Th [(size_t)NLAYERS*DD*NHID];
__device__ __align__(256) bf16 g_W2Tl [(size_t)NLAYERS*DD*NHID];
__device__ __align__(256) bf16 g_hW1Th[(size_t)NHID*DD];
__device__ __align__(256) bf16 g_hW1Tl[(size_t)NHID*DD];

// ---------------------------------------------------------------------------
// Helpers
// ---------------------------------------------------------------------------
__device__ __forceinline__ float warpSum(float v) {
#pragma unroll
  for (int o = 16; o > 0; o >>= 1) v += __shfl_xor_sync(0xffffffffu, v, o);
  return v;
}

__device__ __forceinline__ float blockReduceSum(float v) {
  __shared__ float sh[32];
  int lane = threadIdx.x & 31, wid = threadIdx.x >> 5;
  v = warpSum(v);
  if (lane == 0) sh[wid] = v;
  __syncthreads();
  int nw = (blockDim.x + 31) >> 5;
  v = (threadIdx.x < nw) ? sh[threadIdx.x] : 0.f;
  if (wid == 0) { v = warpSum(v); if (lane == 0) sh[0] = v; }
  __syncthreads();
  float r = sh[0];
  __syncthreads();
  return r;
}

__device__ __forceinline__ float blockReduceMax(float v) {
  __shared__ float sh[32];
  int lane = threadIdx.x & 31, wid = threadIdx.x >> 5;
#pragma unroll
  for (int o = 16; o > 0; o >>= 1) v = fmaxf(v, __shfl_xor_sync(0xffffffffu, v, o));
  if (lane == 0) sh[wid] = v;
  __syncthreads();
  int nw = (blockDim.x + 31) >> 5;
  v = (threadIdx.x < nw) ? sh[threadIdx.x] : -3.4e38f;
  if (wid == 0) {
#pragma unroll
    for (int o = 16; o > 0; o >>= 1) v = fmaxf(v, __shfl_xor_sync(0xffffffffu, v, o));
    if (lane == 0) sh[0] = v;
  }
  __syncthreads();
  float r = sh[0];
  __syncthreads();
  return r;
}

__device__ __forceinline__ float gelu_f(float x) {
  return 0.5f * x * (1.0f + erff(x * 0.7071067811865475f));
}

__device__ __forceinline__ void split2(float v, bf16& h, bf16& l) {
  h = __float2bfloat16_rn(v);
  l = __float2bfloat16_rn(v - __bfloat162float(h));
}

__device__ __forceinline__ unsigned s2u(const void* p) {
  return (unsigned)__cvta_generic_to_shared(p);
}

__device__ __forceinline__ void cpa16(unsigned s, const void* g) {
  asm volatile("cp.async.cg.shared.global [%0], [%1], 16;\n" :: "r"(s), "l"(g));
}

__device__ __forceinline__ void ldsm4(unsigned* r, unsigned addr) {
  asm volatile("ldmatrix.sync.aligned.m8n8.x4.shared.b16 {%0,%1,%2,%3}, [%4];\n"
    : "=r"(r[0]), "=r"(r[1]), "=r"(r[2]), "=r"(r[3]) : "r"(addr));
}

__device__ __forceinline__ void mma16816(float* c, const unsigned* a, const unsigned* b) {
  asm volatile("mma.sync.aligned.m16n8k16.row.col.f32.bf16.bf16.f32 "
    "{%0,%1,%2,%3}, {%4,%5,%6,%7}, {%8,%9}, {%0,%1,%2,%3};\n"
    : "+f"(c[0]), "+f"(c[1]), "+f"(c[2]), "+f"(c[3])
    : "r"(a[0]), "r"(a[1]), "r"(a[2]), "r"(a[3]), "r"(b[0]), "r"(b[1]));
}

// ---------------------------------------------------------------------------
// Preprocessing / LN / softmax / transpose kernels
// ---------------------------------------------------------------------------
__global__ void __launch_bounds__(256) colstats_kernel(const float* __restrict__ xsrc, int mode) {
  int bf = blockIdx.x;
  int b = bf / NFEAT, f = bf - b*NFEAT;
  const float* base = xsrc + (size_t)b*LL*NFEAT + f;
  float m1 = g_m1[bf], s1 = g_s1[bf];
  float m2 = g_m2[bf], s2 = g_s2[bf];
  float lo1 = m1 - 4.f*s1, hi1 = m1 + 4.f*s1;
  float inv2 = 1.f / (s2 + 1e-6f);
  float sum = 0.f, sq = 0.f;
  for (int t = threadIdx.x; t < PP; t += blockDim.x) {
    float v = base[(size_t)t*NFEAT];
    if (mode >= 1) v = fminf(fmaxf(v, lo1), hi1);
    if (mode >= 2) v = (v - m2) * inv2;
    sum += v; sq += v*v;
  }
  sum = blockReduceSum(sum);
  sq  = blockReduceSum(sq);
  if (threadIdx.x == 0) {
    float m = sum * (1.f/PP);
    float var = sq * (1.f/PP) - m*m;
    float s = sqrtf(fmaxf(var, 0.f));
    if (mode == 0)      { g_m1[bf] = m; g_s1[bf] = s; }
    else if (mode == 1) { g_m2[bf] = m; g_s2[bf] = s; }
    else                { g_m3[bf] = m; g_s3[bf] = s; }
  }
}

__global__ void __launch_bounds__(256) norm_write_kernel(const float* __restrict__ xsrc) {
  int idx = blockIdx.x * blockDim.x + threadIdx.x;
  if (idx >= LB*KPAD) return;
  int row = idx / KPAD, f = idx - row*KPAD;
  int l = row / BB, b = row - l*BB;
  float out = 0.f;
  if (f < NFEAT) {
    int bf = b*NFEAT + f;
    float v = xsrc[(size_t)b*LL*NFEAT + (size_t)l*NFEAT + f];
    float m1 = g_m1[bf], s1 = g_s1[bf];
    v = fminf(fmaxf(v, m1 - 4.f*s1), m1 + 4.f*s1);
    v = (v - g_m2[bf]) / (g_s2[bf] + 1e-6f);
    float m3 = g_m3[bf], s3 = g_s3[bf];
    v = fminf(fmaxf(v, m3 - 4.f*s3), m3 + 4.f*s3);
    if (!isfinite(v)) v = 0.f;
    out = v;
  }
  g_xn[idx] = out;
}

__global__ void __launch_bounds__(256) encode_finish_kernel(const float* __restrict__ xeD,
    const float* __restrict__ ysrc, const float* __restrict__ yencW, const float* __restrict__ yencb) {
  int row = blockIdx.x;
  int l = row / BB, b = row - l*BB;
  const float* xr = xeD + (size_t)row * DD;
  float v[4]; float sq = 0.f;
#pragma unroll
  for (int i = 0; i < 4; i++) { v[i] = xr[threadIdx.x + i*256]; sq += v[i]*v[i]; }
  float ms = blockReduceSum(sq) * (1.f/DD);
  float inv = 1.f / sqrtf(ms);
  bool addy = (l < PP);
  float yv = addy ? ysrc[(size_t)b*PP + l] : 0.f;
  float* dst = g_src + ((size_t)b*LL + l) * DD;
#pragma unroll
  for (int i = 0; i < 4; i++) {
    int c = threadIdx.x + i*256;
    float o = v[i] * inv;
    if (addy) o += yv * yencW[c] + yencb[c];
    dst[c] = o;
  }
}

__global__ void __launch_bounds__(256) ln_split_kernel(const float* __restrict__ x,
    const float* __restrict__ gg, const float* __restrict__ bbp,
    bf16* __restrict__ oh, bf16* __restrict__ ol) {
  int row = blockIdx.x;
  const float* xr = x + (size_t)row * DD;
  float v[4]; float s = 0.f;
#pragma unroll
  for (int i = 0; i < 4; i++) { v[i] = xr[threadIdx.x + i*256]; s += v[i]; }
  float m = blockReduceSum(s) * (1.f/DD);
  float d = 0.f;
#pragma unroll
  for (int i = 0; i < 4; i++) { float t = v[i]-m; d += t*t; }
  float var = blockReduceSum(d) * (1.f/DD);
  float r = rsqrtf(var + 1e-5f);
#pragma unroll
  for (int i = 0; i < 4; i++) {
    int c = threadIdx.x + i*256;
    float o = (v[i]-m)*r*gg[c] + bbp[c];
    bf16 h, l; split2(o, h, l);
    oh[(size_t)row*DD + c] = h;
    ol[(size_t)row*DD + c] = l;
  }
}

__global__ void __launch_bounds__(256) qln_split_kernel(const float* __restrict__ qraw,
    const float* __restrict__ gg, const float* __restrict__ bbp,
    bf16* __restrict__ qh, bf16* __restrict__ ql) {
  int row = blockIdx.x;
  int h = threadIdx.x >> 5, lane = threadIdx.x & 31;
  int b = row / LL, l = row - b*LL;
  const float* src = qraw + (size_t)row*DD + h*HDIM;
  float v[4]; float s = 0.f;
#pragma unroll
  for (int i = 0; i < 4; i++) { v[i] = src[lane + i*32]; s += v[i]; }
  float m = warpSum(s) * (1.f/HDIM);
  float d = 0.f;
#pragma unroll
  for (int i = 0; i < 4; i++) { float t = v[i]-m; d += t*t; }
  float var = warpSum(d) * (1.f/HDIM);
  float r = rsqrtf(var + 1e-5f);
  size_t base = ((size_t)(b*HH + h)*LL + l) * HDIM;
#pragma unroll
  for (int i = 0; i < 4; i++) {
    int c = lane + i*32;
    float o = (v[i]-m)*r*gg[c] + bbp[c];
    bf16 hh, llv; split2(o, hh, llv);
    qh[base + c] = hh; ql[base + c] = llv;
  }
}

__global__ void __launch_bounds__(256) klnv_split_kernel(const float* __restrict__ kv,
    const float* __restrict__ gg, const float* __restrict__ bbp,
    bf16* __restrict__ kh, bf16* __restrict__ kl, float* __restrict__ vh) {
  int row = blockIdx.x;
  int h = threadIdx.x >> 5, lane = threadIdx.x & 31;
  int b = row / PP, t = row - b*PP;
  const float* kp = kv + (size_t)row*2*DD + h*HDIM;
  const float* vp = kp + DD;
  float v[4]; float s = 0.f;
#pragma unroll
  for (int i = 0; i < 4; i++) { v[i] = kp[lane + i*32]; s += v[i]; }
  float m = warpSum(s) * (1.f/HDIM);
  float d = 0.f;
#pragma unroll
  for (int i = 0; i < 4; i++) { float t2 = v[i]-m; d += t2*t2; }
  float var = warpSum(d) * (1.f/HDIM);
  float r = rsqrtf(var + 1e-5f);
  size_t base = ((size_t)(b*HH + h)*PP + t) * HDIM;
#pragma unroll
  for (int i = 0; i < 4; i++) {
    int c = lane + i*32;
    float o = (v[i]-m)*r*gg[c] + bbp[c];
    bf16 hh, llv; split2(o, hh, llv);
    kh[base + c] = hh; kl[base + c] = llv;
    vh[base + c] = vp[c];
  }
}

__global__ void __launch_bounds__(256) softmax_split_kernel(const float* __restrict__ x,
    bf16* __restrict__ ph, bf16* __restrict__ pl) {
  const float* xr = x + (size_t)blockIdx.x * PP;
  float v[4];
  float mx = -3.4e38f;
#pragma unroll
  for (int i = 0; i < 4; i++) { v[i] = xr[threadIdx.x + i*256]; mx = fmaxf(mx, v[i]); }
  mx = blockReduceMax(mx);
  float s = 0.f;
#pragma unroll
  for (int i = 0; i < 4; i++) { v[i] = expf(v[i] - mx); s += v[i]; }
  float tot = blockReduceSum(s);
  float inv = 1.f / tot;
  size_t base = (size_t)blockIdx.x * PP;
#pragma unroll
  for (int i = 0; i < 4; i++) {
    float p = v[i] * inv;
    bf16 h, l; split2(p, h, l);
    int c = threadIdx.x + i*256;
    ph[base + c] = h; pl[base + c] = l;
  }
}

__global__ void __launch_bounds__(256) transpose_split_kernel(const float* __restrict__ src,
    bf16* __restrict__ dh, bf16* __restrict__ dl, int R, int C,
    ll sStride, ll dStride) {
  __shared__ float t[32][33];
  int z = blockIdx.z;
  src += (ll)z * sStride;
  dh  += (ll)z * dStride;
  dl  += (ll)z * dStride;
  int c0 = blockIdx.x * 32, r0 = blockIdx.y * 32;
  int tx = threadIdx.x & 31, ty = threadIdx.x >> 5;
#pragma unroll
  for (int j = ty; j < 32; j += 8)
    t[j][tx] = src[(size_t)(r0+j)*C + c0 + tx];
  __syncthreads();
#pragma unroll
  for (int j = ty; j < 32; j += 8) {
    float v = t[tx][j];
    bf16 hh, llv; split2(v, hh, llv);
    size_t off = (size_t)(c0+j)*R + r0 + tx;
    dh[off] = hh; dl[off] = llv;
  }
}

// ---------------------------------------------------------------------------
// fp32 SGEMM (encoder only; K=112 zero-padded A)
// ---------------------------------------------------------------------------
template<bool HASBIAS>
__global__ void __launch_bounds__(256, 2) sgemm_kernel(
    const float* __restrict__ A, const float* __restrict__ B, float* __restrict__ C,
    const float* __restrict__ bias, int K, int kGuard, int lda, int ldb, int ldc)
{
  __shared__ float As[16][128];
  __shared__ float Bs[16][128];
  const int tid = threadIdx.x;
  const int row0 = blockIdx.y * 128;
  const int col0 = blockIdx.x * 128;
  const int tx = tid & 15, ty = tid >> 4;
  const int tm0 = ty*8, tn0 = tx*8;
  float acc[8][8];
#pragma unroll
  for (int i = 0; i < 8; i++)
#pragma unroll
    for (int j = 0; j < 8; j++) acc[i][j] = 0.f;
  for (int k0 = 0; k0 < K; k0 += 16) {
#pragma unroll
    for (int u = 0; u < 2; u++) {
      int f = tid + u*256;
      int r = f >> 2, c4 = (f & 3) << 2;
      float4 va = *reinterpret_cast<const float4*>(A + (size_t)(row0 + r)*lda + (k0 + c4));
      As[c4+0][r] = va.x; As[c4+1][r] = va.y; As[c4+2][r] = va.z; As[c4+3][r] = va.w;
    }
#pragma unroll
    for (int u = 0; u < 2; u++) {
      int f = tid + u*256;
      int kk = f >> 5, n4 = (f & 31) << 2;
      float4 vb = make_float4(0.f, 0.f, 0.f, 0.f);
      if (k0 + kk < kGuard)
        vb = *reinterpret_cast<const float4*>(B + (size_t)(k0 + kk)*ldb + (col0 + n4));
      *reinterpret_cast<float4*>(&Bs[kk][n4]) = vb;
    }
    __syncthreads();
#pragma unroll
    for (int kk = 0; kk < 16; kk++) {
      float4 a0 = *reinterpret_cast<const float4*>(&As[kk][tm0]);
      float4 a1 = *reinterpret_cast<const float4*>(&As[kk][tm0+4]);
      float4 b0 = *reinterpret_cast<const float4*>(&Bs[kk][tn0]);
      float4 b1 = *reinterpret_cast<const float4*>(&Bs[kk][tn0+4]);
      float ra[8] = {a0.x,a0.y,a0.z,a0.w,a1.x,a1.y,a1.z,a1.w};
      float rb[8] = {b0.x,b0.y,b0.z,b0.w,b1.x,b1.y,b1.z,b1.w};
#pragma unroll
      for (int i = 0; i < 8; i++)
#pragma unroll
        for (int j = 0; j < 8; j++)
          acc[i][j] = fmaf(ra[i], rb[j], acc[i][j]);
    }
    __syncthreads();
  }
#pragma unroll
  for (int i = 0; i < 8; i++) {
    float* crow = C + (size_t)(row0 + tm0 + i)*ldc + (col0 + tn0);
#pragma unroll
    for (int j = 0; j < 8; j += 4) {
      float4 v;
      v.x = acc[i][j+0]; v.y = acc[i][j+1]; v.z = acc[i][j+2]; v.w = acc[i][j+3];
      if (HASBIAS) {
        float4 bbv = *reinterpret_cast<const float4*>(bias + col0 + tn0 + j);
        v.x += bbv.x; v.y += bbv.y; v.z += bbv.z; v.w += bbv.w;
      }
      *reinterpret_cast<float4*>(crow + j) = v;
    }
  }
}

// ---------------------------------------------------------------------------
// Tensor-core GEMM (bf16x3 split): C = act(alpha*(Ah+Al)@(Bh+Bl)^T + bias)
// A: [M][K] hi/lo bf16 (lda), B: [N][K] hi/lo bf16 (ldb)  -- TN, k-contiguous
// OUTMODE: 0=store fp32; 1=accumulate fp32; 2=store split bf16;
//          3=accumulate fp32 AND store split bf16 of the sum.
// Block 128x128, K-step 32, 2-stage cp.async pipeline, 2 CTAs/SM target.
// ---------------------------------------------------------------------------
#define LDSROW 40
#define TILE_ELEMS (128*LDSROW)
#define STAGE_ELEMS (4*TILE_ELEMS)
#define MMA_SMEM_BYTES (2*STAGE_ELEMS*2)

template<bool ACT, bool HASBIAS, int OUTMODE>
__global__ void __launch_bounds__(256, 2) mma_gemm_kernel(
    const bf16* __restrict__ Ah, const bf16* __restrict__ Al,
    const bf16* __restrict__ Bh, const bf16* __restrict__ Bl,
    float* __restrict__ C, bf16* __restrict__ Ch, bf16* __restrict__ Cl,
    const float* __restrict__ bias,
    int K, int lda, int ldb, int ldc, int inner,
    ll aSO, ll aSI, ll bSO, ll bSI, ll cSO, ll cSI, float alpha)
{
  extern __shared__ bf16 smbuf[];
  int bz = blockIdx.z;
  int bo = bz / inner, bi = bz - bo*inner;
  ll aoff = (ll)bo*aSO + (ll)bi*aSI;
  ll boff = (ll)bo*bSO + (ll)bi*bSI;
  ll coff = (ll)bo*cSO + (ll)bi*cSI;
  Ah += aoff; Al += aoff; Bh += boff; Bl += boff;

  const int tid = threadIdx.x;
  const int row0 = blockIdx.y * 128;
  const int col0 = blockIdx.x * 128;
  const int wid = tid >> 5, lane = tid & 31;
  const int wm = (wid & 3) * 32;
  const int wn = (wid >> 2) * 64;

  float acc[2][8][4];
#pragma unroll
  for (int mt = 0; mt < 2; mt++)
#pragma unroll
    for (int nt = 0; nt < 8; nt++)
#pragma unroll
      for (int q = 0; q < 4; q++) acc[mt][nt][q] = 0.f;

  // --- prologue: stage 0 ---
  {
    bf16* base = smbuf;
#pragma unroll
    for (int i = 0; i < 2; i++) {
      int c = tid + i*256;
      int r = c >> 2, kc = (c & 3) << 3;
      cpa16(s2u(base + 0*TILE_ELEMS + r*LDSROW + kc), Ah + (size_t)(row0+r)*lda + kc);
      cpa16(s2u(base + 1*TILE_ELEMS + r*LDSROW + kc), Al + (size_t)(row0+r)*lda + kc);
      cpa16(s2u(base + 2*TILE_ELEMS + r*LDSROW + kc), Bh + (size_t)(col0+r)*ldb + kc);
      cpa16(s2u(base + 3*TILE_ELEMS + r*LDSROW + kc), Bl + (size_t)(col0+r)*ldb + kc);
    }
    asm volatile("cp.async.commit_group;\n");
  }

  int s = 0;
  for (int k0 = 0; k0 < K; k0 += 32, s ^= 1) {
    asm volatile("cp.async.wait_group 0;\n");
    __syncthreads();
    if (k0 + 32 < K) {
      bf16* base = smbuf + (s^1)*STAGE_ELEMS;
      int kn = k0 + 32;
#pragma unroll
      for (int i = 0; i < 2; i++) {
        int c = tid + i*256;
        int r = c >> 2, kc = (c & 3) << 3;
        cpa16(s2u(base + 0*TILE_ELEMS + r*LDSROW + kc), Ah + (size_t)(row0+r)*lda + kn + kc);
        cpa16(s2u(base + 1*TILE_ELEMS + r*LDSROW + kc), Al + (size_t)(row0+r)*lda + kn + kc);
        cpa16(s2u(base + 2*TILE_ELEMS + r*LDSROW + kc), Bh + (size_t)(col0+r)*ldb + kn + kc);
        cpa16(s2u(base + 3*TILE_ELEMS + r*LDSROW + kc), Bl + (size_t)(col0+r)*ldb + kn + kc);
      }
      asm volatile("cp.async.commit_group;\n");
    }

    bf16* sAh = smbuf + s*STAGE_ELEMS;
    bf16* sAl = sAh + TILE_ELEMS;
    bf16* sBh = sAh + 2*TILE_ELEMS;
    bf16* sBl = sAh + 3*TILE_ELEMS;
    int arow = lane & 15;
    int khalf = (lane >> 4) << 3;

#pragma unroll
    for (int kk = 0; kk < 2; kk++) {
      int kof = kk*16 + khalf;
      unsigned ahf[2][4], alf[2][4], bfr[8][2];
#pragma unroll
      for (int mt = 0; mt < 2; mt++) {
        ldsm4(ahf[mt], s2u(sAh + (wm + mt*16 + arow)*LDSROW + kof));
        ldsm4(alf[mt], s2u(sAl + (wm + mt*16 + arow)*LDSROW + kof));
      }
      // B hi
#pragma unroll
      for (int np = 0; np < 4; np++) {
        unsigned t[4];
        ldsm4(t, s2u(sBh + (wn + np*16 + arow)*LDSROW + kof));
        bfr[2*np][0] = t[0]; bfr[2*np][1] = t[2];
        bfr[2*np+1][0] = t[1]; bfr[2*np+1][1] = t[3];
      }
#pragma unroll
      for (int mt = 0; mt < 2; mt++)
#pragma unroll
        for (int nt = 0; nt < 8; nt++) {
          mma16816(acc[mt][nt], ahf[mt], bfr[nt]);
          mma16816(acc[mt][nt], alf[mt], bfr[nt]);
        }
      // B lo (reuse regs)
#pragma unroll
      for (int np = 0; np < 4; np++) {
        unsigned t[4];
        ldsm4(t, s2u(sBl + (wn + np*16 + arow)*LDSROW + kof));
        bfr[2*np][0] = t[0]; bfr[2*np][1] = t[2];
        bfr[2*np+1][0] = t[1]; bfr[2*np+1][1] = t[3];
      }
#pragma unroll
      for (int mt = 0; mt < 2; mt++)
#pragma unroll
        for (int nt = 0; nt < 8; nt++)
          mma16816(acc[mt][nt], ahf[mt], bfr[nt]);
    }
  }

  // --- epilogue ---
  int rb = row0 + wm + (lane >> 2);
  int cb = col0 + wn + (lane & 3)*2;
#pragma unroll
  for (int mt = 0; mt < 2; mt++) {
#pragma unroll
    for (int nt = 0; nt < 8; nt++) {
#pragma unroll
      for (int h2 = 0; h2 < 2; h2++) {
        int r = rb + mt*16 + h2*8;
        int cc = cb + nt*8;
        float v0 = alpha * acc[mt][nt][h2*2+0];
        float v1 = alpha * acc[mt][nt][h2*2+1];
        if (HASBIAS) { v0 += bias[cc]; v1 += bias[cc+1]; }
        if (ACT) { v0 = gelu_f(v0); v1 = gelu_f(v1); }
        ll off = coff + (ll)r*ldc + cc;
        if (OUTMODE == 0) {
          float2 o; o.x = v0; o.y = v1;
          *reinterpret_cast<float2*>(C + off) = o;
        } else if (OUTMODE == 1) {
          float2 o = *reinterpret_cast<const float2*>(C + off);
          o.x += v0; o.y += v1;
          *reinterpret_cast<float2*>(C + off) = o;
        } else if (OUTMODE == 2) {
          bf16 h0, l0, h1, l1;
          split2(v0, h0, l0); split2(v1, h1, l1);
          __nv_bfloat162 phv; phv.x = h0; phv.y = h1;
          __nv_bfloat162 plv; plv.x = l0; plv.y = l1;
          *reinterpret_cast<__nv_bfloat162*>(Ch + off) = phv;
          *reinterpret_cast<__nv_bfloat162*>(Cl + off) = plv;
        } else {
          float2 o = *reinterpret_cast<const float2*>(C + off);
          o.x += v0; o.y += v1;
          *reinterpret_cast<float2*>(C + off) = o;
          bf16 h0, l0, h1, l1;
          split2(o.x, h0, l0); split2(o.y, h1, l1);
          __nv_bfloat162 phv; phv.x = h0; phv.y = h1;
          __nv_bfloat162 plv; plv.x = l0; plv.y = l1;
          *reinterpret_cast<__nv_bfloat162*>(Ch + off) = phv;
          *reinterpret_cast<__nv_bfloat162*>(Cl + off) = plv;
        }
      }
    }
  }
}

// ---------------------------------------------------------------------------
// Head second GEMM
// ---------------------------------------------------------------------------
__global__ void __launch_bounds__(256) head2_kernel(const bf16* __restrict__ hbh,
    const bf16* __restrict__ hbl, const float* __restrict__ W2,
    const float* __restrict__ b2, float* __restrict__ out) {
  int idx = blockIdx.x;
  int b = idx / PP, t = idx - b*PP;
  const bf16* hh = hbh + (size_t)idx * NHID;
  const bf16* hl = hbl + (size_t)idx * NHID;
  float acc[NOUTD];
#pragma unroll
  for (int o = 0; o < NOUTD; o++) acc[o] = 0.f;
  for (int k = threadIdx.x; k < NHID; k += 256) {
    float v = __bfloat162float(hh[k]) + __bfloat162float(hl[k]);
    const float* w = W2 + (size_t)k * (NOUTD + 1);
#pragma unroll
    for (int o = 0; o < NOUTD; o++) acc[o] += v * w[o];
  }
  __shared__ float smr[8][NOUTD];
  int lane = threadIdx.x & 31, wid = threadIdx.x >> 5;
#pragma unroll
  for (int o = 0; o < NOUTD; o++) acc[o] = warpSum(acc[o]);
  if (lane == 0) {
#pragma unroll
    for (int o = 0; o < NOUTD; o++) smr[wid][o] = acc[o];
  }
  __syncthreads();
  if (threadIdx.x < NOUTD) {
    float sv = 0.f;
#pragma unroll
    for (int w = 0; w < 8; w++) sv += smr[w][threadIdx.x];
    out[((size_t)t*BB + b)*NOUTD + threadIdx.x] = sv + b2[threadIdx.x];
  }
}

// ---------------------------------------------------------------------------
// Orchestration
// ---------------------------------------------------------------------------
typedef void (*mm_fn)(const bf16*, const bf16*, const bf16*, const bf16*,
                      float*, bf16*, bf16*, const float*,
                      int, int, int, int, int, ll, ll, ll, ll, ll, ll, float);

extern "C" void kernel_launch(void* const* d_in, const int* in_sizes, int n_in,
                              void* d_out, int out_size) {
  (void)in_sizes; (void)n_in; (void)out_size;
  const float* x_src = (const float*)d_in[0];
  const float* y_src = (const float*)d_in[1];
  const float* enc_W = (const float*)d_in[2];
  const float* enc_b = (const float*)d_in[3];
  const float* yenc_W = (const float*)d_in[4];
  const float* yenc_b = (const float*)d_in[5];
  const float* Wq    = (const float*)d_in[6];
  const float* Wkv   = (const float*)d_in[7];
  const float* Wout  = (const float*)d_in[8];
  const float* an_g  = (const float*)d_in[9];
  const float* an_b  = (const float*)d_in[10];
  const float* qn_g  = (const float*)d_in[11];
  const float* qn_b  = (const float*)d_in[12];
  const float* kn_g  = (const float*)d_in[13];
  const float* kn_b  = (const float*)d_in[14];
  const float* fn_g  = (const float*)d_in[15];
  const float* fn_b  = (const float*)d_in[16];
  const float* ffW1  = (const float*)d_in[17];
  const float* ffb1  = (const float*)d_in[18];
  const float* ffW2  = (const float*)d_in[19];
  const float* ffb2  = (const float*)d_in[20];
  const float* hW1   = (const float*)d_in[21];
  const float* hb1   = (const float*)d_in[22];
  const float* hW2   = (const float*)d_in[23];
  const float* hb2   = (const float*)d_in[24];
  float* out = (float*)d_out;

  {
    mm_fn f;
    f = mma_gemm_kernel<false,false,0>;
    cudaFuncSetAttribute(f, cudaFuncAttributeMaxDynamicSharedMemorySize, MMA_SMEM_BYTES);
    f = mma_gemm_kernel<false,false,1>;
    cudaFuncSetAttribute(f, cudaFuncAttributeMaxDynamicSharedMemorySize, MMA_SMEM_BYTES);
    f = mma_gemm_kernel<false,false,2>;
    cudaFuncSetAttribute(f, cudaFuncAttributeMaxDynamicSharedMemorySize, MMA_SMEM_BYTES);
    f = mma_gemm_kernel<true,true,2>;
    cudaFuncSetAttribute(f, cudaFuncAttributeMaxDynamicSharedMemorySize, MMA_SMEM_BYTES);
    f = mma_gemm_kernel<false,true,1>;
    cudaFuncSetAttribute(f, cudaFuncAttributeMaxDynamicSharedMemorySize, MMA_SMEM_BYTES);
    f = mma_gemm_kernel<false,true,3>;
    cudaFuncSetAttribute(f, cudaFuncAttributeMaxDynamicSharedMemorySize, MMA_SMEM_BYTES);
  }

  float *p_xn, *p_src, *p_tmp, *p_vh, *p_logits;
  cudaGetSymbolAddress((void**)&p_xn, g_xn);
  cudaGetSymbolAddress((void**)&p_src, g_src);
  cudaGetSymbolAddress((void**)&p_tmp, g_tmp);
  cudaGetSymbolAddress((void**)&p_vh, g_vh);
  cudaGetSymbolAddress((void**)&p_logits, g_logits);
  bf16 *p_ah, *p_al, *p_qhh, *p_qhl, *p_khh, *p_khl;
  bf16 *p_vth, *p_vtl, *p_ph, *p_pl, *p_ffh, *p_ffl;
  cudaGetSymbolAddress((void**)&p_ah, g_ah);
  cudaGetSymbolAddress((void**)&p_al, g_al);
  cudaGetSymbolAddress((void**)&p_qhh, g_qhh);
  cudaGetSymbolAddress((void**)&p_qhl, g_qhl);
  cudaGetSymbolAddress((void**)&p_khh, g_khh);
  cudaGetSymbolAddress((void**)&p_khl, g_khl);
  cudaGetSymbolAddress((void**)&p_vth, g_vth);
  cudaGetSymbolAddress((void**)&p_vtl, g_vtl);
  cudaGetSymbolAddress((void**)&p_ph, g_ph);
  cudaGetSymbolAddress((void**)&p_pl, g_pl);
  cudaGetSymbolAddress((void**)&p_ffh, g_ffh);
  cudaGetSymbolAddress((void**)&p_ffl, g_ffl);
  bf16 *pWqh, *pWql, *pWkvh, *pWkvl, *pWoh, *pWol;
  bf16 *pW1h, *pW1l, *pW2h, *pW2l, *pHW1h, *pHW1l;
  cudaGetSymbolAddress((void**)&pWqh, g_WqTh);
  cudaGetSymbolAddress((void**)&pWql, g_WqTl);
  cudaGetSymbolAddress((void**)&pWkvh, g_WkvTh);
  cudaGetSymbolAddress((void**)&pWkvl, g_WkvTl);
  cudaGetSymbolAddress((void**)&pWoh, g_WoTh);
  cudaGetSymbolAddress((void**)&pWol, g_WoTl);
  cudaGetSymbolAddress((void**)&pW1h, g_W1Th);
  cudaGetSymbolAddress((void**)&pW1l, g_W1Tl);
  cudaGetSymbolAddress((void**)&pW2h, g_W2Th);
  cudaGetSymbolAddress((void**)&pW2l, g_W2Tl);
  cudaGetSymbolAddress((void**)&pHW1h, g_hW1Th);
  cudaGetSymbolAddress((void**)&pHW1l, g_hW1Tl);

  const float qk_scale = 0.08838834764831845f;

  // --- weight transpose+split ---
  transpose_split_kernel<<<dim3(DD/32, DD/32, NLAYERS), 256>>>(Wq, pWqh, pWql, DD, DD, (ll)DD*DD, (ll)DD*DD);
  transpose_split_kernel<<<dim3(2*DD/32, DD/32, NLAYERS), 256>>>(Wkv, pWkvh, pWkvl, DD, 2*DD, (ll)DD*2*DD, (ll)DD*2*DD);
  transpose_split_kernel<<<dim3(DD/32, DD/32, NLAYERS), 256>>>(Wout, pWoh, pWol, DD, DD, (ll)DD*DD, (ll)DD*DD);
  transpose_split_kernel<<<dim3(NHID/32, DD/32, NLAYERS), 256>>>(ffW1, pW1h, pW1l, DD, NHID, (ll)DD*NHID, (ll)DD*NHID);
  transpose_split_kernel<<<dim3(DD/32, NHID/32, NLAYERS), 256>>>(ffW2, pW2h, pW2l, NHID, DD, (ll)NHID*DD, (ll)NHID*DD);
  transpose_split_kernel<<<dim3(NHID/32, DD/32, 1), 256>>>(hW1, pHW1h, pHW1l, DD, NHID, 0, 0);

  // --- preprocessing + encoder ---
  colstats_kernel<<<BB*NFEAT, 256>>>(x_src, 0);
  colstats_kernel<<<BB*NFEAT, 256>>>(x_src, 1);
  colstats_kernel<<<BB*NFEAT, 256>>>(x_src, 2);
  norm_write_kernel<<<(LB*KPAD + 255)/256, 256>>>(x_src);
  sgemm_kernel<true><<<dim3(DD/128, LB/128, 1), 256>>>(
      p_xn, enc_W, p_tmp, enc_b, KPAD, NFEAT, KPAD, DD, DD);
  encode_finish_kernel<<<LB, 256>>>(p_tmp, y_src, yenc_W, yenc_b);

  for (int i = 0; i < NLAYERS; i++) {
    // --- attention ---
    ln_split_kernel<<<LB, 256>>>(p_src, an_g + i*DD, an_b + i*DD, p_ah, p_al);
    mma_gemm_kernel<false,false,0><<<dim3(8, 64, 1), 256, MMA_SMEM_BYTES>>>(
        p_ah, p_al, pWqh + (size_t)i*DD*DD, pWql + (size_t)i*DD*DD,
        p_tmp, nullptr, nullptr, nullptr,
        DD, DD, DD, DD, 1, 0,0,0,0,0,0, 1.f);
    qln_split_kernel<<<LB, 256>>>(p_tmp, qn_g + i*HDIM, qn_b + i*HDIM, p_qhh, p_qhl);
    mma_gemm_kernel<false,false,0><<<dim3(16, 8, BB), 256, MMA_SMEM_BYTES>>>(
        p_ah, p_al, pWkvh + (size_t)i*DD*2*DD, pWkvl + (size_t)i*DD*2*DD,
        p_tmp, nullptr, nullptr, nullptr,
        DD, DD, DD, 2*DD, 1,
        (ll)LL*DD, 0, 0, 0, (ll)PP*2*DD, 0, 1.f);
    klnv_split_kernel<<<BB*PP, 256>>>(p_tmp, kn_g + i*HDIM, kn_b + i*HDIM, p_khh, p_khl, p_vh);
    transpose_split_kernel<<<dim3(HDIM/32, PP/32, BB*HH), 256>>>(
        p_vh, p_vth, p_vtl, PP, HDIM, (ll)PP*HDIM, (ll)PP*HDIM);
    mma_gemm_kernel<false,false,0><<<dim3(8, 16, BB*HH), 256, MMA_SMEM_BYTES>>>(
        p_qhh, p_qhl, p_khh, p_khl, p_logits, nullptr, nullptr, nullptr,
        HDIM, HDIM, HDIM, PP, 1,
        (ll)LL*HDIM, 0, (ll)PP*HDIM, 0, (ll)LL*PP, 0, qk_scale);
    softmax_split_kernel<<<BB*HH*LL, 256>>>(p_logits, p_ph, p_pl);
    mma_gemm_kernel<false,false,2><<<dim3(1, 16, BB*HH), 256, MMA_SMEM_BYTES>>>(
        p_ph, p_pl, p_vth, p_vtl, nullptr, p_ah, p_al, nullptr,
        PP, PP, PP, DD, HH,
        (ll)HH*LL*PP, (ll)LL*PP,
        (ll)HH*HDIM*PP, (ll)HDIM*PP,
        (ll)LL*DD, (ll)HDIM, 1.f);
    mma_gemm_kernel<false,false,1><<<dim3(8, 64, 1), 256, MMA_SMEM_BYTES>>>(
        p_ah, p_al, pWoh + (size_t)i*DD*DD, pWol + (size_t)i*DD*DD,
        p_src, nullptr, nullptr, nullptr,
        DD, DD, DD, DD, 1, 0,0,0,0,0,0, 1.f);
    // --- FFN ---
    ln_split_kernel<<<LB, 256>>>(p_src, fn_g + i*DD, fn_b + i*DD, p_ah, p_al);
    mma_gemm_kernel<true,true,2><<<dim3(NHID/128, 64, 1), 256, MMA_SMEM_BYTES>>>(
        p_ah, p_al, pW1h + (size_t)i*NHID*DD, pW1l + (size_t)i*NHID*DD,
        nullptr, p_ffh, p_ffl, ffb1 + (size_t)i*NHID,
        DD, DD, DD, NHID, 1, 0,0,0,0,0,0, 1.f);
    if (i < NLAYERS - 1) {
      mma_gemm_kernel<false,true,1><<<dim3(8, 64, 1), 256, MMA_SMEM_BYTES>>>(
          p_ffh, p_ffl, pW2h + (size_t)i*DD*NHID, pW2l + (size_t)i*DD*NHID,
          p_src, nullptr, nullptr, ffb2 + (size_t)i*DD,
          NHID, NHID, NHID, DD, 1, 0,0,0,0,0,0, 1.f);
    } else {
      // last layer: residual accumulate AND emit split bf16 for the head
      mma_gemm_kernel<false,true,3><<<dim3(8, 64, 1), 256, MMA_SMEM_BYTES>>>(
          p_ffh, p_ffl, pW2h + (size_t)i*DD*NHID, pW2l + (size_t)i*DD*NHID,
          p_src, p_ah, p_al, ffb2 + (size_t)i*DD,
          NHID, NHID, NHID, DD, 1, 0,0,0,0,0,0, 1.f);
    }
  }

  // --- head (p_ah/p_al already hold split src from OUTMODE 3) ---
  mma_gemm_kernel<true,true,2><<<dim3(NHID/128, PP/128, BB), 256, MMA_SMEM_BYTES>>>(
      p_ah + (size_t)PP*DD, p_al + (size_t)PP*DD, pHW1h, pHW1l,
      nullptr, p_ffh, p_ffl, hb1,
      DD, DD, DD, NHID, 1,
      (ll)LL*DD, 0, 0, 0, (ll)PP*NHID, 0, 1.f);
  head2_kernel<<<BB*PP, 256>>>(p_ffh, p_ffl, hW2, hb2, out);
}

// round 9
// speedup vs baseline: 1.4221x; 1.2897x over previous
#include <cuda_runtime.h>
#include <cuda_bf16.h>
#include <cuda_fp16.h>
#include <cstdint>
#include <cstddef>
#include <math.h>

// ---------------------------------------------------------------------------
// Problem constants
// ---------------------------------------------------------------------------
#define BB     4
#define LL     2048
#define PP     1024
#define NFEAT  100
#define DD     1024
#define HH     8
#define HDIM   128
#define NHID   4096
#define NLAYERS 3
#define NOUTD  10
#define LB     (LL*BB)
#define KPAD   112

typedef __nv_bfloat16 bf16;
typedef __half fp16;
typedef long long ll;

// ---------------------------------------------------------------------------
// Scratch (device globals)
// ---------------------------------------------------------------------------
__device__ float g_m1[BB*NFEAT], g_s1[BB*NFEAT];
__device__ float g_m2[BB*NFEAT], g_s2[BB*NFEAT];
__device__ float g_m3[BB*NFEAT], g_s3[BB*NFEAT];
__device__ __align__(256) float g_xn[(size_t)LB*KPAD];
__device__ __align__(256) float g_src[(size_t)LB*DD];
__device__ __align__(256) float g_tmp[(size_t)LB*DD];
__device__ __align__(256) float g_vh [(size_t)BB*HH*PP*HDIM];
__device__ __align__(256) float g_logits[(size_t)BB*HH*LL*PP];

// fp16 split activations (dense-GEMM A operands / outputs)
__device__ __align__(256) fp16 g_ah[(size_t)LB*DD];
__device__ __align__(256) fp16 g_al[(size_t)LB*DD];
__device__ __align__(256) fp16 g_ffh[(size_t)LB*NHID];
__device__ __align__(256) fp16 g_ffl[(size_t)LB*NHID];

// bf16 split attention operands (QK / PV inputs)
__device__ __align__(256) bf16 g_qhh[(size_t)BB*HH*LL*HDIM];
__device__ __align__(256) bf16 g_qhl[(size_t)BB*HH*LL*HDIM];
__device__ __align__(256) bf16 g_khh[(size_t)BB*HH*PP*HDIM];
__device__ __align__(256) bf16 g_khl[(size_t)BB*HH*PP*HDIM];
__device__ __align__(256) bf16 g_vth[(size_t)BB*HH*HDIM*PP];
__device__ __align__(256) bf16 g_vtl[(size_t)BB*HH*HDIM*PP];
__device__ __align__(256) bf16 g_ph [(size_t)BB*HH*LL*PP];
__device__ __align__(256) bf16 g_pl [(size_t)BB*HH*LL*PP];

// fp16 transposed weights (single precision level)
__device__ __align__(256) fp16 g_WqT [(size_t)NLAYERS*DD*DD];
__device__ __align__(256) fp16 g_WkvT[(size_t)NLAYERS*2*DD*DD];
__device__ __align__(256) fp16 g_WoT [(size_t)NLAYERS*DD*DD];
__device__ __align__(256) fp16 g_W1T [(size_t)NLAYERS*NHID*DD];
__device__ __align__(256) fp16 g_W2T [(size_t)NLAYERS*DD*NHID];
__device__ __align__(256) fp16 g_hW1T[(size_t)NHID*DD];

// ---------------------------------------------------------------------------
// Helpers
// ---------------------------------------------------------------------------
__device__ __forceinline__ float warpSum(float v) {
#pragma unroll
  for (int o = 16; o > 0; o >>= 1) v += __shfl_xor_sync(0xffffffffu, v, o);
  return v;
}

__device__ __forceinline__ float blockReduceSum(float v) {
  __shared__ float sh[32];
  int lane = threadIdx.x & 31, wid = threadIdx.x >> 5;
  v = warpSum(v);
  if (lane == 0) sh[wid] = v;
  __syncthreads();
  int nw = (blockDim.x + 31) >> 5;
  v = (threadIdx.x < nw) ? sh[threadIdx.x] : 0.f;
  if (wid == 0) { v = warpSum(v); if (lane == 0) sh[0] = v; }
  __syncthreads();
  float r = sh[0];
  __syncthreads();
  return r;
}

__device__ __forceinline__ float blockReduceMax(float v) {
  __shared__ float sh[32];
  int lane = threadIdx.x & 31, wid = threadIdx.x >> 5;
#pragma unroll
  for (int o = 16; o > 0; o >>= 1) v = fmaxf(v, __shfl_xor_sync(0xffffffffu, v, o));
  if (lane == 0) sh[wid] = v;
  __syncthreads();
  int nw = (blockDim.x + 31) >> 5;
  v = (threadIdx.x < nw) ? sh[threadIdx.x] : -3.4e38f;
  if (wid == 0) {
#pragma unroll
    for (int o = 16; o > 0; o >>= 1) v = fmaxf(v, __shfl_xor_sync(0xffffffffu, v, o));
    if (lane == 0) sh[0] = v;
  }
  __syncthreads();
  float r = sh[0];
  __syncthreads();
  return r;
}

__device__ __forceinline__ float gelu_f(float x) {
  return 0.5f * x * (1.0f + erff(x * 0.7071067811865475f));
}

__device__ __forceinline__ void split2(float v, bf16& h, bf16& l) {
  h = __float2bfloat16_rn(v);
  l = __float2bfloat16_rn(v - __bfloat162float(h));
}

__device__ __forceinline__ void split2h(float v, fp16& h, fp16& l) {
  h = __float2half_rn(v);
  l = __float2half_rn(v - __half2float(h));
}

__device__ __forceinline__ unsigned s2u(const void* p) {
  return (unsigned)__cvta_generic_to_shared(p);
}

__device__ __forceinline__ void cpa16(unsigned s, const void* g) {
  asm volatile("cp.async.cg.shared.global [%0], [%1], 16;\n" :: "r"(s), "l"(g));
}

__device__ __forceinline__ void ldsm4(unsigned* r, unsigned addr) {
  asm volatile("ldmatrix.sync.aligned.m8n8.x4.shared.b16 {%0,%1,%2,%3}, [%4];\n"
    : "=r"(r[0]), "=r"(r[1]), "=r"(r[2]), "=r"(r[3]) : "r"(addr));
}

__device__ __forceinline__ void mma_bf(float* c, const unsigned* a, const unsigned* b) {
  asm volatile("mma.sync.aligned.m16n8k16.row.col.f32.bf16.bf16.f32 "
    "{%0,%1,%2,%3}, {%4,%5,%6,%7}, {%8,%9}, {%0,%1,%2,%3};\n"
    : "+f"(c[0]), "+f"(c[1]), "+f"(c[2]), "+f"(c[3])
    : "r"(a[0]), "r"(a[1]), "r"(a[2]), "r"(a[3]), "r"(b[0]), "r"(b[1]));
}

__device__ __forceinline__ void mma_hf(float* c, const unsigned* a, const unsigned* b) {
  asm volatile("mma.sync.aligned.m16n8k16.row.col.f32.f16.f16.f32 "
    "{%0,%1,%2,%3}, {%4,%5,%6,%7}, {%8,%9}, {%0,%1,%2,%3};\n"
    : "+f"(c[0]), "+f"(c[1]), "+f"(c[2]), "+f"(c[3])
    : "r"(a[0]), "r"(a[1]), "r"(a[2]), "r"(a[3]), "r"(b[0]), "r"(b[1]));
}

// ---------------------------------------------------------------------------
// Preprocessing / LN / softmax / transpose kernels
// ---------------------------------------------------------------------------
__global__ void __launch_bounds__(256) colstats_kernel(const float* __restrict__ xsrc, int mode) {
  int bf = blockIdx.x;
  int b = bf / NFEAT, f = bf - b*NFEAT;
  const float* base = xsrc + (size_t)b*LL*NFEAT + f;
  float m1 = g_m1[bf], s1 = g_s1[bf];
  float m2 = g_m2[bf], s2 = g_s2[bf];
  float lo1 = m1 - 4.f*s1, hi1 = m1 + 4.f*s1;
  float inv2 = 1.f / (s2 + 1e-6f);
  float sum = 0.f, sq = 0.f;
  for (int t = threadIdx.x; t < PP; t += blockDim.x) {
    float v = base[(size_t)t*NFEAT];
    if (mode >= 1) v = fminf(fmaxf(v, lo1), hi1);
    if (mode >= 2) v = (v - m2) * inv2;
    sum += v; sq += v*v;
  }
  sum = blockReduceSum(sum);
  sq  = blockReduceSum(sq);
  if (threadIdx.x == 0) {
    float m = sum * (1.f/PP);
    float var = sq * (1.f/PP) - m*m;
    float s = sqrtf(fmaxf(var, 0.f));
    if (mode == 0)      { g_m1[bf] = m; g_s1[bf] = s; }
    else if (mode == 1) { g_m2[bf] = m; g_s2[bf] = s; }
    else                { g_m3[bf] = m; g_s3[bf] = s; }
  }
}

__global__ void __launch_bounds__(256) norm_write_kernel(const float* __restrict__ xsrc) {
  int idx = blockIdx.x * blockDim.x + threadIdx.x;
  if (idx >= LB*KPAD) return;
  int row = idx / KPAD, f = idx - row*KPAD;
  int l = row / BB, b = row - l*BB;
  float out = 0.f;
  if (f < NFEAT) {
    int bf = b*NFEAT + f;
    float v = xsrc[(size_t)b*LL*NFEAT + (size_t)l*NFEAT + f];
    float m1 = g_m1[bf], s1 = g_s1[bf];
    v = fminf(fmaxf(v, m1 - 4.f*s1), m1 + 4.f*s1);
    v = (v - g_m2[bf]) / (g_s2[bf] + 1e-6f);
    float m3 = g_m3[bf], s3 = g_s3[bf];
    v = fminf(fmaxf(v, m3 - 4.f*s3), m3 + 4.f*s3);
    if (!isfinite(v)) v = 0.f;
    out = v;
  }
  g_xn[idx] = out;
}

__global__ void __launch_bounds__(256) encode_finish_kernel(const float* __restrict__ xeD,
    const float* __restrict__ ysrc, const float* __restrict__ yencW, const float* __restrict__ yencb) {
  int row = blockIdx.x;
  int l = row / BB, b = row - l*BB;
  const float* xr = xeD + (size_t)row * DD;
  float v[4]; float sq = 0.f;
#pragma unroll
  for (int i = 0; i < 4; i++) { v[i] = xr[threadIdx.x + i*256]; sq += v[i]*v[i]; }
  float ms = blockReduceSum(sq) * (1.f/DD);
  float inv = 1.f / sqrtf(ms);
  bool addy = (l < PP);
  float yv = addy ? ysrc[(size_t)b*PP + l] : 0.f;
  float* dst = g_src + ((size_t)b*LL + l) * DD;
#pragma unroll
  for (int i = 0; i < 4; i++) {
    int c = threadIdx.x + i*256;
    float o = v[i] * inv;
    if (addy) o += yv * yencW[c] + yencb[c];
    dst[c] = o;
  }
}

// LayerNorm over D -> fp16 split
__global__ void __launch_bounds__(256) ln_splith_kernel(const float* __restrict__ x,
    const float* __restrict__ gg, const float* __restrict__ bbp,
    fp16* __restrict__ oh, fp16* __restrict__ ol) {
  int row = blockIdx.x;
  const float* xr = x + (size_t)row * DD;
  float v[4]; float s = 0.f;
#pragma unroll
  for (int i = 0; i < 4; i++) { v[i] = xr[threadIdx.x + i*256]; s += v[i]; }
  float m = blockReduceSum(s) * (1.f/DD);
  float d = 0.f;
#pragma unroll
  for (int i = 0; i < 4; i++) { float t = v[i]-m; d += t*t; }
  float var = blockReduceSum(d) * (1.f/DD);
  float r = rsqrtf(var + 1e-5f);
#pragma unroll
  for (int i = 0; i < 4; i++) {
    int c = threadIdx.x + i*256;
    float o = (v[i]-m)*r*gg[c] + bbp[c];
    fp16 h, l; split2h(o, h, l);
    oh[(size_t)row*DD + c] = h;
    ol[(size_t)row*DD + c] = l;
  }
}

__global__ void __launch_bounds__(256) qln_split_kernel(const float* __restrict__ qraw,
    const float* __restrict__ gg, const float* __restrict__ bbp,
    bf16* __restrict__ qh, bf16* __restrict__ ql) {
  int row = blockIdx.x;
  int h = threadIdx.x >> 5, lane = threadIdx.x & 31;
  int b = row / LL, l = row - b*LL;
  const float* src = qraw + (size_t)row*DD + h*HDIM;
  float v[4]; float s = 0.f;
#pragma unroll
  for (int i = 0; i < 4; i++) { v[i] = src[lane + i*32]; s += v[i]; }
  float m = warpSum(s) * (1.f/HDIM);
  float d = 0.f;
#pragma unroll
  for (int i = 0; i < 4; i++) { float t = v[i]-m; d += t*t; }
  float var = warpSum(d) * (1.f/HDIM);
  float r = rsqrtf(var + 1e-5f);
  size_t base = ((size_t)(b*HH + h)*LL + l) * HDIM;
#pragma unroll
  for (int i = 0; i < 4; i++) {
    int c = lane + i*32;
    float o = (v[i]-m)*r*gg[c] + bbp[c];
    bf16 hh, llv; split2(o, hh, llv);
    qh[base + c] = hh; ql[base + c] = llv;
  }
}

__global__ void __launch_bounds__(256) klnv_split_kernel(const float* __restrict__ kv,
    const float* __restrict__ gg, const float* __restrict__ bbp,
    bf16* __restrict__ kh, bf16* __restrict__ kl, float* __restrict__ vh) {
  int row = blockIdx.x;
  int h = threadIdx.x >> 5, lane = threadIdx.x & 31;
  int b = row / PP, t = row - b*PP;
  const float* kp = kv + (size_t)row*2*DD + h*HDIM;
  const float* vp = kp + DD;
  float v[4]; float s = 0.f;
#pragma unroll
  for (int i = 0; i < 4; i++) { v[i] = kp[lane + i*32]; s += v[i]; }
  float m = warpSum(s) * (1.f/HDIM);
  float d = 0.f;
#pragma unroll
  for (int i = 0; i < 4; i++) { float t2 = v[i]-m; d += t2*t2; }
  float var = warpSum(d) * (1.f/HDIM);
  float r = rsqrtf(var + 1e-5f);
  size_t base = ((size_t)(b*HH + h)*PP + t) * HDIM;
#pragma unroll
  for (int i = 0; i < 4; i++) {
    int c = lane + i*32;
    float o = (v[i]-m)*r*gg[c] + bbp[c];
    bf16 hh, llv; split2(o, hh, llv);
    kh[base + c] = hh; kl[base + c] = llv;
    vh[base + c] = vp[c];
  }
}

__global__ void __launch_bounds__(256) softmax_split_kernel(const float* __restrict__ x,
    bf16* __restrict__ ph, bf16* __restrict__ pl) {
  const float* xr = x + (size_t)blockIdx.x * PP;
  float v[4];
  float mx = -3.4e38f;
#pragma unroll
  for (int i = 0; i < 4; i++) { v[i] = xr[threadIdx.x + i*256]; mx = fmaxf(mx, v[i]); }
  mx = blockReduceMax(mx);
  float s = 0.f;
#pragma unroll
  for (int i = 0; i < 4; i++) { v[i] = expf(v[i] - mx); s += v[i]; }
  float tot = blockReduceSum(s);
  float inv = 1.f / tot;
  size_t base = (size_t)blockIdx.x * PP;
#pragma unroll
  for (int i = 0; i < 4; i++) {
    float p = v[i] * inv;
    bf16 h, l; split2(p, h, l);
    int c = threadIdx.x + i*256;
    ph[base + c] = h; pl[base + c] = l;
  }
}

// transpose + split bf16 (v only)
__global__ void __launch_bounds__(256) transpose_split_kernel(const float* __restrict__ src,
    bf16* __restrict__ dh, bf16* __restrict__ dl, int R, int C,
    ll sStride, ll dStride) {
  __shared__ float t[32][33];
  int z = blockIdx.z;
  src += (ll)z * sStride;
  dh  += (ll)z * dStride;
  dl  += (ll)z * dStride;
  int c0 = blockIdx.x * 32, r0 = blockIdx.y * 32;
  int tx = threadIdx.x & 31, ty = threadIdx.x >> 5;
#pragma unroll
  for (int j = ty; j < 32; j += 8)
    t[j][tx] = src[(size_t)(r0+j)*C + c0 + tx];
  __syncthreads();
#pragma unroll
  for (int j = ty; j < 32; j += 8) {
    float v = t[tx][j];
    bf16 hh, llv; split2(v, hh, llv);
    size_t off = (size_t)(c0+j)*R + r0 + tx;
    dh[off] = hh; dl[off] = llv;
  }
}

// transpose -> single fp16 (weights)
__global__ void __launch_bounds__(256) transpose_half_kernel(const float* __restrict__ src,
    fp16* __restrict__ dst, int R, int C, ll sStride, ll dStride) {
  __shared__ float t[32][33];
  int z = blockIdx.z;
  src += (ll)z * sStride;
  dst += (ll)z * dStride;
  int c0 = blockIdx.x * 32, r0 = blockIdx.y * 32;
  int tx = threadIdx.x & 31, ty = threadIdx.x >> 5;
#pragma unroll
  for (int j = ty; j < 32; j += 8)
    t[j][tx] = src[(size_t)(r0+j)*C + c0 + tx];
  __syncthreads();
#pragma unroll
  for (int j = ty; j < 32; j += 8)
    dst[(size_t)(c0+j)*R + r0 + tx] = __float2half_rn(t[tx][j]);
}

// ---------------------------------------------------------------------------
// fp32 SGEMM (encoder only)
// ---------------------------------------------------------------------------
template<bool HASBIAS>
__global__ void __launch_bounds__(256, 2) sgemm_kernel(
    const float* __restrict__ A, const float* __restrict__ B, float* __restrict__ C,
    const float* __restrict__ bias, int K, int kGuard, int lda, int ldb, int ldc)
{
  __shared__ float As[16][128];
  __shared__ float Bs[16][128];
  const int tid = threadIdx.x;
  const int row0 = blockIdx.y * 128;
  const int col0 = blockIdx.x * 128;
  const int tx = tid & 15, ty = tid >> 4;
  const int tm0 = ty*8, tn0 = tx*8;
  float acc[8][8];
#pragma unroll
  for (int i = 0; i < 8; i++)
#pragma unroll
    for (int j = 0; j < 8; j++) acc[i][j] = 0.f;
  for (int k0 = 0; k0 < K; k0 += 16) {
#pragma unroll
    for (int u = 0; u < 2; u++) {
      int f = tid + u*256;
      int r = f >> 2, c4 = (f & 3) << 2;
      float4 va = *reinterpret_cast<const float4*>(A + (size_t)(row0 + r)*lda + (k0 + c4));
      As[c4+0][r] = va.x; As[c4+1][r] = va.y; As[c4+2][r] = va.z; As[c4+3][r] = va.w;
    }
#pragma unroll
    for (int u = 0; u < 2; u++) {
      int f = tid + u*256;
      int kk = f >> 5, n4 = (f & 31) << 2;
      float4 vb = make_float4(0.f, 0.f, 0.f, 0.f);
      if (k0 + kk < kGuard)
        vb = *reinterpret_cast<const float4*>(B + (size_t)(k0 + kk)*ldb + (col0 + n4));
      *reinterpret_cast<float4*>(&Bs[kk][n4]) = vb;
    }
    __syncthreads();
#pragma unroll
    for (int kk = 0; kk < 16; kk++) {
      float4 a0 = *reinterpret_cast<const float4*>(&As[kk][tm0]);
      float4 a1 = *reinterpret_cast<const float4*>(&As[kk][tm0+4]);
      float4 b0 = *reinterpret_cast<const float4*>(&Bs[kk][tn0]);
      float4 b1 = *reinterpret_cast<const float4*>(&Bs[kk][tn0+4]);
      float ra[8] = {a0.x,a0.y,a0.z,a0.w,a1.x,a1.y,a1.z,a1.w};
      float rb[8] = {b0.x,b0.y,b0.z,b0.w,b1.x,b1.y,b1.z,b1.w};
#pragma unroll
      for (int i = 0; i < 8; i++)
#pragma unroll
        for (int j = 0; j < 8; j++)
          acc[i][j] = fmaf(ra[i], rb[j], acc[i][j]);
    }
    __syncthreads();
  }
#pragma unroll
  for (int i = 0; i < 8; i++) {
    float* crow = C + (size_t)(row0 + tm0 + i)*ldc + (col0 + tn0);
#pragma unroll
    for (int j = 0; j < 8; j += 4) {
      float4 v;
      v.x = acc[i][j+0]; v.y = acc[i][j+1]; v.z = acc[i][j+2]; v.w = acc[i][j+3];
      if (HASBIAS) {
        float4 bbv = *reinterpret_cast<const float4*>(bias + col0 + tn0 + j);
        v.x += bbv.x; v.y += bbv.y; v.z += bbv.z; v.w += bbv.w;
      }
      *reinterpret_cast<float4*>(crow + j) = v;
    }
  }
}

#define LDSROW 40

// ---------------------------------------------------------------------------
// bf16x3 tensor GEMM (QK, PV): C = alpha*(Ah+Al)@(Bh+Bl)^T
// OUTMODE: 0=store fp32; 2=store split fp16 (for PV->Wout)
// ---------------------------------------------------------------------------
#define TILE_ELEMS (128*LDSROW)
#define STAGE_B3 (4*TILE_ELEMS)
#define B3_SMEM_BYTES (2*STAGE_B3*2)

template<int OUTMODE>
__global__ void __launch_bounds__(256, 2) mma_bf3_kernel(
    const bf16* __restrict__ Ah, const bf16* __restrict__ Al,
    const bf16* __restrict__ Bh, const bf16* __restrict__ Bl,
    float* __restrict__ C, fp16* __restrict__ Ch, fp16* __restrict__ Cl,
    int K, int lda, int ldb, int ldc, int inner,
    ll aSO, ll aSI, ll bSO, ll bSI, ll cSO, ll cSI, float alpha)
{
  extern __shared__ bf16 smbuf[];
  int bz = blockIdx.z;
  int bo = bz / inner, bi = bz - bo*inner;
  ll aoff = (ll)bo*aSO + (ll)bi*aSI;
  ll boff = (ll)bo*bSO + (ll)bi*bSI;
  ll coff = (ll)bo*cSO + (ll)bi*cSI;
  Ah += aoff; Al += aoff; Bh += boff; Bl += boff;

  const int tid = threadIdx.x;
  const int row0 = blockIdx.y * 128;
  const int col0 = blockIdx.x * 128;
  const int wid = tid >> 5, lane = tid & 31;
  const int wm = (wid & 3) * 32;
  const int wn = (wid >> 2) * 64;

  float acc[2][8][4];
#pragma unroll
  for (int mt = 0; mt < 2; mt++)
#pragma unroll
    for (int nt = 0; nt < 8; nt++)
#pragma unroll
      for (int q = 0; q < 4; q++) acc[mt][nt][q] = 0.f;

  {
    bf16* base = smbuf;
#pragma unroll
    for (int i = 0; i < 2; i++) {
      int c = tid + i*256;
      int r = c >> 2, kc = (c & 3) << 3;
      cpa16(s2u(base + 0*TILE_ELEMS + r*LDSROW + kc), Ah + (size_t)(row0+r)*lda + kc);
      cpa16(s2u(base + 1*TILE_ELEMS + r*LDSROW + kc), Al + (size_t)(row0+r)*lda + kc);
      cpa16(s2u(base + 2*TILE_ELEMS + r*LDSROW + kc), Bh + (size_t)(col0+r)*ldb + kc);
      cpa16(s2u(base + 3*TILE_ELEMS + r*LDSROW + kc), Bl + (size_t)(col0+r)*ldb + kc);
    }
    asm volatile("cp.async.commit_group;\n");
  }

  int s = 0;
  for (int k0 = 0; k0 < K; k0 += 32, s ^= 1) {
    asm volatile("cp.async.wait_group 0;\n");
    __syncthreads();
    if (k0 + 32 < K) {
      bf16* base = smbuf + (s^1)*STAGE_B3;
      int kn = k0 + 32;
#pragma unroll
      for (int i = 0; i < 2; i++) {
        int c = tid + i*256;
        int r = c >> 2, kc = (c & 3) << 3;
        cpa16(s2u(base + 0*TILE_ELEMS + r*LDSROW + kc), Ah + (size_t)(row0+r)*lda + kn + kc);
        cpa16(s2u(base + 1*TILE_ELEMS + r*LDSROW + kc), Al + (size_t)(row0+r)*lda + kn + kc);
        cpa16(s2u(base + 2*TILE_ELEMS + r*LDSROW + kc), Bh + (size_t)(col0+r)*ldb + kn + kc);
        cpa16(s2u(base + 3*TILE_ELEMS + r*LDSROW + kc), Bl + (size_t)(col0+r)*ldb + kn + kc);
      }
      asm volatile("cp.async.commit_group;\n");
    }

    bf16* sAh = smbuf + s*STAGE_B3;
    bf16* sAl = sAh + TILE_ELEMS;
    bf16* sBh = sAh + 2*TILE_ELEMS;
    bf16* sBl = sAh + 3*TILE_ELEMS;
    int arow = lane & 15;
    int khalf = (lane >> 4) << 3;

#pragma unroll
    for (int kk = 0; kk < 2; kk++) {
      int kof = kk*16 + khalf;
      unsigned ahf[2][4], alf[2][4], bfr[8][2];
#pragma unroll
      for (int mt = 0; mt < 2; mt++) {
        ldsm4(ahf[mt], s2u(sAh + (wm + mt*16 + arow)*LDSROW + kof));
        ldsm4(alf[mt], s2u(sAl + (wm + mt*16 + arow)*LDSROW + kof));
      }
#pragma unroll
      for (int np = 0; np < 4; np++) {
        unsigned t[4];
        ldsm4(t, s2u(sBh + (wn + np*16 + arow)*LDSROW + kof));
        bfr[2*np][0] = t[0]; bfr[2*np][1] = t[2];
        bfr[2*np+1][0] = t[1]; bfr[2*np+1][1] = t[3];
      }
#pragma unroll
      for (int mt = 0; mt < 2; mt++)
#pragma unroll
        for (int nt = 0; nt < 8; nt++) {
          mma_bf(acc[mt][nt], ahf[mt], bfr[nt]);
          mma_bf(acc[mt][nt], alf[mt], bfr[nt]);
        }
#pragma unroll
      for (int np = 0; np < 4; np++) {
        unsigned t[4];
        ldsm4(t, s2u(sBl + (wn + np*16 + arow)*LDSROW + kof));
        bfr[2*np][0] = t[0]; bfr[2*np][1] = t[2];
        bfr[2*np+1][0] = t[1]; bfr[2*np+1][1] = t[3];
      }
#pragma unroll
      for (int mt = 0; mt < 2; mt++)
#pragma unroll
        for (int nt = 0; nt < 8; nt++)
          mma_bf(acc[mt][nt], ahf[mt], bfr[nt]);
    }
  }

  int rb = row0 + wm + (lane >> 2);
  int cb = col0 + wn + (lane & 3)*2;
#pragma unroll
  for (int mt = 0; mt < 2; mt++) {
#pragma unroll
    for (int nt = 0; nt < 8; nt++) {
#pragma unroll
      for (int h2 = 0; h2 < 2; h2++) {
        int r = rb + mt*16 + h2*8;
        int cc = cb + nt*8;
        float v0 = alpha * acc[mt][nt][h2*2+0];
        float v1 = alpha * acc[mt][nt][h2*2+1];
        ll off = coff + (ll)r*ldc + cc;
        if (OUTMODE == 0) {
          float2 o; o.x = v0; o.y = v1;
          *reinterpret_cast<float2*>(C + off) = o;
        } else {
          fp16 h0, l0, h1, l1;
          split2h(v0, h0, l0); split2h(v1, h1, l1);
          __half2 phv; phv.x = h0; phv.y = h1;
          __half2 plv; plv.x = l0; plv.y = l1;
          *reinterpret_cast<__half2*>(Ch + off) = phv;
          *reinterpret_cast<__half2*>(Cl + off) = plv;
        }
      }
    }
  }
}

// ---------------------------------------------------------------------------
// fp16 2-product GEMM (dense): C = act(alpha*(Ah+Al)@B^T + bias)
// A: [M][K] fp16 hi/lo; B: [N][K] fp16 single. fp32 accumulate.
// OUTMODE: 0=store fp32; 1=accumulate fp32; 2=store split fp16;
//          3=accumulate fp32 AND store split fp16 of the sum.
// ---------------------------------------------------------------------------
#define STAGE_H2 (3*TILE_ELEMS)
#define H2_SMEM_BYTES (2*STAGE_H2*2)

template<bool ACT, bool HASBIAS, int OUTMODE>
__global__ void __launch_bounds__(256, 2) mma_h2_kernel(
    const fp16* __restrict__ Ah, const fp16* __restrict__ Al,
    const fp16* __restrict__ B,
    float* __restrict__ C, fp16* __restrict__ Ch, fp16* __restrict__ Cl,
    const float* __restrict__ bias,
    int K, int lda, int ldb, int ldc, int inner,
    ll aSO, ll aSI, ll bSO, ll cSO, ll cSI, float alpha)
{
  extern __shared__ fp16 smh[];
  int bz = blockIdx.z;
  int bo = bz / inner, bi = bz - bo*inner;
  ll aoff = (ll)bo*aSO + (ll)bi*aSI;
  ll coff = (ll)bo*cSO + (ll)bi*cSI;
  Ah += aoff; Al += aoff; B += (ll)bo*bSO;

  const int tid = threadIdx.x;
  const int row0 = blockIdx.y * 128;
  const int col0 = blockIdx.x * 128;
  const int wid = tid >> 5, lane = tid & 31;
  const int wm = (wid & 3) * 32;
  const int wn = (wid >> 2) * 64;

  float acc[2][8][4];
#pragma unroll
  for (int mt = 0; mt < 2; mt++)
#pragma unroll
    for (int nt = 0; nt < 8; nt++)
#pragma unroll
      for (int q = 0; q < 4; q++) acc[mt][nt][q] = 0.f;

  {
    fp16* base = smh;
#pragma unroll
    for (int i = 0; i < 2; i++) {
      int c = tid + i*256;
      int r = c >> 2, kc = (c & 3) << 3;
      cpa16(s2u(base + 0*TILE_ELEMS + r*LDSROW + kc), Ah + (size_t)(row0+r)*lda + kc);
      cpa16(s2u(base + 1*TILE_ELEMS + r*LDSROW + kc), Al + (size_t)(row0+r)*lda + kc);
      cpa16(s2u(base + 2*TILE_ELEMS + r*LDSROW + kc), B  + (size_t)(col0+r)*ldb + kc);
    }
    asm volatile("cp.async.commit_group;\n");
  }

  int s = 0;
  for (int k0 = 0; k0 < K; k0 += 32, s ^= 1) {
    asm volatile("cp.async.wait_group 0;\n");
    __syncthreads();
    if (k0 + 32 < K) {
      fp16* base = smh + (s^1)*STAGE_H2;
      int kn = k0 + 32;
#pragma unroll
      for (int i = 0; i < 2; i++) {
        int c = tid + i*256;
        int r = c >> 2, kc = (c & 3) << 3;
        cpa16(s2u(base + 0*TILE_ELEMS + r*LDSROW + kc), Ah + (size_t)(row0+r)*lda + kn + kc);
        cpa16(s2u(base + 1*TILE_ELEMS + r*LDSROW + kc), Al + (size_t)(row0+r)*lda + kn + kc);
        cpa16(s2u(base + 2*TILE_ELEMS + r*LDSROW + kc), B  + (size_t)(col0+r)*ldb + kn + kc);
      }
      asm volatile("cp.async.commit_group;\n");
    }

    fp16* sAh = smh + s*STAGE_H2;
    fp16* sAl = sAh + TILE_ELEMS;
    fp16* sB  = sAh + 2*TILE_ELEMS;
    int arow = lane & 15;
    int khalf = (lane >> 4) << 3;

#pragma unroll
    for (int kk = 0; kk < 2; kk++) {
      int kof = kk*16 + khalf;
      unsigned ahf[2][4], alf[2][4], bfr[8][2];
#pragma unroll
      for (int mt = 0; mt < 2; mt++) {
        ldsm4(ahf[mt], s2u(sAh + (wm + mt*16 + arow)*LDSROW + kof));
        ldsm4(alf[mt], s2u(sAl + (wm + mt*16 + arow)*LDSROW + kof));
      }
#pragma unroll
      for (int np = 0; np < 4; np++) {
        unsigned t[4];
        ldsm4(t, s2u(sB + (wn + np*16 + arow)*LDSROW + kof));
        bfr[2*np][0] = t[0]; bfr[2*np][1] = t[2];
        bfr[2*np+1][0] = t[1]; bfr[2*np+1][1] = t[3];
      }
#pragma unroll
      for (int mt = 0; mt < 2; mt++)
#pragma unroll
        for (int nt = 0; nt < 8; nt++) {
          mma_hf(acc[mt][nt], ahf[mt], bfr[nt]);
          mma_hf(acc[mt][nt], alf[mt], bfr[nt]);
        }
    }
  }

  int rb = row0 + wm + (lane >> 2);
  int cb = col0 + wn + (lane & 3)*2;
#pragma unroll
  for (int mt = 0; mt < 2; mt++) {
#pragma unroll
    for (int nt = 0; nt < 8; nt++) {
#pragma unroll
      for (int h2 = 0; h2 < 2; h2++) {
        int r = rb + mt*16 + h2*8;
        int cc = cb + nt*8;
        float v0 = alpha * acc[mt][nt][h2*2+0];
        float v1 = alpha * acc[mt][nt][h2*2+1];
        if (HASBIAS) { v0 += bias[cc]; v1 += bias[cc+1]; }
        if (ACT) { v0 = gelu_f(v0); v1 = gelu_f(v1); }
        ll off = coff + (ll)r*ldc + cc;
        if (OUTMODE == 0) {
          float2 o; o.x = v0; o.y = v1;
          *reinterpret_cast<float2*>(C + off) = o;
        } else if (OUTMODE == 1) {
          float2 o = *reinterpret_cast<const float2*>(C + off);
          o.x += v0; o.y += v1;
          *reinterpret_cast<float2*>(C + off) = o;
        } else if (OUTMODE == 2) {
          fp16 h0, l0, h1, l1;
          split2h(v0, h0, l0); split2h(v1, h1, l1);
          __half2 phv; phv.x = h0; phv.y = h1;
          __half2 plv; plv.x = l0; plv.y = l1;
          *reinterpret_cast<__half2*>(Ch + off) = phv;
          *reinterpret_cast<__half2*>(Cl + off) = plv;
        } else {
          float2 o = *reinterpret_cast<const float2*>(C + off);
          o.x += v0; o.y += v1;
          *reinterpret_cast<float2*>(C + off) = o;
          fp16 h0, l0, h1, l1;
          split2h(o.x, h0, l0); split2h(o.y, h1, l1);
          __half2 phv; phv.x = h0; phv.y = h1;
          __half2 plv; plv.x = l0; plv.y = l1;
          *reinterpret_cast<__half2*>(Ch + off) = phv;
          *reinterpret_cast<__half2*>(Cl + off) = plv;
        }
      }
    }
  }
}

// ---------------------------------------------------------------------------
// Head second GEMM (reads fp16 split hidden)
// ---------------------------------------------------------------------------
__global__ void __launch_bounds__(256) head2_kernel(const fp16* __restrict__ hbh,
    const fp16* __restrict__ hbl, const float* __restrict__ W2,
    const float* __restrict__ b2, float* __restrict__ out) {
  int idx = blockIdx.x;
  int b = idx / PP, t = idx - b*PP;
  const fp16* hh = hbh + (size_t)idx * NHID;
  const fp16* hl = hbl + (size_t)idx * NHID;
  float acc[NOUTD];
#pragma unroll
  for (int o = 0; o < NOUTD; o++) acc[o] = 0.f;
  for (int k = threadIdx.x; k < NHID; k += 256) {
    float v = __half2float(hh[k]) + __half2float(hl[k]);
    const float* w = W2 + (size_t)k * (NOUTD + 1);
#pragma unroll
    for (int o = 0; o < NOUTD; o++) acc[o] += v * w[o];
  }
  __shared__ float smr[8][NOUTD];
  int lane = threadIdx.x & 31, wid = threadIdx.x >> 5;
#pragma unroll
  for (int o = 0; o < NOUTD; o++) acc[o] = warpSum(acc[o]);
  if (lane == 0) {
#pragma unroll
    for (int o = 0; o < NOUTD; o++) smr[wid][o] = acc[o];
  }
  __syncthreads();
  if (threadIdx.x < NOUTD) {
    float sv = 0.f;
#pragma unroll
    for (int w = 0; w < 8; w++) sv += smr[w][threadIdx.x];
    out[((size_t)t*BB + b)*NOUTD + threadIdx.x] = sv + b2[threadIdx.x];
  }
}

// ---------------------------------------------------------------------------
// Orchestration
// ---------------------------------------------------------------------------
typedef void (*b3_fn)(const bf16*, const bf16*, const bf16*, const bf16*,
                      float*, fp16*, fp16*,
                      int, int, int, int, int, ll, ll, ll, ll, ll, ll, float);
typedef void (*h2_fn)(const fp16*, const fp16*, const fp16*,
                      float*, fp16*, fp16*, const float*,
                      int, int, int, int, int, ll, ll, ll, ll, ll, float);

extern "C" void kernel_launch(void* const* d_in, const int* in_sizes, int n_in,
                              void* d_out, int out_size) {
  (void)in_sizes; (void)n_in; (void)out_size;
  const float* x_src = (const float*)d_in[0];
  const float* y_src = (const float*)d_in[1];
  const float* enc_W = (const float*)d_in[2];
  const float* enc_b = (const float*)d_in[3];
  const float* yenc_W = (const float*)d_in[4];
  const float* yenc_b = (const float*)d_in[5];
  const float* Wq    = (const float*)d_in[6];
  const float* Wkv   = (const float*)d_in[7];
  const float* Wout  = (const float*)d_in[8];
  const float* an_g  = (const float*)d_in[9];
  const float* an_b  = (const float*)d_in[10];
  const float* qn_g  = (const float*)d_in[11];
  const float* qn_b  = (const float*)d_in[12];
  const float* kn_g  = (const float*)d_in[13];
  const float* kn_b  = (const float*)d_in[14];
  const float* fn_g  = (const float*)d_in[15];
  const float* fn_b  = (const float*)d_in[16];
  const float* ffW1  = (const float*)d_in[17];
  const float* ffb1  = (const float*)d_in[18];
  const float* ffW2  = (const float*)d_in[19];
  const float* ffb2  = (const float*)d_in[20];
  const float* hW1   = (const float*)d_in[21];
  const float* hb1   = (const float*)d_in[22];
  const float* hW2   = (const float*)d_in[23];
  const float* hb2   = (const float*)d_in[24];
  float* out = (float*)d_out;

  {
    b3_fn f;
    f = mma_bf3_kernel<0>;
    cudaFuncSetAttribute(f, cudaFuncAttributeMaxDynamicSharedMemorySize, B3_SMEM_BYTES);
    f = mma_bf3_kernel<2>;
    cudaFuncSetAttribute(f, cudaFuncAttributeMaxDynamicSharedMemorySize, B3_SMEM_BYTES);
    h2_fn g;
    g = mma_h2_kernel<false,false,0>;
    cudaFuncSetAttribute(g, cudaFuncAttributeMaxDynamicSharedMemorySize, H2_SMEM_BYTES);
    g = mma_h2_kernel<false,false,1>;
    cudaFuncSetAttribute(g, cudaFuncAttributeMaxDynamicSharedMemorySize, H2_SMEM_BYTES);
    g = mma_h2_kernel<true,true,2>;
    cudaFuncSetAttribute(g, cudaFuncAttributeMaxDynamicSharedMemorySize, H2_SMEM_BYTES);
    g = mma_h2_kernel<false,true,1>;
    cudaFuncSetAttribute(g, cudaFuncAttributeMaxDynamicSharedMemorySize, H2_SMEM_BYTES);
    g = mma_h2_kernel<false,true,3>;
    cudaFuncSetAttribute(g, cudaFuncAttributeMaxDynamicSharedMemorySize, H2_SMEM_BYTES);
  }

  float *p_xn, *p_src, *p_tmp, *p_vh, *p_logits;
  cudaGetSymbolAddress((void**)&p_xn, g_xn);
  cudaGetSymbolAddress((void**)&p_src, g_src);
  cudaGetSymbolAddress((void**)&p_tmp, g_tmp);
  cudaGetSymbolAddress((void**)&p_vh, g_vh);
  cudaGetSymbolAddress((void**)&p_logits, g_logits);
  fp16 *p_ah, *p_al, *p_ffh, *p_ffl;
  cudaGetSymbolAddress((void**)&p_ah, g_ah);
  cudaGetSymbolAddress((void**)&p_al, g_al);
  cudaGetSymbolAddress((void**)&p_ffh, g_ffh);
  cudaGetSymbolAddress((void**)&p_ffl, g_ffl);
  bf16 *p_qhh, *p_qhl, *p_khh, *p_khl, *p_vth, *p_vtl, *p_ph, *p_pl;
  cudaGetSymbolAddress((void**)&p_qhh, g_qhh);
  cudaGetSymbolAddress((void**)&p_qhl, g_qhl);
  cudaGetSymbolAddress((void**)&p_khh, g_khh);
  cudaGetSymbolAddress((void**)&p_khl, g_khl);
  cudaGetSymbolAddress((void**)&p_vth, g_vth);
  cudaGetSymbolAddress((void**)&p_vtl, g_vtl);
  cudaGetSymbolAddress((void**)&p_ph, g_ph);
  cudaGetSymbolAddress((void**)&p_pl, g_pl);
  fp16 *pWq, *pWkv, *pWo, *pW1, *pW2, *pHW1;
  cudaGetSymbolAddress((void**)&pWq, g_WqT);
  cudaGetSymbolAddress((void**)&pWkv, g_WkvT);
  cudaGetSymbolAddress((void**)&pWo, g_WoT);
  cudaGetSymbolAddress((void**)&pW1, g_W1T);
  cudaGetSymbolAddress((void**)&pW2, g_W2T);
  cudaGetSymbolAddress((void**)&pHW1, g_hW1T);

  const float qk_scale = 0.08838834764831845f;

  // --- weight transpose -> fp16 ---
  transpose_half_kernel<<<dim3(DD/32, DD/32, NLAYERS), 256>>>(Wq, pWq, DD, DD, (ll)DD*DD, (ll)DD*DD);
  transpose_half_kernel<<<dim3(2*DD/32, DD/32, NLAYERS), 256>>>(Wkv, pWkv, DD, 2*DD, (ll)DD*2*DD, (ll)DD*2*DD);
  transpose_half_kernel<<<dim3(DD/32, DD/32, NLAYERS), 256>>>(Wout, pWo, DD, DD, (ll)DD*DD, (ll)DD*DD);
  transpose_half_kernel<<<dim3(NHID/32, DD/32, NLAYERS), 256>>>(ffW1, pW1, DD, NHID, (ll)DD*NHID, (ll)DD*NHID);
  transpose_half_kernel<<<dim3(DD/32, NHID/32, NLAYERS), 256>>>(ffW2, pW2, NHID, DD, (ll)NHID*DD, (ll)NHID*DD);
  transpose_half_kernel<<<dim3(NHID/32, DD/32, 1), 256>>>(hW1, pHW1, DD, NHID, 0, 0);

  // --- preprocessing + encoder ---
  colstats_kernel<<<BB*NFEAT, 256>>>(x_src, 0);
  colstats_kernel<<<BB*NFEAT, 256>>>(x_src, 1);
  colstats_kernel<<<BB*NFEAT, 256>>>(x_src, 2);
  norm_write_kernel<<<(LB*KPAD + 255)/256, 256>>>(x_src);
  sgemm_kernel<true><<<dim3(DD/128, LB/128, 1), 256>>>(
      p_xn, enc_W, p_tmp, enc_b, KPAD, NFEAT, KPAD, DD, DD);
  encode_finish_kernel<<<LB, 256>>>(p_tmp, y_src, yenc_W, yenc_b);

  for (int i = 0; i < NLAYERS; i++) {
    // --- attention ---
    ln_splith_kernel<<<LB, 256>>>(p_src, an_g + i*DD, an_b + i*DD, p_ah, p_al);
    // q = h @ Wq (fp16 2-product)
    mma_h2_kernel<false,false,0><<<dim3(8, 64, 1), 256, H2_SMEM_BYTES>>>(
        p_ah, p_al, pWq + (size_t)i*DD*DD,
        p_tmp, nullptr, nullptr, nullptr,
        DD, DD, DD, DD, 1, 0,0,0,0,0, 1.f);
    qln_split_kernel<<<LB, 256>>>(p_tmp, qn_g + i*HDIM, qn_b + i*HDIM, p_qhh, p_qhl);
    // kv = h[:, :P] @ Wkv (fp16, batched over b)
    mma_h2_kernel<false,false,0><<<dim3(16, 8, BB), 256, H2_SMEM_BYTES>>>(
        p_ah, p_al, pWkv + (size_t)i*DD*2*DD,
        p_tmp, nullptr, nullptr, nullptr,
        DD, DD, DD, 2*DD, 1,
        (ll)LL*DD, 0, 0, (ll)PP*2*DD, 0, 1.f);
    klnv_split_kernel<<<BB*PP, 256>>>(p_tmp, kn_g + i*HDIM, kn_b + i*HDIM, p_khh, p_khl, p_vh);
    transpose_split_kernel<<<dim3(HDIM/32, PP/32, BB*HH), 256>>>(
        p_vh, p_vth, p_vtl, PP, HDIM, (ll)PP*HDIM, (ll)PP*HDIM);
    // logits = scale * q @ k^T (bf16x3)
    mma_bf3_kernel<0><<<dim3(8, 16, BB*HH), 256, B3_SMEM_BYTES>>>(
        p_qhh, p_qhl, p_khh, p_khl, p_logits, nullptr, nullptr,
        HDIM, HDIM, HDIM, PP, 1,
        (ll)LL*HDIM, 0, (ll)PP*HDIM, 0, (ll)LL*PP, 0, qk_scale);
    softmax_split_kernel<<<BB*HH*LL, 256>>>(p_logits, p_ph, p_pl);
    // attn = probs @ vT^T (bf16x3) -> fp16 split (B,L,H,HD)
    mma_bf3_kernel<2><<<dim3(1, 16, BB*HH), 256, B3_SMEM_BYTES>>>(
        p_ph, p_pl, p_vth, p_vtl, nullptr, p_ah, p_al,
        PP, PP, PP, DD, HH,
        (ll)HH*LL*PP, (ll)LL*PP,
        (ll)HH*HDIM*PP, (ll)HDIM*PP,
        (ll)LL*DD, (ll)HDIM, 1.f);
    // src += attn @ Wout (fp16)
    mma_h2_kernel<false,false,1><<<dim3(8, 64, 1), 256, H2_SMEM_BYTES>>>(
        p_ah, p_al, pWo + (size_t)i*DD*DD,
        p_src, nullptr, nullptr, nullptr,
        DD, DD, DD, DD, 1, 0,0,0,0,0, 1.f);
    // --- FFN ---
    ln_splith_kernel<<<LB, 256>>>(p_src, fn_g + i*DD, fn_b + i*DD, p_ah, p_al);
    mma_h2_kernel<true,true,2><<<dim3(NHID/128, 64, 1), 256, H2_SMEM_BYTES>>>(
        p_ah, p_al, pW1 + (size_t)i*NHID*DD,
        nullptr, p_ffh, p_ffl, ffb1 + (size_t)i*NHID,
        DD, DD, DD, NHID, 1, 0,0,0,0,0, 1.f);
    if (i < NLAYERS - 1) {
      mma_h2_kernel<false,true,1><<<dim3(8, 64, 1), 256, H2_SMEM_BYTES>>>(
          p_ffh, p_ffl, pW2 + (size_t)i*DD*NHID,
          p_src, nullptr, nullptr, ffb2 + (size_t)i*DD,
          NHID, NHID, NHID, DD, 1, 0,0,0,0,0, 1.f);
    } else {
      mma_h2_kernel<false,true,3><<<dim3(8, 64, 1), 256, H2_SMEM_BYTES>>>(
          p_ffh, p_ffl, pW2 + (size_t)i*DD*NHID,
          p_src, p_ah, p_al, ffb2 + (size_t)i*DD,
          NHID, NHID, NHID, DD, 1, 0,0,0,0,0, 1.f);
    }
  }

  // --- head (p_ah/p_al hold fp16 split src from OUTMODE 3) ---
  mma_h2_kernel<true,true,2><<<dim3(NHID/128, PP/128, BB), 256, H2_SMEM_BYTES>>>(
      p_ah + (size_t)PP*DD, p_al + (size_t)PP*DD, pHW1,
      nullptr, p_ffh, p_ffl, hb1,
      DD, DD, DD, NHID, 1,
      (ll)LL*DD, 0, 0, (ll)PP*NHID, 0, 1.f);
  head2_kernel<<<BB*PP, 256>>>(p_ffh, p_ffl, hW2, hb2, out);
}

// round 10
// speedup vs baseline: 2.1838x; 1.5356x over previous
#include <cuda_runtime.h>
#include <cuda_bf16.h>
#include <cuda_fp16.h>
#include <cstdint>
#include <cstddef>
#include <math.h>

// ---------------------------------------------------------------------------
// Problem constants
// ---------------------------------------------------------------------------
#define BB     4
#define LL     2048
#define PP     1024
#define NFEAT  100
#define DD     1024
#define HH     8
#define HDIM   128
#define NHID   4096
#define NLAYERS 3
#define NOUTD  10
#define LB     (LL*BB)
#define KPAD   112

typedef __nv_bfloat16 bf16;
typedef __half fp16;
typedef long long ll;

// ---------------------------------------------------------------------------
// Scratch (device globals)
// ---------------------------------------------------------------------------
__device__ float g_m1[BB*NFEAT], g_s1[BB*NFEAT];
__device__ float g_m2[BB*NFEAT], g_s2[BB*NFEAT];
__device__ float g_m3[BB*NFEAT], g_s3[BB*NFEAT];
__device__ __align__(256) float g_xn[(size_t)LB*KPAD];
__device__ __align__(256) float g_src[(size_t)LB*DD];
__device__ __align__(256) float g_tmp[(size_t)LB*DD];
__device__ __align__(256) float g_vh [(size_t)BB*HH*PP*HDIM];
__device__ __align__(256) float g_logits[(size_t)BB*HH*LL*PP];

// fp16 single activations (dense GEMM operands / outputs)
__device__ __align__(256) fp16 g_ah[(size_t)LB*DD];
__device__ __align__(256) fp16 g_ffh[(size_t)LB*NHID];
__device__ __align__(256) fp16 g_ph [(size_t)BB*HH*LL*PP];   // probs fp16
__device__ __align__(256) fp16 g_vth[(size_t)BB*HH*HDIM*PP]; // vT fp16

// bf16 split QK operands
__device__ __align__(256) bf16 g_qhh[(size_t)BB*HH*LL*HDIM];
__device__ __align__(256) bf16 g_qhl[(size_t)BB*HH*LL*HDIM];
__device__ __align__(256) bf16 g_khh[(size_t)BB*HH*PP*HDIM];
__device__ __align__(256) bf16 g_khl[(size_t)BB*HH*PP*HDIM];

// fp16 transposed weights
__device__ __align__(256) fp16 g_WqT [(size_t)NLAYERS*DD*DD];
__device__ __align__(256) fp16 g_WkvT[(size_t)NLAYERS*2*DD*DD];
__device__ __align__(256) fp16 g_WoT [(size_t)NLAYERS*DD*DD];
__device__ __align__(256) fp16 g_W1T [(size_t)NLAYERS*NHID*DD];
__device__ __align__(256) fp16 g_W2T [(size_t)NLAYERS*DD*NHID];
__device__ __align__(256) fp16 g_hW1T[(size_t)NHID*DD];

// ---------------------------------------------------------------------------
// Helpers
// ---------------------------------------------------------------------------
__device__ __forceinline__ float warpSum(float v) {
#pragma unroll
  for (int o = 16; o > 0; o >>= 1) v += __shfl_xor_sync(0xffffffffu, v, o);
  return v;
}

__device__ __forceinline__ float blockReduceSum(float v) {
  __shared__ float sh[32];
  int lane = threadIdx.x & 31, wid = threadIdx.x >> 5;
  v = warpSum(v);
  if (lane == 0) sh[wid] = v;
  __syncthreads();
  int nw = (blockDim.x + 31) >> 5;
  v = (threadIdx.x < nw) ? sh[threadIdx.x] : 0.f;
  if (wid == 0) { v = warpSum(v); if (lane == 0) sh[0] = v; }
  __syncthreads();
  float r = sh[0];
  __syncthreads();
  return r;
}

__device__ __forceinline__ float blockReduceMax(float v) {
  __shared__ float sh[32];
  int lane = threadIdx.x & 31, wid = threadIdx.x >> 5;
#pragma unroll
  for (int o = 16; o > 0; o >>= 1) v = fmaxf(v, __shfl_xor_sync(0xffffffffu, v, o));
  if (lane == 0) sh[wid] = v;
  __syncthreads();
  int nw = (blockDim.x + 31) >> 5;
  v = (threadIdx.x < nw) ? sh[threadIdx.x] : -3.4e38f;
  if (wid == 0) {
#pragma unroll
    for (int o = 16; o > 0; o >>= 1) v = fmaxf(v, __shfl_xor_sync(0xffffffffu, v, o));
    if (lane == 0) sh[0] = v;
  }
  __syncthreads();
  float r = sh[0];
  __syncthreads();
  return r;
}

__device__ __forceinline__ float gelu_f(float x) {
  return 0.5f * x * (1.0f + erff(x * 0.7071067811865475f));
}

__device__ __forceinline__ void split2(float v, bf16& h, bf16& l) {
  h = __float2bfloat16_rn(v);
  l = __float2bfloat16_rn(v - __bfloat162float(h));
}

__device__ __forceinline__ unsigned s2u(const void* p) {
  return (unsigned)__cvta_generic_to_shared(p);
}

__device__ __forceinline__ void cpa16(unsigned s, const void* g) {
  asm volatile("cp.async.cg.shared.global [%0], [%1], 16;\n" :: "r"(s), "l"(g));
}

__device__ __forceinline__ void ldsm4(unsigned* r, unsigned addr) {
  asm volatile("ldmatrix.sync.aligned.m8n8.x4.shared.b16 {%0,%1,%2,%3}, [%4];\n"
    : "=r"(r[0]), "=r"(r[1]), "=r"(r[2]), "=r"(r[3]) : "r"(addr));
}

__device__ __forceinline__ void mma_bf(float* c, const unsigned* a, const unsigned* b) {
  asm volatile("mma.sync.aligned.m16n8k16.row.col.f32.bf16.bf16.f32 "
    "{%0,%1,%2,%3}, {%4,%5,%6,%7}, {%8,%9}, {%0,%1,%2,%3};\n"
    : "+f"(c[0]), "+f"(c[1]), "+f"(c[2]), "+f"(c[3])
    : "r"(a[0]), "r"(a[1]), "r"(a[2]), "r"(a[3]), "r"(b[0]), "r"(b[1]));
}

__device__ __forceinline__ void mma_hf(float* c, const unsigned* a, const unsigned* b) {
  asm volatile("mma.sync.aligned.m16n8k16.row.col.f32.f16.f16.f32 "
    "{%0,%1,%2,%3}, {%4,%5,%6,%7}, {%8,%9}, {%0,%1,%2,%3};\n"
    : "+f"(c[0]), "+f"(c[1]), "+f"(c[2]), "+f"(c[3])
    : "r"(a[0]), "r"(a[1]), "r"(a[2]), "r"(a[3]), "r"(b[0]), "r"(b[1]));
}

// ---------------------------------------------------------------------------
// Preprocessing / LN / softmax / transpose kernels
// ---------------------------------------------------------------------------
__global__ void __launch_bounds__(256) colstats_kernel(const float* __restrict__ xsrc, int mode) {
  int bf = blockIdx.x;
  int b = bf / NFEAT, f = bf - b*NFEAT;
  const float* base = xsrc + (size_t)b*LL*NFEAT + f;
  float m1 = g_m1[bf], s1 = g_s1[bf];
  float m2 = g_m2[bf], s2 = g_s2[bf];
  float lo1 = m1 - 4.f*s1, hi1 = m1 + 4.f*s1;
  float inv2 = 1.f / (s2 + 1e-6f);
  float sum = 0.f, sq = 0.f;
  for (int t = threadIdx.x; t < PP; t += blockDim.x) {
    float v = base[(size_t)t*NFEAT];
    if (mode >= 1) v = fminf(fmaxf(v, lo1), hi1);
    if (mode >= 2) v = (v - m2) * inv2;
    sum += v; sq += v*v;
  }
  sum = blockReduceSum(sum);
  sq  = blockReduceSum(sq);
  if (threadIdx.x == 0) {
    float m = sum * (1.f/PP);
    float var = sq * (1.f/PP) - m*m;
    float s = sqrtf(fmaxf(var, 0.f));
    if (mode == 0)      { g_m1[bf] = m; g_s1[bf] = s; }
    else if (mode == 1) { g_m2[bf] = m; g_s2[bf] = s; }
    else                { g_m3[bf] = m; g_s3[bf] = s; }
  }
}

__global__ void __launch_bounds__(256) norm_write_kernel(const float* __restrict__ xsrc) {
  int idx = blockIdx.x * blockDim.x + threadIdx.x;
  if (idx >= LB*KPAD) return;
  int row = idx / KPAD, f = idx - row*KPAD;
  int l = row / BB, b = row - l*BB;
  float out = 0.f;
  if (f < NFEAT) {
    int bf = b*NFEAT + f;
    float v = xsrc[(size_t)b*LL*NFEAT + (size_t)l*NFEAT + f];
    float m1 = g_m1[bf], s1 = g_s1[bf];
    v = fminf(fmaxf(v, m1 - 4.f*s1), m1 + 4.f*s1);
    v = (v - g_m2[bf]) / (g_s2[bf] + 1e-6f);
    float m3 = g_m3[bf], s3 = g_s3[bf];
    v = fminf(fmaxf(v, m3 - 4.f*s3), m3 + 4.f*s3);
    if (!isfinite(v)) v = 0.f;
    out = v;
  }
  g_xn[idx] = out;
}

__global__ void __launch_bounds__(256) encode_finish_kernel(const float* __restrict__ xeD,
    const float* __restrict__ ysrc, const float* __restrict__ yencW, const float* __restrict__ yencb) {
  int row = blockIdx.x;
  int l = row / BB, b = row - l*BB;
  const float* xr = xeD + (size_t)row * DD;
  float v[4]; float sq = 0.f;
#pragma unroll
  for (int i = 0; i < 4; i++) { v[i] = xr[threadIdx.x + i*256]; sq += v[i]*v[i]; }
  float ms = blockReduceSum(sq) * (1.f/DD);
  float inv = 1.f / sqrtf(ms);
  bool addy = (l < PP);
  float yv = addy ? ysrc[(size_t)b*PP + l] : 0.f;
  float* dst = g_src + ((size_t)b*LL + l) * DD;
#pragma unroll
  for (int i = 0; i < 4; i++) {
    int c = threadIdx.x + i*256;
    float o = v[i] * inv;
    if (addy) o += yv * yencW[c] + yencb[c];
    dst[c] = o;
  }
}

// LayerNorm over D -> single fp16
__global__ void __launch_bounds__(256) ln_half_kernel(const float* __restrict__ x,
    const float* __restrict__ gg, const float* __restrict__ bbp,
    fp16* __restrict__ oh) {
  int row = blockIdx.x;
  const float* xr = x + (size_t)row * DD;
  float v[4]; float s = 0.f;
#pragma unroll
  for (int i = 0; i < 4; i++) { v[i] = xr[threadIdx.x + i*256]; s += v[i]; }
  float m = blockReduceSum(s) * (1.f/DD);
  float d = 0.f;
#pragma unroll
  for (int i = 0; i < 4; i++) { float t = v[i]-m; d += t*t; }
  float var = blockReduceSum(d) * (1.f/DD);
  float r = rsqrtf(var + 1e-5f);
#pragma unroll
  for (int i = 0; i < 4; i++) {
    int c = threadIdx.x + i*256;
    float o = (v[i]-m)*r*gg[c] + bbp[c];
    oh[(size_t)row*DD + c] = __float2half_rn(o);
  }
}

__global__ void __launch_bounds__(256) qln_split_kernel(const float* __restrict__ qraw,
    const float* __restrict__ gg, const float* __restrict__ bbp,
    bf16* __restrict__ qh, bf16* __restrict__ ql) {
  int row = blockIdx.x;
  int h = threadIdx.x >> 5, lane = threadIdx.x & 31;
  int b = row / LL, l = row - b*LL;
  const float* src = qraw + (size_t)row*DD + h*HDIM;
  float v[4]; float s = 0.f;
#pragma unroll
  for (int i = 0; i < 4; i++) { v[i] = src[lane + i*32]; s += v[i]; }
  float m = warpSum(s) * (1.f/HDIM);
  float d = 0.f;
#pragma unroll
  for (int i = 0; i < 4; i++) { float t = v[i]-m; d += t*t; }
  float var = warpSum(d) * (1.f/HDIM);
  float r = rsqrtf(var + 1e-5f);
  size_t base = ((size_t)(b*HH + h)*LL + l) * HDIM;
#pragma unroll
  for (int i = 0; i < 4; i++) {
    int c = lane + i*32;
    float o = (v[i]-m)*r*gg[c] + bbp[c];
    bf16 hh, llv; split2(o, hh, llv);
    qh[base + c] = hh; ql[base + c] = llv;
  }
}

__global__ void __launch_bounds__(256) klnv_split_kernel(const float* __restrict__ kv,
    const float* __restrict__ gg, const float* __restrict__ bbp,
    bf16* __restrict__ kh, bf16* __restrict__ kl, float* __restrict__ vh) {
  int row = blockIdx.x;
  int h = threadIdx.x >> 5, lane = threadIdx.x & 31;
  int b = row / PP, t = row - b*PP;
  const float* kp = kv + (size_t)row*2*DD + h*HDIM;
  const float* vp = kp + DD;
  float v[4]; float s = 0.f;
#pragma unroll
  for (int i = 0; i < 4; i++) { v[i] = kp[lane + i*32]; s += v[i]; }
  float m = warpSum(s) * (1.f/HDIM);
  float d = 0.f;
#pragma unroll
  for (int i = 0; i < 4; i++) { float t2 = v[i]-m; d += t2*t2; }
  float var = warpSum(d) * (1.f/HDIM);
  float r = rsqrtf(var + 1e-5f);
  size_t base = ((size_t)(b*HH + h)*PP + t) * HDIM;
#pragma unroll
  for (int i = 0; i < 4; i++) {
    int c = lane + i*32;
    float o = (v[i]-m)*r*gg[c] + bbp[c];
    bf16 hh, llv; split2(o, hh, llv);
    kh[base + c] = hh; kl[base + c] = llv;
    vh[base + c] = vp[c];
  }
}

// softmax over PP -> single fp16 probs
__global__ void __launch_bounds__(256) softmax_half_kernel(const float* __restrict__ x,
    fp16* __restrict__ ph) {
  const float* xr = x + (size_t)blockIdx.x * PP;
  float v[4];
  float mx = -3.4e38f;
#pragma unroll
  for (int i = 0; i < 4; i++) { v[i] = xr[threadIdx.x + i*256]; mx = fmaxf(mx, v[i]); }
  mx = blockReduceMax(mx);
  float s = 0.f;
#pragma unroll
  for (int i = 0; i < 4; i++) { v[i] = expf(v[i] - mx); s += v[i]; }
  float tot = blockReduceSum(s);
  float inv = 1.f / tot;
  size_t base = (size_t)blockIdx.x * PP;
#pragma unroll
  for (int i = 0; i < 4; i++) {
    int c = threadIdx.x + i*256;
    ph[base + c] = __float2half_rn(v[i] * inv);
  }
}

// transpose -> single fp16 (weights + v)
__global__ void __launch_bounds__(256) transpose_half_kernel(const float* __restrict__ src,
    fp16* __restrict__ dst, int R, int C, ll sStride, ll dStride) {
  __shared__ float t[32][33];
  int z = blockIdx.z;
  src += (ll)z * sStride;
  dst += (ll)z * dStride;
  int c0 = blockIdx.x * 32, r0 = blockIdx.y * 32;
  int tx = threadIdx.x & 31, ty = threadIdx.x >> 5;
#pragma unroll
  for (int j = ty; j < 32; j += 8)
    t[j][tx] = src[(size_t)(r0+j)*C + c0 + tx];
  __syncthreads();
#pragma unroll
  for (int j = ty; j < 32; j += 8)
    dst[(size_t)(c0+j)*R + r0 + tx] = __float2half_rn(t[tx][j]);
}

// ---------------------------------------------------------------------------
// fp32 SGEMM (encoder only)
// ---------------------------------------------------------------------------
template<bool HASBIAS>
__global__ void __launch_bounds__(256, 2) sgemm_kernel(
    const float* __restrict__ A, const float* __restrict__ B, float* __restrict__ C,
    const float* __restrict__ bias, int K, int kGuard, int lda, int ldb, int ldc)
{
  __shared__ float As[16][128];
  __shared__ float Bs[16][128];
  const int tid = threadIdx.x;
  const int row0 = blockIdx.y * 128;
  const int col0 = blockIdx.x * 128;
  const int tx = tid & 15, ty = tid >> 4;
  const int tm0 = ty*8, tn0 = tx*8;
  float acc[8][8];
#pragma unroll
  for (int i = 0; i < 8; i++)
#pragma unroll
    for (int j = 0; j < 8; j++) acc[i][j] = 0.f;
  for (int k0 = 0; k0 < K; k0 += 16) {
#pragma unroll
    for (int u = 0; u < 2; u++) {
      int f = tid + u*256;
      int r = f >> 2, c4 = (f & 3) << 2;
      float4 va = *reinterpret_cast<const float4*>(A + (size_t)(row0 + r)*lda + (k0 + c4));
      As[c4+0][r] = va.x; As[c4+1][r] = va.y; As[c4+2][r] = va.z; As[c4+3][r] = va.w;
    }
#pragma unroll
    for (int u = 0; u < 2; u++) {
      int f = tid + u*256;
      int kk = f >> 5, n4 = (f & 31) << 2;
      float4 vb = make_float4(0.f, 0.f, 0.f, 0.f);
      if (k0 + kk < kGuard)
        vb = *reinterpret_cast<const float4*>(B + (size_t)(k0 + kk)*ldb + (col0 + n4));
      *reinterpret_cast<float4*>(&Bs[kk][n4]) = vb;
    }
    __syncthreads();
#pragma unroll
    for (int kk = 0; kk < 16; kk++) {
      float4 a0 = *reinterpret_cast<const float4*>(&As[kk][tm0]);
      float4 a1 = *reinterpret_cast<const float4*>(&As[kk][tm0+4]);
      float4 b0 = *reinterpret_cast<const float4*>(&Bs[kk][tn0]);
      float4 b1 = *reinterpret_cast<const float4*>(&Bs[kk][tn0+4]);
      float ra[8] = {a0.x,a0.y,a0.z,a0.w,a1.x,a1.y,a1.z,a1.w};
      float rb[8] = {b0.x,b0.y,b0.z,b0.w,b1.x,b1.y,b1.z,b1.w};
#pragma unroll
      for (int i = 0; i < 8; i++)
#pragma unroll
        for (int j = 0; j < 8; j++)
          acc[i][j] = fmaf(ra[i], rb[j], acc[i][j]);
    }
    __syncthreads();
  }
#pragma unroll
  for (int i = 0; i < 8; i++) {
    float* crow = C + (size_t)(row0 + tm0 + i)*ldc + (col0 + tn0);
#pragma unroll
    for (int j = 0; j < 8; j += 4) {
      float4 v;
      v.x = acc[i][j+0]; v.y = acc[i][j+1]; v.z = acc[i][j+2]; v.w = acc[i][j+3];
      if (HASBIAS) {
        float4 bbv = *reinterpret_cast<const float4*>(bias + col0 + tn0 + j);
        v.x += bbv.x; v.y += bbv.y; v.z += bbv.z; v.w += bbv.w;
      }
      *reinterpret_cast<float4*>(crow + j) = v;
    }
  }
}

#define LDSROW 40
#define TILE_ELEMS (128*LDSROW)

// ---------------------------------------------------------------------------
// bf16x3 GEMM (QK only): C = alpha*(Ah+Al)@(Bh+Bl)^T -> fp32
// ---------------------------------------------------------------------------
#define STAGE_B3 (4*TILE_ELEMS)
#define B3_SMEM_BYTES (2*STAGE_B3*2)

__global__ void __launch_bounds__(256, 2) mma_bf3_kernel(
    const bf16* __restrict__ Ah, const bf16* __restrict__ Al,
    const bf16* __restrict__ Bh, const bf16* __restrict__ Bl,
    float* __restrict__ C,
    int K, int lda, int ldb, int ldc,
    ll aSO, ll bSO, ll cSO, float alpha)
{
  extern __shared__ bf16 smbuf[];
  int bz = blockIdx.z;
  ll aoff = (ll)bz*aSO;
  ll boff = (ll)bz*bSO;
  ll coff = (ll)bz*cSO;
  Ah += aoff; Al += aoff; Bh += boff; Bl += boff;

  const int tid = threadIdx.x;
  const int row0 = blockIdx.y * 128;
  const int col0 = blockIdx.x * 128;
  const int wid = tid >> 5, lane = tid & 31;
  const int wm = (wid & 3) * 32;
  const int wn = (wid >> 2) * 64;

  float acc[2][8][4];
#pragma unroll
  for (int mt = 0; mt < 2; mt++)
#pragma unroll
    for (int nt = 0; nt < 8; nt++)
#pragma unroll
      for (int q = 0; q < 4; q++) acc[mt][nt][q] = 0.f;

  {
    bf16* base = smbuf;
#pragma unroll
    for (int i = 0; i < 2; i++) {
      int c = tid + i*256;
      int r = c >> 2, kc = (c & 3) << 3;
      cpa16(s2u(base + 0*TILE_ELEMS + r*LDSROW + kc), Ah + (size_t)(row0+r)*lda + kc);
      cpa16(s2u(base + 1*TILE_ELEMS + r*LDSROW + kc), Al + (size_t)(row0+r)*lda + kc);
      cpa16(s2u(base + 2*TILE_ELEMS + r*LDSROW + kc), Bh + (size_t)(col0+r)*ldb + kc);
      cpa16(s2u(base + 3*TILE_ELEMS + r*LDSROW + kc), Bl + (size_t)(col0+r)*ldb + kc);
    }
    asm volatile("cp.async.commit_group;\n");
  }

  int s = 0;
  for (int k0 = 0; k0 < K; k0 += 32, s ^= 1) {
    asm volatile("cp.async.wait_group 0;\n");
    __syncthreads();
    if (k0 + 32 < K) {
      bf16* base = smbuf + (s^1)*STAGE_B3;
      int kn = k0 + 32;
#pragma unroll
      for (int i = 0; i < 2; i++) {
        int c = tid + i*256;
        int r = c >> 2, kc = (c & 3) << 3;
        cpa16(s2u(base + 0*TILE_ELEMS + r*LDSROW + kc), Ah + (size_t)(row0+r)*lda + kn + kc);
        cpa16(s2u(base + 1*TILE_ELEMS + r*LDSROW + kc), Al + (size_t)(row0+r)*lda + kn + kc);
        cpa16(s2u(base + 2*TILE_ELEMS + r*LDSROW + kc), Bh + (size_t)(col0+r)*ldb + kn + kc);
        cpa16(s2u(base + 3*TILE_ELEMS + r*LDSROW + kc), Bl + (size_t)(col0+r)*ldb + kn + kc);
      }
      asm volatile("cp.async.commit_group;\n");
    }

    bf16* sAh = smbuf + s*STAGE_B3;
    bf16* sAl = sAh + TILE_ELEMS;
    bf16* sBh = sAh + 2*TILE_ELEMS;
    bf16* sBl = sAh + 3*TILE_ELEMS;
    int arow = lane & 15;
    int khalf = (lane >> 4) << 3;

#pragma unroll
    for (int kk = 0; kk < 2; kk++) {
      int kof = kk*16 + khalf;
      unsigned ahf[2][4], alf[2][4], bfr[8][2];
#pragma unroll
      for (int mt = 0; mt < 2; mt++) {
        ldsm4(ahf[mt], s2u(sAh + (wm + mt*16 + arow)*LDSROW + kof));
        ldsm4(alf[mt], s2u(sAl + (wm + mt*16 + arow)*LDSROW + kof));
      }
#pragma unroll
      for (int np = 0; np < 4; np++) {
        unsigned t[4];
        ldsm4(t, s2u(sBh + (wn + np*16 + arow)*LDSROW + kof));
        bfr[2*np][0] = t[0]; bfr[2*np][1] = t[2];
        bfr[2*np+1][0] = t[1]; bfr[2*np+1][1] = t[3];
      }
#pragma unroll
      for (int mt = 0; mt < 2; mt++)
#pragma unroll
        for (int nt = 0; nt < 8; nt++) {
          mma_bf(acc[mt][nt], ahf[mt], bfr[nt]);
          mma_bf(acc[mt][nt], alf[mt], bfr[nt]);
        }
#pragma unroll
      for (int np = 0; np < 4; np++) {
        unsigned t[4];
        ldsm4(t, s2u(sBl + (wn + np*16 + arow)*LDSROW + kof));
        bfr[2*np][0] = t[0]; bfr[2*np][1] = t[2];
        bfr[2*np+1][0] = t[1]; bfr[2*np+1][1] = t[3];
      }
#pragma unroll
      for (int mt = 0; mt < 2; mt++)
#pragma unroll
        for (int nt = 0; nt < 8; nt++)
          mma_bf(acc[mt][nt], ahf[mt], bfr[nt]);
    }
  }

  int rb = row0 + wm + (lane >> 2);
  int cb = col0 + wn + (lane & 3)*2;
#pragma unroll
  for (int mt = 0; mt < 2; mt++) {
#pragma unroll
    for (int nt = 0; nt < 8; nt++) {
#pragma unroll
      for (int h2 = 0; h2 < 2; h2++) {
        int r = rb + mt*16 + h2*8;
        int cc = cb + nt*8;
        float2 o;
        o.x = alpha * acc[mt][nt][h2*2+0];
        o.y = alpha * acc[mt][nt][h2*2+1];
        *reinterpret_cast<float2*>(C + coff + (ll)r*ldc + cc) = o;
      }
    }
  }
}

// ---------------------------------------------------------------------------
// fp16 single-product GEMM: C = act(alpha*A@B^T + bias)
// A: [M][K] fp16; B: [N][K] fp16. fp32 accumulate.
// OUTMODE: 0=store fp32; 1=accumulate fp32; 2=store fp16;
//          3=accumulate fp32 AND store fp16 of the sum.
// ---------------------------------------------------------------------------
#define STAGE_H1 (2*TILE_ELEMS)
#define H1_SMEM_BYTES (2*STAGE_H1*2)

template<bool ACT, bool HASBIAS, int OUTMODE>
__global__ void __launch_bounds__(256, 2) mma_h1_kernel(
    const fp16* __restrict__ A, const fp16* __restrict__ B,
    float* __restrict__ C, fp16* __restrict__ Ch,
    const float* __restrict__ bias,
    int K, int lda, int ldb, int ldc, int inner,
    ll aSO, ll aSI, ll bSO, ll bSI, ll cSO, ll cSI, float alpha)
{
  extern __shared__ fp16 smh[];
  int bz = blockIdx.z;
  int bo = bz / inner, bi = bz - bo*inner;
  ll aoff = (ll)bo*aSO + (ll)bi*aSI;
  ll boff = (ll)bo*bSO + (ll)bi*bSI;
  ll coff = (ll)bo*cSO + (ll)bi*cSI;
  A += aoff; B += boff;

  const int tid = threadIdx.x;
  const int row0 = blockIdx.y * 128;
  const int col0 = blockIdx.x * 128;
  const int wid = tid >> 5, lane = tid & 31;
  const int wm = (wid & 3) * 32;
  const int wn = (wid >> 2) * 64;

  float acc[2][8][4];
#pragma unroll
  for (int mt = 0; mt < 2; mt++)
#pragma unroll
    for (int nt = 0; nt < 8; nt++)
#pragma unroll
      for (int q = 0; q < 4; q++) acc[mt][nt][q] = 0.f;

  {
    fp16* base = smh;
#pragma unroll
    for (int i = 0; i < 2; i++) {
      int c = tid + i*256;
      int r = c >> 2, kc = (c & 3) << 3;
      cpa16(s2u(base + 0*TILE_ELEMS + r*LDSROW + kc), A + (size_t)(row0+r)*lda + kc);
      cpa16(s2u(base + 1*TILE_ELEMS + r*LDSROW + kc), B + (size_t)(col0+r)*ldb + kc);
    }
    asm volatile("cp.async.commit_group;\n");
  }

  int s = 0;
  for (int k0 = 0; k0 < K; k0 += 32, s ^= 1) {
    asm volatile("cp.async.wait_group 0;\n");
    __syncthreads();
    if (k0 + 32 < K) {
      fp16* base = smh + (s^1)*STAGE_H1;
      int kn = k0 + 32;
#pragma unroll
      for (int i = 0; i < 2; i++) {
        int c = tid + i*256;
        int r = c >> 2, kc = (c & 3) << 3;
        cpa16(s2u(base + 0*TILE_ELEMS + r*LDSROW + kc), A + (size_t)(row0+r)*lda + kn + kc);
        cpa16(s2u(base + 1*TILE_ELEMS + r*LDSROW + kc), B + (size_t)(col0+r)*ldb + kn + kc);
      }
      asm volatile("cp.async.commit_group;\n");
    }

    fp16* sA = smh + s*STAGE_H1;
    fp16* sB = sA + TILE_ELEMS;
    int arow = lane & 15;
    int khalf = (lane >> 4) << 3;

#pragma unroll
    for (int kk = 0; kk < 2; kk++) {
      int kof = kk*16 + khalf;
      unsigned af[2][4], bfr[8][2];
#pragma unroll
      for (int mt = 0; mt < 2; mt++)
        ldsm4(af[mt], s2u(sA + (wm + mt*16 + arow)*LDSROW + kof));
#pragma unroll
      for (int np = 0; np < 4; np++) {
        unsigned t[4];
        ldsm4(t, s2u(sB + (wn + np*16 + arow)*LDSROW + kof));
        bfr[2*np][0] = t[0]; bfr[2*np][1] = t[2];
        bfr[2*np+1][0] = t[1]; bfr[2*np+1][1] = t[3];
      }
#pragma unroll
      for (int mt = 0; mt < 2; mt++)
#pragma unroll
        for (int nt = 0; nt < 8; nt++)
          mma_hf(acc[mt][nt], af[mt], bfr[nt]);
    }
  }

  int rb = row0 + wm + (lane >> 2);
  int cb = col0 + wn + (lane & 3)*2;
#pragma unroll
  for (int mt = 0; mt < 2; mt++) {
#pragma unroll
    for (int nt = 0; nt < 8; nt++) {
#pragma unroll
      for (int h2 = 0; h2 < 2; h2++) {
        int r = rb + mt*16 + h2*8;
        int cc = cb + nt*8;
        float v0 = alpha * acc[mt][nt][h2*2+0];
        float v1 = alpha * acc[mt][nt][h2*2+1];
        if (HASBIAS) { v0 += bias[cc]; v1 += bias[cc+1]; }
        if (ACT) { v0 = gelu_f(v0); v1 = gelu_f(v1); }
        ll off = coff + (ll)r*ldc + cc;
        if (OUTMODE == 0) {
          float2 o; o.x = v0; o.y = v1;
          *reinterpret_cast<float2*>(C + off) = o;
        } else if (OUTMODE == 1) {
          float2 o = *reinterpret_cast<const float2*>(C + off);
          o.x += v0; o.y += v1;
          *reinterpret_cast<float2*>(C + off) = o;
        } else if (OUTMODE == 2) {
          __half2 hv; hv.x = __float2half_rn(v0); hv.y = __float2half_rn(v1);
          *reinterpret_cast<__half2*>(Ch + off) = hv;
        } else {
          float2 o = *reinterpret_cast<const float2*>(C + off);
          o.x += v0; o.y += v1;
          *reinterpret_cast<float2*>(C + off) = o;
          __half2 hv; hv.x = __float2half_rn(o.x); hv.y = __float2half_rn(o.y);
          *reinterpret_cast<__half2*>(Ch + off) = hv;
        }
      }
    }
  }
}

// ---------------------------------------------------------------------------
// Head second GEMM (reads single fp16 hidden)
// ---------------------------------------------------------------------------
__global__ void __launch_bounds__(256) head2_kernel(const fp16* __restrict__ hb,
    const float* __restrict__ W2, const float* __restrict__ b2,
    float* __restrict__ out) {
  int idx = blockIdx.x;
  int b = idx / PP, t = idx - b*PP;
  const fp16* hh = hb + (size_t)idx * NHID;
  float acc[NOUTD];
#pragma unroll
  for (int o = 0; o < NOUTD; o++) acc[o] = 0.f;
  for (int k = threadIdx.x; k < NHID; k += 256) {
    float v = __half2float(hh[k]);
    const float* w = W2 + (size_t)k * (NOUTD + 1);
#pragma unroll
    for (int o = 0; o < NOUTD; o++) acc[o] += v * w[o];
  }
  __shared__ float smr[8][NOUTD];
  int lane = threadIdx.x & 31, wid = threadIdx.x >> 5;
#pragma unroll
  for (int o = 0; o < NOUTD; o++) acc[o] = warpSum(acc[o]);
  if (lane == 0) {
#pragma unroll
    for (int o = 0; o < NOUTD; o++) smr[wid][o] = acc[o];
  }
  __syncthreads();
  if (threadIdx.x < NOUTD) {
    float sv = 0.f;
#pragma unroll
    for (int w = 0; w < 8; w++) sv += smr[w][threadIdx.x];
    out[((size_t)t*BB + b)*NOUTD + threadIdx.x] = sv + b2[threadIdx.x];
  }
}

// ---------------------------------------------------------------------------
// Orchestration
// ---------------------------------------------------------------------------
typedef void (*h1_fn)(const fp16*, const fp16*,
                      float*, fp16*, const float*,
                      int, int, int, int, int, ll, ll, ll, ll, ll, ll, float);

extern "C" void kernel_launch(void* const* d_in, const int* in_sizes, int n_in,
                              void* d_out, int out_size) {
  (void)in_sizes; (void)n_in; (void)out_size;
  const float* x_src = (const float*)d_in[0];
  const float* y_src = (const float*)d_in[1];
  const float* enc_W = (const float*)d_in[2];
  const float* enc_b = (const float*)d_in[3];
  const float* yenc_W = (const float*)d_in[4];
  const float* yenc_b = (const float*)d_in[5];
  const float* Wq    = (const float*)d_in[6];
  const float* Wkv   = (const float*)d_in[7];
  const float* Wout  = (const float*)d_in[8];
  const float* an_g  = (const float*)d_in[9];
  const float* an_b  = (const float*)d_in[10];
  const float* qn_g  = (const float*)d_in[11];
  const float* qn_b  = (const float*)d_in[12];
  const float* kn_g  = (const float*)d_in[13];
  const float* kn_b  = (const float*)d_in[14];
  const float* fn_g  = (const float*)d_in[15];
  const float* fn_b  = (const float*)d_in[16];
  const float* ffW1  = (const float*)d_in[17];
  const float* ffb1  = (const float*)d_in[18];
  const float* ffW2  = (const float*)d_in[19];
  const float* ffb2  = (const float*)d_in[20];
  const float* hW1   = (const float*)d_in[21];
  const float* hb1   = (const float*)d_in[22];
  const float* hW2   = (const float*)d_in[23];
  const float* hb2   = (const float*)d_in[24];
  float* out = (float*)d_out;

  {
    cudaFuncSetAttribute(mma_bf3_kernel, cudaFuncAttributeMaxDynamicSharedMemorySize, B3_SMEM_BYTES);
    h1_fn g;
    g = mma_h1_kernel<false,false,0>;
    cudaFuncSetAttribute(g, cudaFuncAttributeMaxDynamicSharedMemorySize, H1_SMEM_BYTES);
    g = mma_h1_kernel<false,false,1>;
    cudaFuncSetAttribute(g, cudaFuncAttributeMaxDynamicSharedMemorySize, H1_SMEM_BYTES);
    g = mma_h1_kernel<false,false,2>;
    cudaFuncSetAttribute(g, cudaFuncAttributeMaxDynamicSharedMemorySize, H1_SMEM_BYTES);
    g = mma_h1_kernel<true,true,2>;
    cudaFuncSetAttribute(g, cudaFuncAttributeMaxDynamicSharedMemorySize, H1_SMEM_BYTES);
    g = mma_h1_kernel<false,true,1>;
    cudaFuncSetAttribute(g, cudaFuncAttributeMaxDynamicSharedMemorySize, H1_SMEM_BYTES);
    g = mma_h1_kernel<false,true,3>;
    cudaFuncSetAttribute(g, cudaFuncAttributeMaxDynamicSharedMemorySize, H1_SMEM_BYTES);
  }

  float *p_xn, *p_src, *p_tmp, *p_vh, *p_logits;
  cudaGetSymbolAddress((void**)&p_xn, g_xn);
  cudaGetSymbolAddress((void**)&p_src, g_src);
  cudaGetSymbolAddress((void**)&p_tmp, g_tmp);
  cudaGetSymbolAddress((void**)&p_vh, g_vh);
  cudaGetSymbolAddress((void**)&p_logits, g_logits);
  fp16 *p_ah, *p_ffh, *p_ph, *p_vth;
  cudaGetSymbolAddress((void**)&p_ah, g_ah);
  cudaGetSymbolAddress((void**)&p_ffh, g_ffh);
  cudaGetSymbolAddress((void**)&p_ph, g_ph);
  cudaGetSymbolAddress((void**)&p_vth, g_vth);
  bf16 *p_qhh, *p_qhl, *p_khh, *p_khl;
  cudaGetSymbolAddress((void**)&p_qhh, g_qhh);
  cudaGetSymbolAddress((void**)&p_qhl, g_qhl);
  cudaGetSymbolAddress((void**)&p_khh, g_khh);
  cudaGetSymbolAddress((void**)&p_khl, g_khl);
  fp16 *pWq, *pWkv, *pWo, *pW1, *pW2, *pHW1;
  cudaGetSymbolAddress((void**)&pWq, g_WqT);
  cudaGetSymbolAddress((void**)&pWkv, g_WkvT);
  cudaGetSymbolAddress((void**)&pWo, g_WoT);
  cudaGetSymbolAddress((void**)&pW1, g_W1T);
  cudaGetSymbolAddress((void**)&pW2, g_W2T);
  cudaGetSymbolAddress((void**)&pHW1, g_hW1T);

  const float qk_scale = 0.08838834764831845f;

  // --- weight transpose -> fp16 ---
  transpose_half_kernel<<<dim3(DD/32, DD/32, NLAYERS), 256>>>(Wq, pWq, DD, DD, (ll)DD*DD, (ll)DD*DD);
  transpose_half_kernel<<<dim3(2*DD/32, DD/32, NLAYERS), 256>>>(Wkv, pWkv, DD, 2*DD, (ll)DD*2*DD, (ll)DD*2*DD);
  transpose_half_kernel<<<dim3(DD/32, DD/32, NLAYERS), 256>>>(Wout, pWo, DD, DD, (ll)DD*DD, (ll)DD*DD);
  transpose_half_kernel<<<dim3(NHID/32, DD/32, NLAYERS), 256>>>(ffW1, pW1, DD, NHID, (ll)DD*NHID, (ll)DD*NHID);
  transpose_half_kernel<<<dim3(DD/32, NHID/32, NLAYERS), 256>>>(ffW2, pW2, NHID, DD, (ll)NHID*DD, (ll)NHID*DD);
  transpose_half_kernel<<<dim3(NHID/32, DD/32, 1), 256>>>(hW1, pHW1, DD, NHID, 0, 0);

  // --- preprocessing + encoder ---
  colstats_kernel<<<BB*NFEAT, 256>>>(x_src, 0);
  colstats_kernel<<<BB*NFEAT, 256>>>(x_src, 1);
  colstats_kernel<<<BB*NFEAT, 256>>>(x_src, 2);
  norm_write_kernel<<<(LB*KPAD + 255)/256, 256>>>(x_src);
  sgemm_kernel<true><<<dim3(DD/128, LB/128, 1), 256>>>(
      p_xn, enc_W, p_tmp, enc_b, KPAD, NFEAT, KPAD, DD, DD);
  encode_finish_kernel<<<LB, 256>>>(p_tmp, y_src, yenc_W, yenc_b);

  for (int i = 0; i < NLAYERS; i++) {
    // --- attention ---
    ln_half_kernel<<<LB, 256>>>(p_src, an_g + i*DD, an_b + i*DD, p_ah);
    // q = h @ Wq (fp16)
    mma_h1_kernel<false,false,0><<<dim3(8, 64, 1), 256, H1_SMEM_BYTES>>>(
        p_ah, pWq + (size_t)i*DD*DD, p_tmp, nullptr, nullptr,
        DD, DD, DD, DD, 1, 0,0,0,0,0,0, 1.f);
    qln_split_kernel<<<LB, 256>>>(p_tmp, qn_g + i*HDIM, qn_b + i*HDIM, p_qhh, p_qhl);
    // kv = h[:, :P] @ Wkv (fp16, batched over b)
    mma_h1_kernel<false,false,0><<<dim3(16, 8, BB), 256, H1_SMEM_BYTES>>>(
        p_ah, pWkv + (size_t)i*DD*2*DD, p_tmp, nullptr, nullptr,
        DD, DD, DD, 2*DD, 1,
        (ll)LL*DD, 0, 0, 0, (ll)PP*2*DD, 0, 1.f);
    klnv_split_kernel<<<BB*PP, 256>>>(p_tmp, kn_g + i*HDIM, kn_b + i*HDIM, p_khh, p_khl, p_vh);
    // vT per (b,h): [P][HD] -> [HD][P] fp16
    transpose_half_kernel<<<dim3(HDIM/32, PP/32, BB*HH), 256>>>(
        p_vh, p_vth, PP, HDIM, (ll)PP*HDIM, (ll)HDIM*PP);
    // logits = scale * q @ k^T (bf16x3)
    mma_bf3_kernel<<<dim3(8, 16, BB*HH), 256, B3_SMEM_BYTES>>>(
        p_qhh, p_qhl, p_khh, p_khl, p_logits,
        HDIM, HDIM, HDIM, PP,
        (ll)LL*HDIM, (ll)PP*HDIM, (ll)LL*PP, qk_scale);
    softmax_half_kernel<<<BB*HH*LL, 256>>>(p_logits, p_ph);
    // attn = probs @ vT^T (fp16 single) -> fp16 (B,L,H,HD)
    mma_h1_kernel<false,false,2><<<dim3(1, 16, BB*HH), 256, H1_SMEM_BYTES>>>(
        p_ph, p_vth, nullptr, p_ah, nullptr,
        PP, PP, PP, DD, HH,
        (ll)HH*LL*PP, (ll)LL*PP,
        (ll)HH*HDIM*PP, (ll)HDIM*PP,
        (ll)LL*DD, (ll)HDIM, 1.f);
    // src += attn @ Wout (fp16)
    mma_h1_kernel<false,false,1><<<dim3(8, 64, 1), 256, H1_SMEM_BYTES>>>(
        p_ah, pWo + (size_t)i*DD*DD, p_src, nullptr, nullptr,
        DD, DD, DD, DD, 1, 0,0,0,0,0,0, 1.f);
    // --- FFN ---
    ln_half_kernel<<<LB, 256>>>(p_src, fn_g + i*DD, fn_b + i*DD, p_ah);
    mma_h1_kernel<true,true,2><<<dim3(NHID/128, 64, 1), 256, H1_SMEM_BYTES>>>(
        p_ah, pW1 + (size_t)i*NHID*DD, nullptr, p_ffh, ffb1 + (size_t)i*NHID,
        DD, DD, DD, NHID, 1, 0,0,0,0,0,0, 1.f);
    if (i < NLAYERS - 1) {
      mma_h1_kernel<false,true,1><<<dim3(8, 64, 1), 256, H1_SMEM_BYTES>>>(
          p_ffh, pW2 + (size_t)i*DD*NHID, p_src, nullptr, ffb2 + (size_t)i*DD,
          NHID, NHID, NHID, DD, 1, 0,0,0,0,0,0, 1.f);
    } else {
      // last layer: residual accumulate AND emit fp16 for the head
      mma_h1_kernel<false,true,3><<<dim3(8, 64, 1), 256, H1_SMEM_BYTES>>>(
          p_ffh, pW2 + (size_t)i*DD*NHID, p_src, p_ah, ffb2 + (size_t)i*DD,
          NHID, NHID, NHID, DD, 1, 0,0,0,0,0,0, 1.f);
    }
  }

  // --- head (p_ah holds fp16 src from OUTMODE 3) ---
  mma_h1_kernel<true,true,2><<<dim3(NHID/128, PP/128, BB), 256, H1_SMEM_BYTES>>>(
      p_ah + (size_t)PP*DD, pHW1, nullptr, p_ffh, hb1,
      DD, DD, DD, NHID, 1,
      (ll)LL*DD, 0, 0, 0, (ll)PP*NHID, 0, 1.f);
  head2_kernel<<<BB*PP, 256>>>(p_ffh, hW2, hb2, out);
}

// round 12
// speedup vs baseline: 2.3395x; 1.0713x over previous
#include <cuda_runtime.h>
#include <cuda_bf16.h>
#include <cuda_fp16.h>
#include <cstdint>
#include <cstddef>
#include <math.h>

// ---------------------------------------------------------------------------
// Problem constants
// ---------------------------------------------------------------------------
#define BB     4
#define LL     2048
#define PP     1024
#define NFEAT  100
#define DD     1024
#define HH     8
#define HDIM   128
#define NHID   4096
#define NLAYERS 3
#define NOUTD  10
#define LB     (LL*BB)
#define KPAD   112

typedef __nv_bfloat16 bf16;
typedef __half fp16;
typedef long long ll;

// ---------------------------------------------------------------------------
// Scratch (device globals)
// ---------------------------------------------------------------------------
__device__ float g_m1[BB*NFEAT], g_s1[BB*NFEAT];
__device__ float g_m2[BB*NFEAT], g_s2[BB*NFEAT];
__device__ float g_m3[BB*NFEAT], g_s3[BB*NFEAT];
__device__ __align__(256) float g_xn[(size_t)LB*KPAD];
__device__ __align__(256) float g_src[(size_t)LB*DD];
__device__ __align__(256) float g_tmp[(size_t)LB*DD];
__device__ __align__(256) float g_vh [(size_t)BB*HH*PP*HDIM];

// fp16 single activations
__device__ __align__(256) fp16 g_ah[(size_t)LB*DD];
__device__ __align__(256) fp16 g_ffh[(size_t)LB*NHID];
__device__ __align__(256) fp16 g_vth[(size_t)BB*HH*HDIM*PP]; // vT fp16

// bf16 split QK operands
__device__ __align__(256) bf16 g_qhh[(size_t)BB*HH*LL*HDIM];
__device__ __align__(256) bf16 g_qhl[(size_t)BB*HH*LL*HDIM];
__device__ __align__(256) bf16 g_khh[(size_t)BB*HH*PP*HDIM];
__device__ __align__(256) bf16 g_khl[(size_t)BB*HH*PP*HDIM];

// fp16 transposed weights
__device__ __align__(256) fp16 g_WqT [(size_t)NLAYERS*DD*DD];
__device__ __align__(256) fp16 g_WkvT[(size_t)NLAYERS*2*DD*DD];
__device__ __align__(256) fp16 g_WoT [(size_t)NLAYERS*DD*DD];
__device__ __align__(256) fp16 g_W1T [(size_t)NLAYERS*NHID*DD];
__device__ __align__(256) fp16 g_W2T [(size_t)NLAYERS*DD*NHID];
__device__ __align__(256) fp16 g_hW1T[(size_t)NHID*DD];

// ---------------------------------------------------------------------------
// Helpers
// ---------------------------------------------------------------------------
__device__ __forceinline__ float warpSum(float v) {
#pragma unroll
  for (int o = 16; o > 0; o >>= 1) v += __shfl_xor_sync(0xffffffffu, v, o);
  return v;
}

__device__ __forceinline__ float blockReduceSum(float v) {
  __shared__ float sh[32];
  int lane = threadIdx.x & 31, wid = threadIdx.x >> 5;
  v = warpSum(v);
  if (lane == 0) sh[wid] = v;
  __syncthreads();
  int nw = (blockDim.x + 31) >> 5;
  v = (threadIdx.x < nw) ? sh[threadIdx.x] : 0.f;
  if (wid == 0) { v = warpSum(v); if (lane == 0) sh[0] = v; }
  __syncthreads();
  float r = sh[0];
  __syncthreads();
  return r;
}

__device__ __forceinline__ float gelu_f(float x) {
  return 0.5f * x * (1.0f + erff(x * 0.7071067811865475f));
}

__device__ __forceinline__ void split2(float v, bf16& h, bf16& l) {
  h = __float2bfloat16_rn(v);
  l = __float2bfloat16_rn(v - __bfloat162float(h));
}

// pack two floats into one 32-bit word of two fp16 (low = a, high = b)
__device__ __forceinline__ unsigned packh2(float a, float b) {
  __half2 h = __floats2half2_rn(a, b);
  return *reinterpret_cast<unsigned*>(&h);
}

// fast exp on the FMA pipe (no MUFU). rel err ~2e-6 on the needed range (x<=0).
__device__ __forceinline__ float fexp(float x) {
  float y = fmaxf(x * 1.4426950408889634f, -100.f);
  float t = y + 12582912.f;
  float i = t - 12582912.f;
  float u = (y - i) * 0.6931471805599453f;
  float p = 0.008333333f;
  p = fmaf(p, u, 0.041666667f);
  p = fmaf(p, u, 0.166666667f);
  p = fmaf(p, u, 0.5f);
  p = fmaf(p, u, 1.0f);
  p = fmaf(p, u, 1.0f);
  int ei = (int)i;
  return p * __uint_as_float((unsigned)((ei + 127) << 23));
}

__device__ __forceinline__ unsigned s2u(const void* p) {
  return (unsigned)__cvta_generic_to_shared(p);
}

__device__ __forceinline__ void cpa16(unsigned s, const void* g) {
  asm volatile("cp.async.cg.shared.global [%0], [%1], 16;\n" :: "r"(s), "l"(g));
}

__device__ __forceinline__ void ldsm4(unsigned* r, unsigned addr) {
  asm volatile("ldmatrix.sync.aligned.m8n8.x4.shared.b16 {%0,%1,%2,%3}, [%4];\n"
    : "=r"(r[0]), "=r"(r[1]), "=r"(r[2]), "=r"(r[3]) : "r"(addr));
}

__device__ __forceinline__ void mma_bf(float* c, const unsigned* a, const unsigned* b) {
  asm volatile("mma.sync.aligned.m16n8k16.row.col.f32.bf16.bf16.f32 "
    "{%0,%1,%2,%3}, {%4,%5,%6,%7}, {%8,%9}, {%0,%1,%2,%3};\n"
    : "+f"(c[0]), "+f"(c[1]), "+f"(c[2]), "+f"(c[3])
    : "r"(a[0]), "r"(a[1]), "r"(a[2]), "r"(a[3]), "r"(b[0]), "r"(b[1]));
}

__device__ __forceinline__ void mma_hf(float* c, const unsigned* a, const unsigned* b) {
  asm volatile("mma.sync.aligned.m16n8k16.row.col.f32.f16.f16.f32 "
    "{%0,%1,%2,%3}, {%4,%5,%6,%7}, {%8,%9}, {%0,%1,%2,%3};\n"
    : "+f"(c[0]), "+f"(c[1]), "+f"(c[2]), "+f"(c[3])
    : "r"(a[0]), "r"(a[1]), "r"(a[2]), "r"(a[3]), "r"(b[0]), "r"(b[1]));
}

// ---------------------------------------------------------------------------
// Preprocessing / LN / transpose kernels
// ---------------------------------------------------------------------------
__global__ void __launch_bounds__(256) colstats_kernel(const float* __restrict__ xsrc, int mode) {
  int bf = blockIdx.x;
  int b = bf / NFEAT, f = bf - b*NFEAT;
  const float* base = xsrc + (size_t)b*LL*NFEAT + f;
  float m1 = g_m1[bf], s1 = g_s1[bf];
  float m2 = g_m2[bf], s2 = g_s2[bf];
  float lo1 = m1 - 4.f*s1, hi1 = m1 + 4.f*s1;
  float inv2 = 1.f / (s2 + 1e-6f);
  float sum = 0.f, sq = 0.f;
  for (int t = threadIdx.x; t < PP; t += blockDim.x) {
    float v = base[(size_t)t*NFEAT];
    if (mode >= 1) v = fminf(fmaxf(v, lo1), hi1);
    if (mode >= 2) v = (v - m2) * inv2;
    sum += v; sq += v*v;
  }
  sum = blockReduceSum(sum);
  sq  = blockReduceSum(sq);
  if (threadIdx.x == 0) {
    float m = sum * (1.f/PP);
    float var = sq * (1.f/PP) - m*m;
    float s = sqrtf(fmaxf(var, 0.f));
    if (mode == 0)      { g_m1[bf] = m; g_s1[bf] = s; }
    else if (mode == 1) { g_m2[bf] = m; g_s2[bf] = s; }
    else                { g_m3[bf] = m; g_s3[bf] = s; }
  }
}

__global__ void __launch_bounds__(256) norm_write_kernel(const float* __restrict__ xsrc) {
  int idx = blockIdx.x * blockDim.x + threadIdx.x;
  if (idx >= LB*KPAD) return;
  int row = idx / KPAD, f = idx - row*KPAD;
  int l = row / BB, b = row - l*BB;
  float out = 0.f;
  if (f < NFEAT) {
    int bf = b*NFEAT + f;
    float v = xsrc[(size_t)b*LL*NFEAT + (size_t)l*NFEAT + f];
    float m1 = g_m1[bf], s1 = g_s1[bf];
    v = fminf(fmaxf(v, m1 - 4.f*s1), m1 + 4.f*s1);
    v = (v - g_m2[bf]) / (g_s2[bf] + 1e-6f);
    float m3 = g_m3[bf], s3 = g_s3[bf];
    v = fminf(fmaxf(v, m3 - 4.f*s3), m3 + 4.f*s3);
    if (!isfinite(v)) v = 0.f;
    out = v;
  }
  g_xn[idx] = out;
}

__global__ void __launch_bounds__(256) encode_finish_kernel(const float* __restrict__ xeD,
    const float* __restrict__ ysrc, const float* __restrict__ yencW, const float* __restrict__ yencb) {
  int row = blockIdx.x;
  int l = row / BB, b = row - l*BB;
  const float* xr = xeD + (size_t)row * DD;
  float v[4]; float sq = 0.f;
#pragma unroll
  for (int i = 0; i < 4; i++) { v[i] = xr[threadIdx.x + i*256]; sq += v[i]*v[i]; }
  float ms = blockReduceSum(sq) * (1.f/DD);
  float inv = 1.f / sqrtf(ms);
  bool addy = (l < PP);
  float yv = addy ? ysrc[(size_t)b*PP + l] : 0.f;
  float* dst = g_src + ((size_t)b*LL + l) * DD;
#pragma unroll
  for (int i = 0; i < 4; i++) {
    int c = threadIdx.x + i*256;
    float o = v[i] * inv;
    if (addy) o += yv * yencW[c] + yencb[c];
    dst[c] = o;
  }
}

__global__ void __launch_bounds__(256) ln_half_kernel(const float* __restrict__ x,
    const float* __restrict__ gg, const float* __restrict__ bbp,
    fp16* __restrict__ oh) {
  int row = blockIdx.x;
  const float* xr = x + (size_t)row * DD;
  float v[4]; float s = 0.f;
#pragma unroll
  for (int i = 0; i < 4; i++) { v[i] = xr[threadIdx.x + i*256]; s += v[i]; }
  float m = blockReduceSum(s) * (1.f/DD);
  float d = 0.f;
#pragma unroll
  for (int i = 0; i < 4; i++) { float t = v[i]-m; d += t*t; }
  float var = blockReduceSum(d) * (1.f/DD);
  float r = rsqrtf(var + 1e-5f);
#pragma unroll
  for (int i = 0; i < 4; i++) {
    int c = threadIdx.x + i*256;
    float o = (v[i]-m)*r*gg[c] + bbp[c];
    oh[(size_t)row*DD + c] = __float2half_rn(o);
  }
}

__global__ void __launch_bounds__(256) qln_split_kernel(const float* __restrict__ qraw,
    const float* __restrict__ gg, const float* __restrict__ bbp,
    bf16* __restrict__ qh, bf16* __restrict__ ql) {
  int row = blockIdx.x;
  int h = threadIdx.x >> 5, lane = threadIdx.x & 31;
  int b = row / LL, l = row - b*LL;
  const float* src = qraw + (size_t)row*DD + h*HDIM;
  float v[4]; float s = 0.f;
#pragma unroll
  for (int i = 0; i < 4; i++) { v[i] = src[lane + i*32]; s += v[i]; }
  float m = warpSum(s) * (1.f/HDIM);
  float d = 0.f;
#pragma unroll
  for (int i = 0; i < 4; i++) { float t = v[i]-m; d += t*t; }
  float var = warpSum(d) * (1.f/HDIM);
  float r = rsqrtf(var + 1e-5f);
  size_t base = ((size_t)(b*HH + h)*LL + l) * HDIM;
#pragma unroll
  for (int i = 0; i < 4; i++) {
    int c = lane + i*32;
    float o = (v[i]-m)*r*gg[c] + bbp[c];
    bf16 hh, llv; split2(o, hh, llv);
    qh[base + c] = hh; ql[base + c] = llv;
  }
}

__global__ void __launch_bounds__(256) klnv_split_kernel(const float* __restrict__ kv,
    const float* __restrict__ gg, const float* __restrict__ bbp,
    bf16* __restrict__ kh, bf16* __restrict__ kl, float* __restrict__ vh) {
  int row = blockIdx.x;
  int h = threadIdx.x >> 5, lane = threadIdx.x & 31;
  int b = row / PP, t = row - b*PP;
  const float* kp = kv + (size_t)row*2*DD + h*HDIM;
  const float* vp = kp + DD;
  float v[4]; float s = 0.f;
#pragma unroll
  for (int i = 0; i < 4; i++) { v[i] = kp[lane + i*32]; s += v[i]; }
  float m = warpSum(s) * (1.f/HDIM);
  float d = 0.f;
#pragma unroll
  for (int i = 0; i < 4; i++) { float t2 = v[i]-m; d += t2*t2; }
  float var = warpSum(d) * (1.f/HDIM);
  float r = rsqrtf(var + 1e-5f);
  size_t base = ((size_t)(b*HH + h)*PP + t) * HDIM;
#pragma unroll
  for (int i = 0; i < 4; i++) {
    int c = lane + i*32;
    float o = (v[i]-m)*r*gg[c] + bbp[c];
    bf16 hh, llv; split2(o, hh, llv);
    kh[base + c] = hh; kl[base + c] = llv;
    vh[base + c] = vp[c];
  }
}

__global__ void __launch_bounds__(256) transpose_half_kernel(const float* __restrict__ src,
    fp16* __restrict__ dst, int R, int C, ll sStride, ll dStride) {
  __shared__ float t[32][33];
  int z = blockIdx.z;
  src += (ll)z * sStride;
  dst += (ll)z * dStride;
  int c0 = blockIdx.x * 32, r0 = blockIdx.y * 32;
  int tx = threadIdx.x & 31, ty = threadIdx.x >> 5;
#pragma unroll
  for (int j = ty; j < 32; j += 8)
    t[j][tx] = src[(size_t)(r0+j)*C + c0 + tx];
  __syncthreads();
#pragma unroll
  for (int j = ty; j < 32; j += 8)
    dst[(size_t)(c0+j)*R + r0 + tx] = __float2half_rn(t[tx][j]);
}

// ---------------------------------------------------------------------------
// fp32 SGEMM (encoder only)
// ---------------------------------------------------------------------------
template<bool HASBIAS>
__global__ void __launch_bounds__(256, 2) sgemm_kernel(
    const float* __restrict__ A, const float* __restrict__ B, float* __restrict__ C,
    const float* __restrict__ bias, int K, int kGuard, int lda, int ldb, int ldc)
{
  __shared__ float As[16][128];
  __shared__ float Bs[16][128];
  const int tid = threadIdx.x;
  const int row0 = blockIdx.y * 128;
  const int col0 = blockIdx.x * 128;
  const int tx = tid & 15, ty = tid >> 4;
  const int tm0 = ty*8, tn0 = tx*8;
  float acc[8][8];
#pragma unroll
  for (int i = 0; i < 8; i++)
#pragma unroll
    for (int j = 0; j < 8; j++) acc[i][j] = 0.f;
  for (int k0 = 0; k0 < K; k0 += 16) {
#pragma unroll
    for (int u = 0; u < 2; u++) {
      int f = tid + u*256;
      int r = f >> 2, c4 = (f & 3) << 2;
      float4 va = *reinterpret_cast<const float4*>(A + (size_t)(row0 + r)*lda + (k0 + c4));
      As[c4+0][r] = va.x; As[c4+1][r] = va.y; As[c4+2][r] = va.z; As[c4+3][r] = va.w;
    }
#pragma unroll
    for (int u = 0; u < 2; u++) {
      int f = tid + u*256;
      int kk = f >> 5, n4 = (f & 31) << 2;
      float4 vb = make_float4(0.f, 0.f, 0.f, 0.f);
      if (k0 + kk < kGuard)
        vb = *reinterpret_cast<const float4*>(B + (size_t)(k0 + kk)*ldb + (col0 + n4));
      *reinterpret_cast<float4*>(&Bs[kk][n4]) = vb;
    }
    __syncthreads();
#pragma unroll
    for (int kk = 0; kk < 16; kk++) {
      float4 a0 = *reinterpret_cast<const float4*>(&As[kk][tm0]);
      float4 a1 = *reinterpret_cast<const float4*>(&As[kk][tm0+4]);
      float4 b0 = *reinterpret_cast<const float4*>(&Bs[kk][tn0]);
      float4 b1 = *reinterpret_cast<const float4*>(&Bs[kk][tn0+4]);
      float ra[8] = {a0.x,a0.y,a0.z,a0.w,a1.x,a1.y,a1.z,a1.w};
      float rb[8] = {b0.x,b0.y,b0.z,b0.w,b1.x,b1.y,b1.z,b1.w};
#pragma unroll
      for (int i = 0; i < 8; i++)
#pragma unroll
        for (int j = 0; j < 8; j++)
          acc[i][j] = fmaf(ra[i], rb[j], acc[i][j]);
    }
    __syncthreads();
  }
#pragma unroll
  for (int i = 0; i < 8; i++) {
    float* crow = C + (size_t)(row0 + tm0 + i)*ldc + (col0 + tn0);
#pragma unroll
    for (int j = 0; j < 8; j += 4) {
      float4 v;
      v.x = acc[i][j+0]; v.y = acc[i][j+1]; v.z = acc[i][j+2]; v.w = acc[i][j+3];
      if (HASBIAS) {
        float4 bbv = *reinterpret_cast<const float4*>(bias + col0 + tn0 + j);
        v.x += bbv.x; v.y += bbv.y; v.z += bbv.z; v.w += bbv.w;
      }
      *reinterpret_cast<float4*>(crow + j) = v;
    }
  }
}

#define LDSROW 40
#define TILE_ELEMS (128*LDSROW)

// ---------------------------------------------------------------------------
// Fused flash attention: per (b,h), 128 Q rows per CTA.
// S = scale*(Qh+Ql)@(Kh+Kl)^T (bf16x3), online softmax (poly exp),
// O += P(fp16) @ V (from vT tiles). Writes fp16 attn out in (B,L,D) layout.
// 8 warps, each owns 16 rows x full 128 cols.
// ---------------------------------------------------------------------------
#define FROWS 136
#define FTILE (128*FROWS)
#define FLASH_SMEM (5*FTILE*2)

__global__ void __launch_bounds__(256) flash_attn_kernel(
    const bf16* __restrict__ Qh, const bf16* __restrict__ Ql,
    const bf16* __restrict__ Kh, const bf16* __restrict__ Kl,
    const fp16* __restrict__ Vt, fp16* __restrict__ Oout, float scale)
{
  extern __shared__ char fsm[];
  bf16* sQh = (bf16*)fsm;
  bf16* sQl = sQh + FTILE;
  bf16* sKh = sQl + FTILE;
  bf16* sKl = sKh + FTILE;
  fp16* sVt = (fp16*)(sKl + FTILE);

  const int bh = blockIdx.z;
  const int b = bh >> 3, h = bh & 7;
  const int qrow0 = blockIdx.x * 128;
  const bf16* gQh = Qh + ((size_t)bh*LL + qrow0)*HDIM;
  const bf16* gQl = Ql + ((size_t)bh*LL + qrow0)*HDIM;
  const bf16* gKh = Kh + (size_t)bh*PP*HDIM;
  const bf16* gKl = Kl + (size_t)bh*PP*HDIM;
  const fp16* gVt = Vt + (size_t)bh*HDIM*PP;

  const int tid = threadIdx.x, wid = tid >> 5, lane = tid & 31;
  const int arow = lane & 15;
  const int khalf = (lane >> 4) << 3;

  // load Q tiles (resident)
#pragma unroll
  for (int i = 0; i < 8; i++) {
    int id = tid + (i << 8);
    int r = id >> 4, c = (id & 15) << 3;
    cpa16(s2u(sQh + r*FROWS + c), gQh + (size_t)r*HDIM + c);
    cpa16(s2u(sQl + r*FROWS + c), gQl + (size_t)r*HDIM + c);
  }
  asm volatile("cp.async.commit_group;\n");

  float accO[16][4];
#pragma unroll
  for (int nt = 0; nt < 16; nt++)
#pragma unroll
    for (int q = 0; q < 4; q++) accO[nt][q] = 0.f;
  float m0 = -3.4e38f, m1 = -3.4e38f, l0 = 0.f, l1 = 0.f;

  for (int kt = 0; kt < PP/128; kt++) {
    __syncthreads();   // previous-iteration smem reads done before overwrite
#pragma unroll
    for (int i = 0; i < 8; i++) {
      int id = tid + (i << 8);
      int r = id >> 4, c = (id & 15) << 3;
      cpa16(s2u(sKh + r*FROWS + c), gKh + (size_t)(kt*128 + r)*HDIM + c);
      cpa16(s2u(sKl + r*FROWS + c), gKl + (size_t)(kt*128 + r)*HDIM + c);
      cpa16(s2u(sVt + r*FROWS + c), gVt + (size_t)r*PP + kt*128 + c);
    }
    asm volatile("cp.async.commit_group;\n");
    asm volatile("cp.async.wait_group 0;\n" ::: "memory");
    __syncthreads();

    // --- S = (Qh+Ql)@(Kh+Kl)^T ---
    float accS[16][4];
#pragma unroll
    for (int nt = 0; nt < 16; nt++)
#pragma unroll
      for (int q = 0; q < 4; q++) accS[nt][q] = 0.f;

#pragma unroll
    for (int kk = 0; kk < 8; kk++) {
      int kof = kk*16 + khalf;
      unsigned ah[4], al[4], bfr[16][2];
      ldsm4(ah, s2u(sQh + (wid*16 + arow)*FROWS + kof));
      ldsm4(al, s2u(sQl + (wid*16 + arow)*FROWS + kof));
#pragma unroll
      for (int np = 0; np < 8; np++) {
        unsigned t[4];
        ldsm4(t, s2u(sKh + (np*16 + arow)*FROWS + kof));
        bfr[2*np][0] = t[0]; bfr[2*np][1] = t[2];
        bfr[2*np+1][0] = t[1]; bfr[2*np+1][1] = t[3];
      }
#pragma unroll
      for (int nt = 0; nt < 16; nt++) {
        mma_bf(accS[nt], ah, bfr[nt]);
        mma_bf(accS[nt], al, bfr[nt]);
      }
#pragma unroll
      for (int np = 0; np < 8; np++) {
        unsigned t[4];
        ldsm4(t, s2u(sKl + (np*16 + arow)*FROWS + kof));
        bfr[2*np][0] = t[0]; bfr[2*np][1] = t[2];
        bfr[2*np+1][0] = t[1]; bfr[2*np+1][1] = t[3];
      }
#pragma unroll
      for (int nt = 0; nt < 16; nt++)
        mma_bf(accS[nt], ah, bfr[nt]);
    }

    // --- online softmax ---
    float rmax0 = -3.4e38f, rmax1 = -3.4e38f;
#pragma unroll
    for (int nt = 0; nt < 16; nt++) {
      accS[nt][0] *= scale; accS[nt][1] *= scale;
      accS[nt][2] *= scale; accS[nt][3] *= scale;
      rmax0 = fmaxf(rmax0, fmaxf(accS[nt][0], accS[nt][1]));
      rmax1 = fmaxf(rmax1, fmaxf(accS[nt][2], accS[nt][3]));
    }
    rmax0 = fmaxf(rmax0, __shfl_xor_sync(0xffffffffu, rmax0, 1));
    rmax0 = fmaxf(rmax0, __shfl_xor_sync(0xffffffffu, rmax0, 2));
    rmax1 = fmaxf(rmax1, __shfl_xor_sync(0xffffffffu, rmax1, 1));
    rmax1 = fmaxf(rmax1, __shfl_xor_sync(0xffffffffu, rmax1, 2));
    float mn0 = fmaxf(m0, rmax0), mn1 = fmaxf(m1, rmax1);
    float a0 = fexp(m0 - mn0), a1 = fexp(m1 - mn1);
    float rs0 = 0.f, rs1 = 0.f;
#pragma unroll
    for (int nt = 0; nt < 16; nt++) {
      accS[nt][0] = fexp(accS[nt][0] - mn0);
      accS[nt][1] = fexp(accS[nt][1] - mn0);
      accS[nt][2] = fexp(accS[nt][2] - mn1);
      accS[nt][3] = fexp(accS[nt][3] - mn1);
      rs0 += accS[nt][0] + accS[nt][1];
      rs1 += accS[nt][2] + accS[nt][3];
    }
    rs0 += __shfl_xor_sync(0xffffffffu, rs0, 1);
    rs0 += __shfl_xor_sync(0xffffffffu, rs0, 2);
    rs1 += __shfl_xor_sync(0xffffffffu, rs1, 1);
    rs1 += __shfl_xor_sync(0xffffffffu, rs1, 2);
    l0 = l0*a0 + rs0; l1 = l1*a1 + rs1;
    m0 = mn0; m1 = mn1;
#pragma unroll
    for (int nt = 0; nt < 16; nt++) {
      accO[nt][0] *= a0; accO[nt][1] *= a0;
      accO[nt][2] *= a1; accO[nt][3] *= a1;
    }

    // --- O += P @ V (P from accS, fp16; B from vT tile) ---
#pragma unroll
    for (int kc = 0; kc < 8; kc++) {
      unsigned pa[4];
      pa[0] = packh2(accS[2*kc][0], accS[2*kc][1]);
      pa[1] = packh2(accS[2*kc][2], accS[2*kc][3]);
      pa[2] = packh2(accS[2*kc+1][0], accS[2*kc+1][1]);
      pa[3] = packh2(accS[2*kc+1][2], accS[2*kc+1][3]);
      unsigned bfr[16][2];
      int kof = kc*16 + khalf;
#pragma unroll
      for (int np = 0; np < 8; np++) {
        unsigned t[4];
        ldsm4(t, s2u(sVt + (np*16 + arow)*FROWS + kof));
        bfr[2*np][0] = t[0]; bfr[2*np][1] = t[2];
        bfr[2*np+1][0] = t[1]; bfr[2*np+1][1] = t[3];
      }
#pragma unroll
      for (int nt = 0; nt < 16; nt++)
        mma_hf(accO[nt], pa, bfr[nt]);
    }
  }

  // --- epilogue: O /= l, write fp16 into (B,L,D) with head offset ---
  float inv0 = 1.f / l0, inv1 = 1.f / l1;
  int r0 = qrow0 + wid*16 + (lane >> 2);
  int cb = (lane & 3)*2;
#pragma unroll
  for (int nt = 0; nt < 16; nt++) {
    int col = nt*8 + cb;
    size_t o0 = ((size_t)(b*LL) + r0)*DD + h*HDIM + col;
    size_t o1 = ((size_t)(b*LL) + r0 + 8)*DD + h*HDIM + col;
    __half2 v0; v0.x = __float2half_rn(accO[nt][0]*inv0); v0.y = __float2half_rn(accO[nt][1]*inv0);
    __half2 v1; v1.x = __float2half_rn(accO[nt][2]*inv1); v1.y = __float2half_rn(accO[nt][3]*inv1);
    *reinterpret_cast<__half2*>(Oout + o0) = v0;
    *reinterpret_cast<__half2*>(Oout + o1) = v1;
  }
}

// ---------------------------------------------------------------------------
// fp16 single-product GEMM (dense): C = act(alpha*A@B^T + bias)
// OUTMODE: 0=store fp32; 1=accumulate fp32; 2=store fp16;
//          3=accumulate fp32 AND store fp16 of the sum.
// ---------------------------------------------------------------------------
#define STAGE_H1 (2*TILE_ELEMS)
#define H1_SMEM_BYTES (2*STAGE_H1*2)

template<bool ACT, bool HASBIAS, int OUTMODE>
__global__ void __launch_bounds__(256, 2) mma_h1_kernel(
    const fp16* __restrict__ A, const fp16* __restrict__ B,
    float* __restrict__ C, fp16* __restrict__ Ch,
    const float* __restrict__ bias,
    int K, int lda, int ldb, int ldc, int inner,
    ll aSO, ll aSI, ll bSO, ll bSI, ll cSO, ll cSI, float alpha)
{
  extern __shared__ fp16 smh[];
  int bz = blockIdx.z;
  int bo = bz / inner, bi = bz - bo*inner;
  ll aoff = (ll)bo*aSO + (ll)bi*aSI;
  ll boff = (ll)bo*bSO + (ll)bi*bSI;
  ll coff = (ll)bo*cSO + (ll)bi*cSI;
  A += aoff; B += boff;

  const int tid = threadIdx.x;
  const int row0 = blockIdx.y * 128;
  const int col0 = blockIdx.x * 128;
  const int wid = tid >> 5, lane = tid & 31;
  const int wm = (wid & 3) * 32;
  const int wn = (wid >> 2) * 64;

  float acc[2][8][4];
#pragma unroll
  for (int mt = 0; mt < 2; mt++)
#pragma unroll
    for (int nt = 0; nt < 8; nt++)
#pragma unroll
      for (int q = 0; q < 4; q++) acc[mt][nt][q] = 0.f;

  {
    fp16* base = smh;
#pragma unroll
    for (int i = 0; i < 2; i++) {
      int c = tid + i*256;
      int r = c >> 2, kc = (c & 3) << 3;
      cpa16(s2u(base + 0*TILE_ELEMS + r*LDSROW + kc), A + (size_t)(row0+r)*lda + kc);
      cpa16(s2u(base + 1*TILE_ELEMS + r*LDSROW + kc), B + (size_t)(col0+r)*ldb + kc);
    }
    asm volatile("cp.async.commit_group;\n");
  }

  int s = 0;
  for (int k0 = 0; k0 < K; k0 += 32, s ^= 1) {
    asm volatile("cp.async.wait_group 0;\n");
    __syncthreads();
    if (k0 + 32 < K) {
      fp16* base = smh + (s^1)*STAGE_H1;
      int kn = k0 + 32;
#pragma unroll
      for (int i = 0; i < 2; i++) {
        int c = tid + i*256;
        int r = c >> 2, kc = (c & 3) << 3;
        cpa16(s2u(base + 0*TILE_ELEMS + r*LDSROW + kc), A + (size_t)(row0+r)*lda + kn + kc);
        cpa16(s2u(base + 1*TILE_ELEMS + r*LDSROW + kc), B + (size_t)(col0+r)*ldb + kn + kc);
      }
      asm volatile("cp.async.commit_group;\n");
    }

    fp16* sA = smh + s*STAGE_H1;
    fp16* sB = sA + TILE_ELEMS;
    int arow = lane & 15;
    int khalf = (lane >> 4) << 3;

#pragma unroll
    for (int kk = 0; kk < 2; kk++) {
      int kof = kk*16 + khalf;
      unsigned af[2][4], bfr[8][2];
#pragma unroll
      for (int mt = 0; mt < 2; mt++)
        ldsm4(af[mt], s2u(sA + (wm + mt*16 + arow)*LDSROW + kof));
#pragma unroll
      for (int np = 0; np < 4; np++) {
        unsigned t[4];
        ldsm4(t, s2u(sB + (wn + np*16 + arow)*LDSROW + kof));
        bfr[2*np][0] = t[0]; bfr[2*np][1] = t[2];
        bfr[2*np+1][0] = t[1]; bfr[2*np+1][1] = t[3];
      }
#pragma unroll
      for (int mt = 0; mt < 2; mt++)
#pragma unroll
        for (int nt = 0; nt < 8; nt++)
          mma_hf(acc[mt][nt], af[mt], bfr[nt]);
    }
  }

  int rb = row0 + wm + (lane >> 2);
  int cb = col0 + wn + (lane & 3)*2;
#pragma unroll
  for (int mt = 0; mt < 2; mt++) {
#pragma unroll
    for (int nt = 0; nt < 8; nt++) {
#pragma unroll
      for (int h2 = 0; h2 < 2; h2++) {
        int r = rb + mt*16 + h2*8;
        int cc = cb + nt*8;
        float v0 = alpha * acc[mt][nt][h2*2+0];
        float v1 = alpha * acc[mt][nt][h2*2+1];
        if (HASBIAS) { v0 += bias[cc]; v1 += bias[cc+1]; }
        if (ACT) { v0 = gelu_f(v0); v1 = gelu_f(v1); }
        ll off = coff + (ll)r*ldc + cc;
        if (OUTMODE == 0) {
          float2 o; o.x = v0; o.y = v1;
          *reinterpret_cast<float2*>(C + off) = o;
        } else if (OUTMODE == 1) {
          float2 o = *reinterpret_cast<const float2*>(C + off);
          o.x += v0; o.y += v1;
          *reinterpret_cast<float2*>(C + off) = o;
        } else if (OUTMODE == 2) {
          __half2 hv; hv.x = __float2half_rn(v0); hv.y = __float2half_rn(v1);
          *reinterpret_cast<__half2*>(Ch + off) = hv;
        } else {
          float2 o = *reinterpret_cast<const float2*>(C + off);
          o.x += v0; o.y += v1;
          *reinterpret_cast<float2*>(C + off) = o;
          __half2 hv; hv.x = __float2half_rn(o.x); hv.y = __float2half_rn(o.y);
          *reinterpret_cast<__half2*>(Ch + off) = hv;
        }
      }
    }
  }
}

// ---------------------------------------------------------------------------
// Head second GEMM
// ---------------------------------------------------------------------------
__global__ void __launch_bounds__(256) head2_kernel(const fp16* __restrict__ hb,
    const float* __restrict__ W2, const float* __restrict__ b2,
    float* __restrict__ out) {
  int idx = blockIdx.x;
  int b = idx / PP, t = idx - b*PP;
  const fp16* hh = hb + (size_t)idx * NHID;
  float acc[NOUTD];
#pragma unroll
  for (int o = 0; o < NOUTD; o++) acc[o] = 0.f;
  for (int k = threadIdx.x; k < NHID; k += 256) {
    float v = __half2float(hh[k]);
    const float* w = W2 + (size_t)k * (NOUTD + 1);
#pragma unroll
    for (int o = 0; o < NOUTD; o++) acc[o] += v * w[o];
  }
  __shared__ float smr[8][NOUTD];
  int lane = threadIdx.x & 31, wid = threadIdx.x >> 5;
#pragma unroll
  for (int o = 0; o < NOUTD; o++) acc[o] = warpSum(acc[o]);
  if (lane == 0) {
#pragma unroll
    for (int o = 0; o < NOUTD; o++) smr[wid][o] = acc[o];
  }
  __syncthreads();
  if (threadIdx.x < NOUTD) {
    float sv = 0.f;
#pragma unroll
    for (int w = 0; w < 8; w++) sv += smr[w][threadIdx.x];
    out[((size_t)t*BB + b)*NOUTD + threadIdx.x] = sv + b2[threadIdx.x];
  }
}

// ---------------------------------------------------------------------------
// Orchestration
// ---------------------------------------------------------------------------
typedef void (*h1_fn)(const fp16*, const fp16*,
                      float*, fp16*, const float*,
                      int, int, int, int, int, ll, ll, ll, ll, ll, ll, float);

extern "C" void kernel_launch(void* const* d_in, const int* in_sizes, int n_in,
                              void* d_out, int out_size) {
  (void)in_sizes; (void)n_in; (void)out_size;
  const float* x_src = (const float*)d_in[0];
  const float* y_src = (const float*)d_in[1];
  const float* enc_W = (const float*)d_in[2];
  const float* enc_b = (const float*)d_in[3];
  const float* yenc_W = (const float*)d_in[4];
  const float* yenc_b = (const float*)d_in[5];
  const float* Wq    = (const float*)d_in[6];
  const float* Wkv   = (const float*)d_in[7];
  const float* Wout  = (const float*)d_in[8];
  const float* an_g  = (const float*)d_in[9];
  const float* an_b  = (const float*)d_in[10];
  const float* qn_g  = (const float*)d_in[11];
  const float* qn_b  = (const float*)d_in[12];
  const float* kn_g  = (const float*)d_in[13];
  const float* kn_b  = (const float*)d_in[14];
  const float* fn_g  = (const float*)d_in[15];
  const float* fn_b  = (const float*)d_in[16];
  const float* ffW1  = (const float*)d_in[17];
  const float* ffb1  = (const float*)d_in[18];
  const float* ffW2  = (const float*)d_in[19];
  const float* ffb2  = (const float*)d_in[20];
  const float* hW1   = (const float*)d_in[21];
  const float* hb1   = (const float*)d_in[22];
  const float* hW2   = (const float*)d_in[23];
  const float* hb2   = (const float*)d_in[24];
  float* out = (float*)d_out;

  {
    cudaFuncSetAttribute(flash_attn_kernel, cudaFuncAttributeMaxDynamicSharedMemorySize, FLASH_SMEM);
    h1_fn g;
    g = mma_h1_kernel<false,false,0>;
    cudaFuncSetAttribute(g, cudaFuncAttributeMaxDynamicSharedMemorySize, H1_SMEM_BYTES);
    g = mma_h1_kernel<false,false,1>;
    cudaFuncSetAttribute(g, cudaFuncAttributeMaxDynamicSharedMemorySize, H1_SMEM_BYTES);
    g = mma_h1_kernel<true,true,2>;
    cudaFuncSetAttribute(g, cudaFuncAttributeMaxDynamicSharedMemorySize, H1_SMEM_BYTES);
    g = mma_h1_kernel<false,true,1>;
    cudaFuncSetAttribute(g, cudaFuncAttributeMaxDynamicSharedMemorySize, H1_SMEM_BYTES);
    g = mma_h1_kernel<false,true,3>;
    cudaFuncSetAttribute(g, cudaFuncAttributeMaxDynamicSharedMemorySize, H1_SMEM_BYTES);
  }

  float *p_xn, *p_src, *p_tmp, *p_vh;
  cudaGetSymbolAddress((void**)&p_xn, g_xn);
  cudaGetSymbolAddress((void**)&p_src, g_src);
  cudaGetSymbolAddress((void**)&p_tmp, g_tmp);
  cudaGetSymbolAddress((void**)&p_vh, g_vh);
  fp16 *p_ah, *p_ffh, *p_vth;
  cudaGetSymbolAddress((void**)&p_ah, g_ah);
  cudaGetSymbolAddress((void**)&p_ffh, g_ffh);
  cudaGetSymbolAddress((void**)&p_vth, g_vth);
  bf16 *p_qhh, *p_qhl, *p_khh, *p_khl;
  cudaGetSymbolAddress((void**)&p_qhh, g_qhh);
  cudaGetSymbolAddress((void**)&p_qhl, g_qhl);
  cudaGetSymbolAddress((void**)&p_khh, g_khh);
  cudaGetSymbolAddress((void**)&p_khl, g_khl);
  fp16 *pWq, *pWkv, *pWo, *pW1, *pW2, *pHW1;
  cudaGetSymbolAddress((void**)&pWq, g_WqT);
  cudaGetSymbolAddress((void**)&pWkv, g_WkvT);
  cudaGetSymbolAddress((void**)&pWo, g_WoT);
  cudaGetSymbolAddress((void**)&pW1, g_W1T);
  cudaGetSymbolAddress((void**)&pW2, g_W2T);
  cudaGetSymbolAddress((void**)&pHW1, g_hW1T);

  const float qk_scale = 0.08838834764831845f;

  // --- weight transpose -> fp16 ---
  transpose_half_kernel<<<dim3(DD/32, DD/32, NLAYERS), 256>>>(Wq, pWq, DD, DD, (ll)DD*DD, (ll)DD*DD);
  transpose_half_kernel<<<dim3(2*DD/32, DD/32, NLAYERS), 256>>>(Wkv, pWkv, DD, 2*DD, (ll)DD*2*DD, (ll)DD*2*DD);
  transpose_half_kernel<<<dim3(DD/32, DD/32, NLAYERS), 256>>>(Wout, pWo, DD, DD, (ll)DD*DD, (ll)DD*DD);
  transpose_half_kernel<<<dim3(NHID/32, DD/32, NLAYERS), 256>>>(ffW1, pW1, DD, NHID, (ll)DD*NHID, (ll)DD*NHID);
  transpose_half_kernel<<<dim3(DD/32, NHID/32, NLAYERS), 256>>>(ffW2, pW2, NHID, DD, (ll)NHID*DD, (ll)NHID*DD);
  transpose_half_kernel<<<dim3(NHID/32, DD/32, 1), 256>>>(hW1, pHW1, DD, NHID, 0, 0);

  // --- preprocessing + encoder ---
  colstats_kernel<<<BB*NFEAT, 256>>>(x_src, 0);
  colstats_kernel<<<BB*NFEAT, 256>>>(x_src, 1);
  colstats_kernel<<<BB*NFEAT, 256>>>(x_src, 2);
  norm_write_kernel<<<(LB*KPAD + 255)/256, 256>>>(x_src);
  sgemm_kernel<true><<<dim3(DD/128, LB/128, 1), 256>>>(
      p_xn, enc_W, p_tmp, enc_b, KPAD, NFEAT, KPAD, DD, DD);
  encode_finish_kernel<<<LB, 256>>>(p_tmp, y_src, yenc_W, yenc_b);

  for (int i = 0; i < NLAYERS; i++) {
    // --- attention ---
    ln_half_kernel<<<LB, 256>>>(p_src, an_g + i*DD, an_b + i*DD, p_ah);
    mma_h1_kernel<false,false,0><<<dim3(8, 64, 1), 256, H1_SMEM_BYTES>>>(
        p_ah, pWq + (size_t)i*DD*DD, p_tmp, nullptr, nullptr,
        DD, DD, DD, DD, 1, 0,0,0,0,0,0, 1.f);
    qln_split_kernel<<<LB, 256>>>(p_tmp, qn_g + i*HDIM, qn_b + i*HDIM, p_qhh, p_qhl);
    mma_h1_kernel<false,false,0><<<dim3(16, 8, BB), 256, H1_SMEM_BYTES>>>(
        p_ah, pWkv + (size_t)i*DD*2*DD, p_tmp, nullptr, nullptr,
        DD, DD, DD, 2*DD, 1,
        (ll)LL*DD, 0, 0, 0, (ll)PP*2*DD, 0, 1.f);
    klnv_split_kernel<<<BB*PP, 256>>>(p_tmp, kn_g + i*HDIM, kn_b + i*HDIM, p_khh, p_khl, p_vh);
    transpose_half_kernel<<<dim3(HDIM/32, PP/32, BB*HH), 256>>>(
        p_vh, p_vth, PP, HDIM, (ll)PP*HDIM, (ll)HDIM*PP);
    // fused attention -> fp16 attn out in (B,L,D)
    flash_attn_kernel<<<dim3(LL/128, 1, BB*HH), 256, FLASH_SMEM>>>(
        p_qhh, p_qhl, p_khh, p_khl, p_vth, p_ah, qk_scale);
    // src += attn @ Wout
    mma_h1_kernel<false,false,1><<<dim3(8, 64, 1), 256, H1_SMEM_BYTES>>>(
        p_ah, pWo + (size_t)i*DD*DD, p_src, nullptr, nullptr,
        DD, DD, DD, DD, 1, 0,0,0,0,0,0, 1.f);
    // --- FFN ---
    ln_half_kernel<<<LB, 256>>>(p_src, fn_g + i*DD, fn_b + i*DD, p_ah);
    mma_h1_kernel<true,true,2><<<dim3(NHID/128, 64, 1), 256, H1_SMEM_BYTES>>>(
        p_ah, pW1 + (size_t)i*NHID*DD, nullptr, p_ffh, ffb1 + (size_t)i*NHID,
        DD, DD, DD, NHID, 1, 0,0,0,0,0,0, 1.f);
    if (i < NLAYERS - 1) {
      mma_h1_kernel<false,true,1><<<dim3(8, 64, 1), 256, H1_SMEM_BYTES>>>(
          p_ffh, pW2 + (size_t)i*DD*NHID, p_src, nullptr, ffb2 + (size_t)i*DD,
          NHID, NHID, NHID, DD, 1, 0,0,0,0,0,0, 1.f);
    } else {
      mma_h1_kernel<false,true,3><<<dim3(8, 64, 1), 256, H1_SMEM_BYTES>>>(
          p_ffh, pW2 + (size_t)i*DD*NHID, p_src, p_ah, ffb2 + (size_t)i*DD,
          NHID, NHID, NHID, DD, 1, 0,0,0,0,0,0, 1.f);
    }
  }

  // --- head ---
  mma_h1_kernel<true,true,2><<<dim3(NHID/128, PP/128, BB), 256, H1_SMEM_BYTES>>>(
      p_ah + (size_t)PP*DD, pHW1, nullptr, p_ffh, hb1,
      DD, DD, DD, NHID, 1,
      (ll)LL*DD, 0, 0, 0, (ll)PP*NHID, 0, 1.f);
  head2_kernel<<<BB*PP, 256>>>(p_ffh, hW2, hb2, out);
}

// round 15
// speedup vs baseline: 2.4620x; 1.0523x over previous
// TabDPT fused kernel — rev C (fp16x2 QK flash attention).
// Semantically identical to rev B; textual revision to bust any
// content-addressed build/artifact cache after repeated infra failures.
#include <cuda_runtime.h>
#include <cuda_bf16.h>
#include <cuda_fp16.h>
#include <cstdint>
#include <cstddef>
#include <math.h>

// ---------------------------------------------------------------------------
// Problem constants
// ---------------------------------------------------------------------------
#define BB     4
#define LL     2048
#define PP     1024
#define NFEAT  100
#define DD     1024
#define HH     8
#define HDIM   128
#define NHID   4096
#define NLAYERS 3
#define NOUTD  10
#define LB     (LL*BB)
#define KPAD   112

typedef __nv_bfloat16 bf16;
typedef __half fp16;
typedef long long ll;

// ---------------------------------------------------------------------------
// Scratch (device globals)
// ---------------------------------------------------------------------------
__device__ float g_m1[BB*NFEAT], g_s1[BB*NFEAT];
__device__ float g_m2[BB*NFEAT], g_s2[BB*NFEAT];
__device__ float g_m3[BB*NFEAT], g_s3[BB*NFEAT];
__device__ __align__(256) float g_xn[(size_t)LB*KPAD];
__device__ __align__(256) float g_src[(size_t)LB*DD];
__device__ __align__(256) float g_tmp[(size_t)LB*DD];
__device__ __align__(256) float g_vh [(size_t)BB*HH*PP*HDIM];

// fp16 single activations
__device__ __align__(256) fp16 g_ah[(size_t)LB*DD];
__device__ __align__(256) fp16 g_ffh[(size_t)LB*NHID];
__device__ __align__(256) fp16 g_vth[(size_t)BB*HH*HDIM*PP]; // vT fp16

// fp16 attention operands: Q split hi/lo (exact), K single
__device__ __align__(256) fp16 g_qhh[(size_t)BB*HH*LL*HDIM];
__device__ __align__(256) fp16 g_qhl[(size_t)BB*HH*LL*HDIM];
__device__ __align__(256) fp16 g_khh[(size_t)BB*HH*PP*HDIM];

// fp16 transposed weights
__device__ __align__(256) fp16 g_WqT [(size_t)NLAYERS*DD*DD];
__device__ __align__(256) fp16 g_WkvT[(size_t)NLAYERS*2*DD*DD];
__device__ __align__(256) fp16 g_WoT [(size_t)NLAYERS*DD*DD];
__device__ __align__(256) fp16 g_W1T [(size_t)NLAYERS*NHID*DD];
__device__ __align__(256) fp16 g_W2T [(size_t)NLAYERS*DD*NHID];
__device__ __align__(256) fp16 g_hW1T[(size_t)NHID*DD];

// ---------------------------------------------------------------------------
// Helpers
// ---------------------------------------------------------------------------
__device__ __forceinline__ float warpSum(float v) {
#pragma unroll
  for (int o = 16; o > 0; o >>= 1) v += __shfl_xor_sync(0xffffffffu, v, o);
  return v;
}

__device__ __forceinline__ float blockReduceSum(float v) {
  __shared__ float sh[32];
  int lane = threadIdx.x & 31, wid = threadIdx.x >> 5;
  v = warpSum(v);
  if (lane == 0) sh[wid] = v;
  __syncthreads();
  int nw = (blockDim.x + 31) >> 5;
  v = (threadIdx.x < nw) ? sh[threadIdx.x] : 0.f;
  if (wid == 0) { v = warpSum(v); if (lane == 0) sh[0] = v; }
  __syncthreads();
  float r = sh[0];
  __syncthreads();
  return r;
}

__device__ __forceinline__ float gelu_f(float x) {
  return 0.5f * x * (1.0f + erff(x * 0.7071067811865475f));
}

__device__ __forceinline__ void splitHalf2(float v, fp16& h, fp16& l) {
  h = __float2half_rn(v);
  l = __float2half_rn(v - __half2float(h));
}

// pack two floats into one 32-bit word of two fp16 (low = a, high = b)
__device__ __forceinline__ unsigned packh2(float a, float b) {
  __half2 h = __floats2half2_rn(a, b);
  return *reinterpret_cast<unsigned*>(&h);
}

// fast exp on the FMA pipe (no MUFU). rel err ~2e-6 on the needed range (x<=0).
__device__ __forceinline__ float fexp(float x) {
  float y = fmaxf(x * 1.4426950408889634f, -100.f);
  float t = y + 12582912.f;
  float i = t - 12582912.f;
  float u = (y - i) * 0.6931471805599453f;
  float p = 0.008333333f;
  p = fmaf(p, u, 0.041666667f);
  p = fmaf(p, u, 0.166666667f);
  p = fmaf(p, u, 0.5f);
  p = fmaf(p, u, 1.0f);
  p = fmaf(p, u, 1.0f);
  int ei = (int)i;
  return p * __uint_as_float((unsigned)((ei + 127) << 23));
}

__device__ __forceinline__ unsigned s2u(const void* p) {
  return (unsigned)__cvta_generic_to_shared(p);
}

__device__ __forceinline__ void cpa16(unsigned s, const void* g) {
  asm volatile("cp.async.cg.shared.global [%0], [%1], 16;\n" :: "r"(s), "l"(g));
}

__device__ __forceinline__ void ldsm4(unsigned* r, unsigned addr) {
  asm volatile("ldmatrix.sync.aligned.m8n8.x4.shared.b16 {%0,%1,%2,%3}, [%4];\n"
    : "=r"(r[0]), "=r"(r[1]), "=r"(r[2]), "=r"(r[3]) : "r"(addr));
}

__device__ __forceinline__ void mma_hf(float* c, const unsigned* a, const unsigned* b) {
  asm volatile("mma.sync.aligned.m16n8k16.row.col.f32.f16.f16.f32 "
    "{%0,%1,%2,%3}, {%4,%5,%6,%7}, {%8,%9}, {%0,%1,%2,%3};\n"
    : "+f"(c[0]), "+f"(c[1]), "+f"(c[2]), "+f"(c[3])
    : "r"(a[0]), "r"(a[1]), "r"(a[2]), "r"(a[3]), "r"(b[0]), "r"(b[1]));
}

// ---------------------------------------------------------------------------
// Preprocessing / LN / transpose kernels
// ---------------------------------------------------------------------------
__global__ void __launch_bounds__(256) colstats_kernel(const float* __restrict__ xsrc, int mode) {
  int bf = blockIdx.x;
  int b = bf / NFEAT, f = bf - b*NFEAT;
  const float* base = xsrc + (size_t)b*LL*NFEAT + f;
  float m1 = g_m1[bf], s1 = g_s1[bf];
  float m2 = g_m2[bf], s2 = g_s2[bf];
  float lo1 = m1 - 4.f*s1, hi1 = m1 + 4.f*s1;
  float inv2 = 1.f / (s2 + 1e-6f);
  float sum = 0.f, sq = 0.f;
  for (int t = threadIdx.x; t < PP; t += blockDim.x) {
    float v = base[(size_t)t*NFEAT];
    if (mode >= 1) v = fminf(fmaxf(v, lo1), hi1);
    if (mode >= 2) v = (v - m2) * inv2;
    sum += v; sq += v*v;
  }
  sum = blockReduceSum(sum);
  sq  = blockReduceSum(sq);
  if (threadIdx.x == 0) {
    float m = sum * (1.f/PP);
    float var = sq * (1.f/PP) - m*m;
    float s = sqrtf(fmaxf(var, 0.f));
    if (mode == 0)      { g_m1[bf] = m; g_s1[bf] = s; }
    else if (mode == 1) { g_m2[bf] = m; g_s2[bf] = s; }
    else                { g_m3[bf] = m; g_s3[bf] = s; }
  }
}

__global__ void __launch_bounds__(256) norm_write_kernel(const float* __restrict__ xsrc) {
  int idx = blockIdx.x * blockDim.x + threadIdx.x;
  if (idx >= LB*KPAD) return;
  int row = idx / KPAD, f = idx - row*KPAD;
  int l = row / BB, b = row - l*BB;
  float out = 0.f;
  if (f < NFEAT) {
    int bf = b*NFEAT + f;
    float v = xsrc[(size_t)b*LL*NFEAT + (size_t)l*NFEAT + f];
    float m1 = g_m1[bf], s1 = g_s1[bf];
    v = fminf(fmaxf(v, m1 - 4.f*s1), m1 + 4.f*s1);
    v = (v - g_m2[bf]) / (g_s2[bf] + 1e-6f);
    float m3 = g_m3[bf], s3 = g_s3[bf];
    v = fminf(fmaxf(v, m3 - 4.f*s3), m3 + 4.f*s3);
    if (!isfinite(v)) v = 0.f;
    out = v;
  }
  g_xn[idx] = out;
}

__global__ void __launch_bounds__(256) encode_finish_kernel(const float* __restrict__ xeD,
    const float* __restrict__ ysrc, const float* __restrict__ yencW, const float* __restrict__ yencb) {
  int row = blockIdx.x;
  int l = row / BB, b = row - l*BB;
  const float* xr = xeD + (size_t)row * DD;
  float v[4]; float sq = 0.f;
#pragma unroll
  for (int i = 0; i < 4; i++) { v[i] = xr[threadIdx.x + i*256]; sq += v[i]*v[i]; }
  float ms = blockReduceSum(sq) * (1.f/DD);
  float inv = 1.f / sqrtf(ms);
  bool addy = (l < PP);
  float yv = addy ? ysrc[(size_t)b*PP + l] : 0.f;
  float* dst = g_src + ((size_t)b*LL + l) * DD;
#pragma unroll
  for (int i = 0; i < 4; i++) {
    int c = threadIdx.x + i*256;
    float o = v[i] * inv;
    if (addy) o += yv * yencW[c] + yencb[c];
    dst[c] = o;
  }
}

__global__ void __launch_bounds__(256) ln_half_kernel(const float* __restrict__ x,
    const float* __restrict__ gg, const float* __restrict__ bbp,
    fp16* __restrict__ oh) {
  int row = blockIdx.x;
  const float* xr = x + (size_t)row * DD;
  float v[4]; float s = 0.f;
#pragma unroll
  for (int i = 0; i < 4; i++) { v[i] = xr[threadIdx.x + i*256]; s += v[i]; }
  float m = blockReduceSum(s) * (1.f/DD);
  float d = 0.f;
#pragma unroll
  for (int i = 0; i < 4; i++) { float t = v[i]-m; d += t*t; }
  float var = blockReduceSum(d) * (1.f/DD);
  float r = rsqrtf(var + 1e-5f);
#pragma unroll
  for (int i = 0; i < 4; i++) {
    int c = threadIdx.x + i*256;
    float o = (v[i]-m)*r*gg[c] + bbp[c];
    oh[(size_t)row*DD + c] = __float2half_rn(o);
  }
}

// q per-head LN -> fp16 split (B,H,L,HD)
__global__ void __launch_bounds__(256) qln_split_kernel(const float* __restrict__ qraw,
    const float* __restrict__ gg, const float* __restrict__ bbp,
    fp16* __restrict__ qh, fp16* __restrict__ ql) {
  int row = blockIdx.x;
  int h = threadIdx.x >> 5, lane = threadIdx.x & 31;
  int b = row / LL, l = row - b*LL;
  const float* src = qraw + (size_t)row*DD + h*HDIM;
  float v[4]; float s = 0.f;
#pragma unroll
  for (int i = 0; i < 4; i++) { v[i] = src[lane + i*32]; s += v[i]; }
  float m = warpSum(s) * (1.f/HDIM);
  float d = 0.f;
#pragma unroll
  for (int i = 0; i < 4; i++) { float t = v[i]-m; d += t*t; }
  float var = warpSum(d) * (1.f/HDIM);
  float r = rsqrtf(var + 1e-5f);
  size_t base = ((size_t)(b*HH + h)*LL + l) * HDIM;
#pragma unroll
  for (int i = 0; i < 4; i++) {
    int c = lane + i*32;
    float o = (v[i]-m)*r*gg[c] + bbp[c];
    fp16 hh, llv; splitHalf2(o, hh, llv);
    qh[base + c] = hh; ql[base + c] = llv;
  }
}

// k per-head LN -> single fp16; v copy fp32
__global__ void __launch_bounds__(256) klnv_split_kernel(const float* __restrict__ kv,
    const float* __restrict__ gg, const float* __restrict__ bbp,
    fp16* __restrict__ kh, float* __restrict__ vh) {
  int row = blockIdx.x;
  int h = threadIdx.x >> 5, lane = threadIdx.x & 31;
  int b = row / PP, t = row - b*PP;
  const float* kp = kv + (size_t)row*2*DD + h*HDIM;
  const float* vp = kp + DD;
  float v[4]; float s = 0.f;
#pragma unroll
  for (int i = 0; i < 4; i++) { v[i] = kp[lane + i*32]; s += v[i]; }
  float m = warpSum(s) * (1.f/HDIM);
  float d = 0.f;
#pragma unroll
  for (int i = 0; i < 4; i++) { float t2 = v[i]-m; d += t2*t2; }
  float var = warpSum(d) * (1.f/HDIM);
  float r = rsqrtf(var + 1e-5f);
  size_t base = ((size_t)(b*HH + h)*PP + t) * HDIM;
#pragma unroll
  for (int i = 0; i < 4; i++) {
    int c = lane + i*32;
    float o = (v[i]-m)*r*gg[c] + bbp[c];
    kh[base + c] = __float2half_rn(o);
    vh[base + c] = vp[c];
  }
}

__global__ void __launch_bounds__(256) transpose_half_kernel(const float* __restrict__ src,
    fp16* __restrict__ dst, int R, int C, ll sStride, ll dStride) {
  __shared__ float t[32][33];
  int z = blockIdx.z;
  src += (ll)z * sStride;
  dst += (ll)z * dStride;
  int c0 = blockIdx.x * 32, r0 = blockIdx.y * 32;
  int tx = threadIdx.x & 31, ty = threadIdx.x >> 5;
#pragma unroll
  for (int j = ty; j < 32; j += 8)
    t[j][tx] = src[(size_t)(r0+j)*C + c0 + tx];
  __syncthreads();
#pragma unroll
  for (int j = ty; j < 32; j += 8)
    dst[(size_t)(c0+j)*R + r0 + tx] = __float2half_rn(t[tx][j]);
}

// ---------------------------------------------------------------------------
// fp32 SGEMM (encoder only)
// ---------------------------------------------------------------------------
template<bool HASBIAS>
__global__ void __launch_bounds__(256, 2) sgemm_kernel(
    const float* __restrict__ A, const float* __restrict__ B, float* __restrict__ C,
    const float* __restrict__ bias, int K, int kGuard, int lda, int ldb, int ldc)
{
  __shared__ float As[16][128];
  __shared__ float Bs[16][128];
  const int tid = threadIdx.x;
  const int row0 = blockIdx.y * 128;
  const int col0 = blockIdx.x * 128;
  const int tx = tid & 15, ty = tid >> 4;
  const int tm0 = ty*8, tn0 = tx*8;
  float acc[8][8];
#pragma unroll
  for (int i = 0; i < 8; i++)
#pragma unroll
    for (int j = 0; j < 8; j++) acc[i][j] = 0.f;
  for (int k0 = 0; k0 < K; k0 += 16) {
#pragma unroll
    for (int u = 0; u < 2; u++) {
      int f = tid + u*256;
      int r = f >> 2, c4 = (f & 3) << 2;
      float4 va = *reinterpret_cast<const float4*>(A + (size_t)(row0 + r)*lda + (k0 + c4));
      As[c4+0][r] = va.x; As[c4+1][r] = va.y; As[c4+2][r] = va.z; As[c4+3][r] = va.w;
    }
#pragma unroll
    for (int u = 0; u < 2; u++) {
      int f = tid + u*256;
      int kk = f >> 5, n4 = (f & 31) << 2;
      float4 vb = make_float4(0.f, 0.f, 0.f, 0.f);
      if (k0 + kk < kGuard)
        vb = *reinterpret_cast<const float4*>(B + (size_t)(k0 + kk)*ldb + (col0 + n4));
      *reinterpret_cast<float4*>(&Bs[kk][n4]) = vb;
    }
    __syncthreads();
#pragma unroll
    for (int kk = 0; kk < 16; kk++) {
      float4 a0 = *reinterpret_cast<const float4*>(&As[kk][tm0]);
      float4 a1 = *reinterpret_cast<const float4*>(&As[kk][tm0+4]);
      float4 b0 = *reinterpret_cast<const float4*>(&Bs[kk][tn0]);
      float4 b1 = *reinterpret_cast<const float4*>(&Bs[kk][tn0+4]);
      float ra[8] = {a0.x,a0.y,a0.z,a0.w,a1.x,a1.y,a1.z,a1.w};
      float rb[8] = {b0.x,b0.y,b0.z,b0.w,b1.x,b1.y,b1.z,b1.w};
#pragma unroll
      for (int i = 0; i < 8; i++)
#pragma unroll
        for (int j = 0; j < 8; j++)
          acc[i][j] = fmaf(ra[i], rb[j], acc[i][j]);
    }
    __syncthreads();
  }
#pragma unroll
  for (int i = 0; i < 8; i++) {
    float* crow = C + (size_t)(row0 + tm0 + i)*ldc + (col0 + tn0);
#pragma unroll
    for (int j = 0; j < 8; j += 4) {
      float4 v;
      v.x = acc[i][j+0]; v.y = acc[i][j+1]; v.z = acc[i][j+2]; v.w = acc[i][j+3];
      if (HASBIAS) {
        float4 bbv = *reinterpret_cast<const float4*>(bias + col0 + tn0 + j);
        v.x += bbv.x; v.y += bbv.y; v.z += bbv.z; v.w += bbv.w;
      }
      *reinterpret_cast<float4*>(crow + j) = v;
    }
  }
}

#define LDSROW 40
#define TILE_ELEMS (128*LDSROW)

// ---------------------------------------------------------------------------
// Fused flash attention (fp16x2 QK): per (b,h), 128 Q rows per CTA.
// S = scale*(Qh+Ql)@K^T (Q fp16 hi/lo, K fp16 single), online softmax (poly exp),
// O += P(fp16) @ V (from vT tiles). Writes fp16 attn out in (B,L,D) layout.
// 8 warps, each owns 16 rows x full 128 cols.
// ---------------------------------------------------------------------------
#define FROWS 136
#define FTILE (128*FROWS)
#define FLASH_SMEM (4*FTILE*2)

__global__ void __launch_bounds__(256) flash_attn_kernel(
    const fp16* __restrict__ Qh, const fp16* __restrict__ Ql,
    const fp16* __restrict__ Kh,
    const fp16* __restrict__ Vt, fp16* __restrict__ Oout, float scale)
{
  extern __shared__ char fsm[];
  fp16* sQh = (fp16*)fsm;
  fp16* sQl = sQh + FTILE;
  fp16* sKh = sQl + FTILE;
  fp16* sVt = sKh + FTILE;

  const int bh = blockIdx.z;
  const int b = bh >> 3, h = bh & 7;
  const int qrow0 = blockIdx.x * 128;
  const fp16* gQh = Qh + ((size_t)bh*LL + qrow0)*HDIM;
  const fp16* gQl = Ql + ((size_t)bh*LL + qrow0)*HDIM;
  const fp16* gKh = Kh + (size_t)bh*PP*HDIM;
  const fp16* gVt = Vt + (size_t)bh*HDIM*PP;

  const int tid = threadIdx.x, wid = tid >> 5, lane = tid & 31;
  const int arow = lane & 15;
  const int khalf = (lane >> 4) << 3;

  // load Q tiles (resident)
#pragma unroll
  for (int i = 0; i < 8; i++) {
    int id = tid + (i << 8);
    int r = id >> 4, c = (id & 15) << 3;
    cpa16(s2u(sQh + r*FROWS + c), gQh + (size_t)r*HDIM + c);
    cpa16(s2u(sQl + r*FROWS + c), gQl + (size_t)r*HDIM + c);
  }
  asm volatile("cp.async.commit_group;\n");

  float accO[16][4];
#pragma unroll
  for (int nt = 0; nt < 16; nt++)
#pragma unroll
    for (int q = 0; q < 4; q++) accO[nt][q] = 0.f;
  float m0 = -3.4e38f, m1 = -3.4e38f, l0 = 0.f, l1 = 0.f;

  for (int kt = 0; kt < PP/128; kt++) {
    __syncthreads();   // previous-iteration smem reads done before overwrite
#pragma unroll
    for (int i = 0; i < 8; i++) {
      int id = tid + (i << 8);
      int r = id >> 4, c = (id & 15) << 3;
      cpa16(s2u(sKh + r*FROWS + c), gKh + (size_t)(kt*128 + r)*HDIM + c);
      cpa16(s2u(sVt + r*FROWS + c), gVt + (size_t)r*PP + kt*128 + c);
    }
    asm volatile("cp.async.commit_group;\n");
    asm volatile("cp.async.wait_group 0;\n" ::: "memory");
    __syncthreads();

    // --- S = (Qh+Ql)@K^T ---
    float accS[16][4];
#pragma unroll
    for (int nt = 0; nt < 16; nt++)
#pragma unroll
      for (int q = 0; q < 4; q++) accS[nt][q] = 0.f;

#pragma unroll
    for (int kk = 0; kk < 8; kk++) {
      int kof = kk*16 + khalf;
      unsigned ah[4], al[4], bfr[16][2];
      ldsm4(ah, s2u(sQh + (wid*16 + arow)*FROWS + kof));
      ldsm4(al, s2u(sQl + (wid*16 + arow)*FROWS + kof));
#pragma unroll
      for (int np = 0; np < 8; np++) {
        unsigned t[4];
        ldsm4(t, s2u(sKh + (np*16 + arow)*FROWS + kof));
        bfr[2*np][0] = t[0]; bfr[2*np][1] = t[2];
        bfr[2*np+1][0] = t[1]; bfr[2*np+1][1] = t[3];
      }
#pragma unroll
      for (int nt = 0; nt < 16; nt++) {
        mma_hf(accS[nt], ah, bfr[nt]);
        mma_hf(accS[nt], al, bfr[nt]);
      }
    }

    // --- online softmax ---
    float rmax0 = -3.4e38f, rmax1 = -3.4e38f;
#pragma unroll
    for (int nt = 0; nt < 16; nt++) {
      accS[nt][0] *= scale; accS[nt][1] *= scale;
      accS[nt][2] *= scale; accS[nt][3] *= scale;
      rmax0 = fmaxf(rmax0, fmaxf(accS[nt][0], accS[nt][1]));
      rmax1 = fmaxf(rmax1, fmaxf(accS[nt][2], accS[nt][3]));
    }
    rmax0 = fmaxf(rmax0, __shfl_xor_sync(0xffffffffu, rmax0, 1));
    rmax0 = fmaxf(rmax0, __shfl_xor_sync(0xffffffffu, rmax0, 2));
    rmax1 = fmaxf(rmax1, __shfl_xor_sync(0xffffffffu, rmax1, 1));
    rmax1 = fmaxf(rmax1, __shfl_xor_sync(0xffffffffu, rmax1, 2));
    float mn0 = fmaxf(m0, rmax0), mn1 = fmaxf(m1, rmax1);
    float a0 = fexp(m0 - mn0), a1 = fexp(m1 - mn1);
    float rs0 = 0.f, rs1 = 0.f;
#pragma unroll
    for (int nt = 0; nt < 16; nt++) {
      accS[nt][0] = fexp(accS[nt][0] - mn0);
      accS[nt][1] = fexp(accS[nt][1] - mn0);
      accS[nt][2] = fexp(accS[nt][2] - mn1);
      accS[nt][3] = fexp(accS[nt][3] - mn1);
      rs0 += accS[nt][0] + accS[nt][1];
      rs1 += accS[nt][2] + accS[nt][3];
    }
    rs0 += __shfl_xor_sync(0xffffffffu, rs0, 1);
    rs0 += __shfl_xor_sync(0xffffffffu, rs0, 2);
    rs1 += __shfl_xor_sync(0xffffffffu, rs1, 1);
    rs1 += __shfl_xor_sync(0xffffffffu, rs1, 2);
    l0 = l0*a0 + rs0; l1 = l1*a1 + rs1;
    m0 = mn0; m1 = mn1;
#pragma unroll
    for (int nt = 0; nt < 16; nt++) {
      accO[nt][0] *= a0; accO[nt][1] *= a0;
      accO[nt][2] *= a1; accO[nt][3] *= a1;
    }

    // --- O += P @ V (P from accS, fp16; B from vT tile) ---
#pragma unroll
    for (int kc = 0; kc < 8; kc++) {
      unsigned pa[4];
      pa[0] = packh2(accS[2*kc][0], accS[2*kc][1]);
      pa[1] = packh2(accS[2*kc][2], accS[2*kc][3]);
      pa[2] = packh2(accS[2*kc+1][0], accS[2*kc+1][1]);
      pa[3] = packh2(accS[2*kc+1][2], accS[2*kc+1][3]);
      unsigned bfr[16][2];
      int kof = kc*16 + khalf;
#pragma unroll
      for (int np = 0; np < 8; np++) {
        unsigned t[4];
        ldsm4(t, s2u(sVt + (np*16 + arow)*FROWS + kof));
        bfr[2*np][0] = t[0]; bfr[2*np][1] = t[2];
        bfr[2*np+1][0] = t[1]; bfr[2*np+1][1] = t[3];
      }
#pragma unroll
      for (int nt = 0; nt < 16; nt++)
        mma_hf(accO[nt], pa, bfr[nt]);
    }
  }

  // --- epilogue: O /= l, write fp16 into (B,L,D) with head offset ---
  float inv0 = 1.f / l0, inv1 = 1.f / l1;
  int r0 = qrow0 + wid*16 + (lane >> 2);
  int cb = (lane & 3)*2;
#pragma unroll
  for (int nt = 0; nt < 16; nt++) {
    int col = nt*8 + cb;
    size_t o0 = ((size_t)(b*LL) + r0)*DD + h*HDIM + col;
    size_t o1 = ((size_t)(b*LL) + r0 + 8)*DD + h*HDIM + col;
    __half2 v0; v0.x = __float2half_rn(accO[nt][0]*inv0); v0.y = __float2half_rn(accO[nt][1]*inv0);
    __half2 v1; v1.x = __float2half_rn(accO[nt][2]*inv1); v1.y = __float2half_rn(accO[nt][3]*inv1);
    *reinterpret_cast<__half2*>(Oout + o0) = v0;
    *reinterpret_cast<__half2*>(Oout + o1) = v1;
  }
}

// ---------------------------------------------------------------------------
// fp16 single-product GEMM (dense): C = act(alpha*A@B^T + bias)
// OUTMODE: 0=store fp32; 1=accumulate fp32; 2=store fp16;
//          3=accumulate fp32 AND store fp16 of the sum.
// ---------------------------------------------------------------------------
#define STAGE_H1 (2*TILE_ELEMS)
#define H1_SMEM_BYTES (2*STAGE_H1*2)

template<bool ACT, bool HASBIAS, int OUTMODE>
__global__ void __launch_bounds__(256, 2) mma_h1_kernel(
    const fp16* __restrict__ A, const fp16* __restrict__ B,
    float* __restrict__ C, fp16* __restrict__ Ch,
    const float* __restrict__ bias,
    int K, int lda, int ldb, int ldc, int inner,
    ll aSO, ll aSI, ll bSO, ll bSI, ll cSO, ll cSI, float alpha)
{
  extern __shared__ fp16 smh[];
  int bz = blockIdx.z;
  int bo = bz / inner, bi = bz - bo*inner;
  ll aoff = (ll)bo*aSO + (ll)bi*aSI;
  ll boff = (ll)bo*bSO + (ll)bi*bSI;
  ll coff = (ll)bo*cSO + (ll)bi*cSI;
  A += aoff; B += boff;

  const int tid = threadIdx.x;
  const int row0 = blockIdx.y * 128;
  const int col0 = blockIdx.x * 128;
  const int wid = tid >> 5, lane = tid & 31;
  const int wm = (wid & 3) * 32;
  const int wn = (wid >> 2) * 64;

  float acc[2][8][4];
#pragma unroll
  for (int mt = 0; mt < 2; mt++)
#pragma unroll
    for (int nt = 0; nt < 8; nt++)
#pragma unroll
      for (int q = 0; q < 4; q++) acc[mt][nt][q] = 0.f;

  {
    fp16* base = smh;
#pragma unroll
    for (int i = 0; i < 2; i++) {
      int c = tid + i*256;
      int r = c >> 2, kc = (c & 3) << 3;
      cpa16(s2u(base + 0*TILE_ELEMS + r*LDSROW + kc), A + (size_t)(row0+r)*lda + kc);
      cpa16(s2u(base + 1*TILE_ELEMS + r*LDSROW + kc), B + (size_t)(col0+r)*ldb + kc);
    }
    asm volatile("cp.async.commit_group;\n");
  }

  int s = 0;
  for (int k0 = 0; k0 < K; k0 += 32, s ^= 1) {
    asm volatile("cp.async.wait_group 0;\n");
    __syncthreads();
    if (k0 + 32 < K) {
      fp16* base = smh + (s^1)*STAGE_H1;
      int kn = k0 + 32;
#pragma unroll
      for (int i = 0; i < 2; i++) {
        int c = tid + i*256;
        int r = c >> 2, kc = (c & 3) << 3;
        cpa16(s2u(base + 0*TILE_ELEMS + r*LDSROW + kc), A + (size_t)(row0+r)*lda + kn + kc);
        cpa16(s2u(base + 1*TILE_ELEMS + r*LDSROW + kc), B + (size_t)(col0+r)*ldb + kn + kc);
      }
      asm volatile("cp.async.commit_group;\n");
    }

    fp16* sA = smh + s*STAGE_H1;
    fp16* sB = sA + TILE_ELEMS;
    int arow = lane & 15;
    int khalf = (lane >> 4) << 3;

#pragma unroll
    for (int kk = 0; kk < 2; kk++) {
      int kof = kk*16 + khalf;
      unsigned af[2][4], bfr[8][2];
#pragma unroll
      for (int mt = 0; mt < 2; mt++)
        ldsm4(af[mt], s2u(sA + (wm + mt*16 + arow)*LDSROW + kof));
#pragma unroll
      for (int np = 0; np < 4; np++) {
        unsigned t[4];
        ldsm4(t, s2u(sB + (wn + np*16 + arow)*LDSROW + kof));
        bfr[2*np][0] = t[0]; bfr[2*np][1] = t[2];
        bfr[2*np+1][0] = t[1]; bfr[2*np+1][1] = t[3];
      }
#pragma unroll
      for (int mt = 0; mt < 2; mt++)
#pragma unroll
        for (int nt = 0; nt < 8; nt++)
          mma_hf(acc[mt][nt], af[mt], bfr[nt]);
    }
  }

  int rb = row0 + wm + (lane >> 2);
  int cb = col0 + wn + (lane & 3)*2;
#pragma unroll
  for (int mt = 0; mt < 2; mt++) {
#pragma unroll
    for (int nt = 0; nt < 8; nt++) {
#pragma unroll
      for (int h2 = 0; h2 < 2; h2++) {
        int r = rb + mt*16 + h2*8;
        int cc = cb + nt*8;
        float v0 = alpha * acc[mt][nt][h2*2+0];
        float v1 = alpha * acc[mt][nt][h2*2+1];
        if (HASBIAS) { v0 += bias[cc]; v1 += bias[cc+1]; }
        if (ACT) { v0 = gelu_f(v0); v1 = gelu_f(v1); }
        ll off = coff + (ll)r*ldc + cc;
        if (OUTMODE == 0) {
          float2 o; o.x = v0; o.y = v1;
          *reinterpret_cast<float2*>(C + off) = o;
        } else if (OUTMODE == 1) {
          float2 o = *reinterpret_cast<const float2*>(C + off);
          o.x += v0; o.y += v1;
          *reinterpret_cast<float2*>(C + off) = o;
        } else if (OUTMODE == 2) {
          __half2 hv; hv.x = __float2half_rn(v0); hv.y = __float2half_rn(v1);
          *reinterpret_cast<__half2*>(Ch + off) = hv;
        } else {
          float2 o = *reinterpret_cast<const float2*>(C + off);
          o.x += v0; o.y += v1;
          *reinterpret_cast<float2*>(C + off) = o;
          __half2 hv; hv.x = __float2half_rn(o.x); hv.y = __float2half_rn(o.y);
          *reinterpret_cast<__half2*>(Ch + off) = hv;
        }
      }
    }
  }
}

// ---------------------------------------------------------------------------
// Head second GEMM
// ---------------------------------------------------------------------------
__global__ void __launch_bounds__(256) head2_kernel(const fp16* __restrict__ hb,
    const float* __restrict__ W2, const float* __restrict__ b2,
    float* __restrict__ out) {
  int idx = blockIdx.x;
  int b = idx / PP, t = idx - b*PP;
  const fp16* hh = hb + (size_t)idx * NHID;
  float acc[NOUTD];
#pragma unroll
  for (int o = 0; o < NOUTD; o++) acc[o] = 0.f;
  for (int k = threadIdx.x; k < NHID; k += 256) {
    float v = __half2float(hh[k]);
    const float* w = W2 + (size_t)k * (NOUTD + 1);
#pragma unroll
    for (int o = 0; o < NOUTD; o++) acc[o] += v * w[o];
  }
  __shared__ float smr[8][NOUTD];
  int lane = threadIdx.x & 31, wid = threadIdx.x >> 5;
#pragma unroll
  for (int o = 0; o < NOUTD; o++) acc[o] = warpSum(acc[o]);
  if (lane == 0) {
#pragma unroll
    for (int o = 0; o < NOUTD; o++) smr[wid][o] = acc[o];
  }
  __syncthreads();
  if (threadIdx.x < NOUTD) {
    float sv = 0.f;
#pragma unroll
    for (int w = 0; w < 8; w++) sv += smr[w][threadIdx.x];
    out[((size_t)t*BB + b)*NOUTD + threadIdx.x] = sv + b2[threadIdx.x];
  }
}

// ---------------------------------------------------------------------------
// Orchestration
// ---------------------------------------------------------------------------
typedef void (*h1_fn)(const fp16*, const fp16*,
                      float*, fp16*, const float*,
                      int, int, int, int, int, ll, ll, ll, ll, ll, ll, float);

extern "C" void kernel_launch(void* const* d_in, const int* in_sizes, int n_in,
                              void* d_out, int out_size) {
  (void)in_sizes; (void)n_in; (void)out_size;
  const float* x_src = (const float*)d_in[0];
  const float* y_src = (const float*)d_in[1];
  const float* enc_W = (const float*)d_in[2];
  const float* enc_b = (const float*)d_in[3];
  const float* yenc_W = (const float*)d_in[4];
  const float* yenc_b = (const float*)d_in[5];
  const float* Wq    = (const float*)d_in[6];
  const float* Wkv   = (const float*)d_in[7];
  const float* Wout  = (const float*)d_in[8];
  const float* an_g  = (const float*)d_in[9];
  const float* an_b  = (const float*)d_in[10];
  const float* qn_g  = (const float*)d_in[11];
  const float* qn_b  = (const float*)d_in[12];
  const float* kn_g  = (const float*)d_in[13];
  const float* kn_b  = (const float*)d_in[14];
  const float* fn_g  = (const float*)d_in[15];
  const float* fn_b  = (const float*)d_in[16];
  const float* ffW1  = (const float*)d_in[17];
  const float* ffb1  = (const float*)d_in[18];
  const float* ffW2  = (const float*)d_in[19];
  const float* ffb2  = (const float*)d_in[20];
  const float* hW1   = (const float*)d_in[21];
  const float* hb1   = (const float*)d_in[22];
  const float* hW2   = (const float*)d_in[23];
  const float* hb2   = (const float*)d_in[24];
  float* out = (float*)d_out;

  {
    cudaFuncSetAttribute(flash_attn_kernel, cudaFuncAttributeMaxDynamicSharedMemorySize, FLASH_SMEM);
    h1_fn g;
    g = mma_h1_kernel<false,false,0>;
    cudaFuncSetAttribute(g, cudaFuncAttributeMaxDynamicSharedMemorySize, H1_SMEM_BYTES);
    g = mma_h1_kernel<false,false,1>;
    cudaFuncSetAttribute(g, cudaFuncAttributeMaxDynamicSharedMemorySize, H1_SMEM_BYTES);
    g = mma_h1_kernel<true,true,2>;
    cudaFuncSetAttribute(g, cudaFuncAttributeMaxDynamicSharedMemorySize, H1_SMEM_BYTES);
    g = mma_h1_kernel<false,true,1>;
    cudaFuncSetAttribute(g, cudaFuncAttributeMaxDynamicSharedMemorySize, H1_SMEM_BYTES);
    g = mma_h1_kernel<false,true,3>;
    cudaFuncSetAttribute(g, cudaFuncAttributeMaxDynamicSharedMemorySize, H1_SMEM_BYTES);
  }

  float *p_xn, *p_src, *p_tmp, *p_vh;
  cudaGetSymbolAddress((void**)&p_xn, g_xn);
  cudaGetSymbolAddress((void**)&p_src, g_src);
  cudaGetSymbolAddress((void**)&p_tmp, g_tmp);
  cudaGetSymbolAddress((void**)&p_vh, g_vh);
  fp16 *p_ah, *p_ffh, *p_vth, *p_qhh, *p_qhl, *p_khh;
  cudaGetSymbolAddress((void**)&p_ah, g_ah);
  cudaGetSymbolAddress((void**)&p_ffh, g_ffh);
  cudaGetSymbolAddress((void**)&p_vth, g_vth);
  cudaGetSymbolAddress((void**)&p_qhh, g_qhh);
  cudaGetSymbolAddress((void**)&p_qhl, g_qhl);
  cudaGetSymbolAddress((void**)&p_khh, g_khh);
  fp16 *pWq, *pWkv, *pWo, *pW1, *pW2, *pHW1;
  cudaGetSymbolAddress((void**)&pWq, g_WqT);
  cudaGetSymbolAddress((void**)&pWkv, g_WkvT);
  cudaGetSymbolAddress((void**)&pWo, g_WoT);
  cudaGetSymbolAddress((void**)&pW1, g_W1T);
  cudaGetSymbolAddress((void**)&pW2, g_W2T);
  cudaGetSymbolAddress((void**)&pHW1, g_hW1T);

  const float qk_scale = 0.08838834764831845f;

  // --- weight transpose -> fp16 ---
  transpose_half_kernel<<<dim3(DD/32, DD/32, NLAYERS), 256>>>(Wq, pWq, DD, DD, (ll)DD*DD, (ll)DD*DD);
  transpose_half_kernel<<<dim3(2*DD/32, DD/32, NLAYERS), 256>>>(Wkv, pWkv, DD, 2*DD, (ll)DD*2*DD, (ll)DD*2*DD);
  transpose_half_kernel<<<dim3(DD/32, DD/32, NLAYERS), 256>>>(Wout, pWo, DD, DD, (ll)DD*DD, (ll)DD*DD);
  transpose_half_kernel<<<dim3(NHID/32, DD/32, NLAYERS), 256>>>(ffW1, pW1, DD, NHID, (ll)DD*NHID, (ll)DD*NHID);
  transpose_half_kernel<<<dim3(DD/32, NHID/32, NLAYERS), 256>>>(ffW2, pW2, NHID, DD, (ll)NHID*DD, (ll)NHID*DD);
  transpose_half_kernel<<<dim3(NHID/32, DD/32, 1), 256>>>(hW1, pHW1, DD, NHID, 0, 0);

  // --- preprocessing + encoder ---
  colstats_kernel<<<BB*NFEAT, 256>>>(x_src, 0);
  colstats_kernel<<<BB*NFEAT, 256>>>(x_src, 1);
  colstats_kernel<<<BB*NFEAT, 256>>>(x_src, 2);
  norm_write_kernel<<<(LB*KPAD + 255)/256, 256>>>(x_src);
  sgemm_kernel<true><<<dim3(DD/128, LB/128, 1), 256>>>(
      p_xn, enc_W, p_tmp, enc_b, KPAD, NFEAT, KPAD, DD, DD);
  encode_finish_kernel<<<LB, 256>>>(p_tmp, y_src, yenc_W, yenc_b);

  for (int i = 0; i < NLAYERS; i++) {
    // --- attention ---
    ln_half_kernel<<<LB, 256>>>(p_src, an_g + i*DD, an_b + i*DD, p_ah);
    mma_h1_kernel<false,false,0><<<dim3(8, 64, 1), 256, H1_SMEM_BYTES>>>(
        p_ah, pWq + (size_t)i*DD*DD, p_tmp, nullptr, nullptr,
        DD, DD, DD, DD, 1, 0,0,0,0,0,0, 1.f);
    qln_split_kernel<<<LB, 256>>>(p_tmp, qn_g + i*HDIM, qn_b + i*HDIM, p_qhh, p_qhl);
    mma_h1_kernel<false,false,0><<<dim3(16, 8, BB), 256, H1_SMEM_BYTES>>>(
        p_ah, pWkv + (size_t)i*DD*2*DD, p_tmp, nullptr, nullptr,
        DD, DD, DD, 2*DD, 1,
        (ll)LL*DD, 0, 0, 0, (ll)PP*2*DD, 0, 1.f);
    klnv_split_kernel<<<BB*PP, 256>>>(p_tmp, kn_g + i*HDIM, kn_b + i*HDIM, p_khh, p_vh);
    transpose_half_kernel<<<dim3(HDIM/32, PP/32, BB*HH), 256>>>(
        p_vh, p_vth, PP, HDIM, (ll)PP*HDIM, (ll)HDIM*PP);
    // fused attention -> fp16 attn out in (B,L,D)
    flash_attn_kernel<<<dim3(LL/128, 1, BB*HH), 256, FLASH_SMEM>>>(
        p_qhh, p_qhl, p_khh, p_vth, p_ah, qk_scale);
    // src += attn @ Wout
    mma_h1_kernel<false,false,1><<<dim3(8, 64, 1), 256, H1_SMEM_BYTES>>>(
        p_ah, pWo + (size_t)i*DD*DD, p_src, nullptr, nullptr,
        DD, DD, DD, DD, 1, 0,0,0,0,0,0, 1.f);
    // --- FFN ---
    ln_half_kernel<<<LB, 256>>>(p_src, fn_g + i*DD, fn_b + i*DD, p_ah);
    mma_h1_kernel<true,true,2><<<dim3(NHID/128, 64, 1), 256, H1_SMEM_BYTES>>>(
        p_ah, pW1 + (size_t)i*NHID*DD, nullptr, p_ffh, ffb1 + (size_t)i*NHID,
        DD, DD, DD, NHID, 1, 0,0,0,0,0,0, 1.f);
    if (i < NLAYERS - 1) {
      mma_h1_kernel<false,true,1><<<dim3(8, 64, 1), 256, H1_SMEM_BYTES>>>(
          p_ffh, pW2 + (size_t)i*DD*NHID, p_src, nullptr, ffb2 + (size_t)i*DD,
          NHID, NHID, NHID, DD, 1, 0,0,0,0,0,0, 1.f);
    } else {
      mma_h1_kernel<false,true,3><<<dim3(8, 64, 1), 256, H1_SMEM_BYTES>>>(
          p_ffh, pW2 + (size_t)i*DD*NHID, p_src, p_ah, ffb2 + (size_t)i*DD,
          NHID, NHID, NHID, DD, 1, 0,0,0,0,0,0, 1.f);
    }
  }

  // --- head ---
  mma_h1_kernel<true,true,2><<<dim3(NHID/128, PP/128, BB), 256, H1_SMEM_BYTES>>>(
      p_ah + (size_t)PP*DD, pHW1, nullptr, p_ffh, hb1,
      DD, DD, DD, NHID, 1,
      (ll)LL*DD, 0, 0, 0, (ll)PP*NHID, 0, 1.f);
  head2_kernel<<<BB*PP, 256>>>(p_ffh, hW2, hb2, out);
}